// round 6
// baseline (speedup 1.0000x reference)
#include <cuda_runtime.h>
#include <math.h>
#include <stdint.h>

#define BB 2
#define SS 1024
#define HID 4096
#define NH 32
#define NKV 8
#define HD 128
#define LCK 3
#define MROWS (BB*SS)   // 2048
#define QDIM (NH*HD)    // 4096
#define KVDIM (NKV*HD)  // 1024

// ---------------- scratch (static device globals; no allocations) ----------
__device__ float g_q[(size_t)MROWS * QDIM];     // 32 MB
__device__ float g_k[(size_t)MROWS * KVDIM];    // 8 MB
__device__ float g_v[(size_t)MROWS * KVDIM];    // 8 MB
__device__ float g_attn[(size_t)MROWS * QDIM];  // 32 MB
__device__ float g_xr[(size_t)MROWS * HID];     // 32 MB (tf32-rounded x)
__device__ float g_wq[(size_t)HID * QDIM];      // 64 MB rounded weights
__device__ float g_wk[(size_t)HID * KVDIM];     // 16 MB
__device__ float g_wv[(size_t)HID * KVDIM];     // 16 MB
__device__ float g_wo[(size_t)QDIM * HID];      // 64 MB

// ---------------- PTX helpers -----------------------------------------------
__device__ __forceinline__ void cp16(uint32_t dst, const void* src) {
    asm volatile("cp.async.cg.shared.global [%0], [%1], 16;" :: "r"(dst), "l"(src));
}
__device__ __forceinline__ float f2tf32(float x) {
    uint32_t u;
    asm("cvt.rna.tf32.f32 %0, %1;" : "=r"(u) : "f"(x));
    return __uint_as_float(u);
}
__device__ __forceinline__ void mma8(float* c, const uint32_t* a, const uint32_t* b) {
    asm volatile(
        "mma.sync.aligned.m16n8k8.row.col.f32.tf32.tf32.f32 "
        "{%0,%1,%2,%3},{%4,%5,%6,%7},{%8,%9},{%0,%1,%2,%3};"
        : "+f"(c[0]), "+f"(c[1]), "+f"(c[2]), "+f"(c[3])
        : "r"(a[0]), "r"(a[1]), "r"(a[2]), "r"(a[3]), "r"(b[0]), "r"(b[1]));
}
// packed f32x2
__device__ __forceinline__ unsigned long long fma2(unsigned long long a,
                                                   unsigned long long b,
                                                   unsigned long long c) {
    unsigned long long d;
    asm("fma.rn.f32x2 %0, %1, %2, %3;" : "=l"(d) : "l"(a), "l"(b), "l"(c));
    return d;
}
__device__ __forceinline__ unsigned long long mul2(unsigned long long a,
                                                   unsigned long long b) {
    unsigned long long d;
    asm("mul.rn.f32x2 %0, %1, %2;" : "=l"(d) : "l"(a), "l"(b));
    return d;
}
__device__ __forceinline__ unsigned long long pack2(float x) {
    unsigned long long d;
    asm("mov.b64 %0, {%1, %2};" : "=l"(d) : "f"(x), "f"(x));
    return d;
}
__device__ __forceinline__ void unpack2(unsigned long long v, float& lo, float& hi) {
    asm("mov.b64 {%0, %1}, %2;" : "=f"(lo), "=f"(hi) : "l"(v));
}

// ---------------- fused tf32 round pass (all 5 tensors, one launch) ----------
#define R_X  ((size_t)MROWS * HID / 4)        // 2M float4
#define R_WQ ((size_t)HID * QDIM / 4)         // 4M
#define R_WK ((size_t)HID * KVDIM / 4)        // 1M
#define R_WV ((size_t)HID * KVDIM / 4)        // 1M
#define R_WO ((size_t)QDIM * HID / 4)         // 4M
__global__ void round_all_kernel(const float4* __restrict__ x,  float4* __restrict__ xr,
                                 const float4* __restrict__ wq, float4* __restrict__ wqr,
                                 const float4* __restrict__ wk, float4* __restrict__ wkr,
                                 const float4* __restrict__ wv, float4* __restrict__ wvr,
                                 const float4* __restrict__ wo, float4* __restrict__ wor) {
    size_t i = (size_t)blockIdx.x * 256 + threadIdx.x;
    const float4* in;
    float4* out;
    if (i < R_X)                    { in = x;  out = xr;  }
    else if ((i -= R_X) < R_WQ)     { in = wq; out = wqr; }
    else if ((i -= R_WQ) < R_WK)    { in = wk; out = wkr; }
    else if ((i -= R_WK) < R_WV)    { in = wv; out = wvr; }
    else { i -= R_WV;                 in = wo; out = wor; }
    float4 v = in[i];
    v.x = f2tf32(v.x); v.y = f2tf32(v.y); v.z = f2tf32(v.z); v.w = f2tf32(v.w);
    out[i] = v;
}

// ---------------- legacy-mma TF32 GEMM ---------------------------------------
// C[M,N] = A[M,K] @ B[K,N].  A,B row-major, pre-rounded to tf32.
// Block tile 128x128, BK=32, 8 warps (2M x 4N grid, 64x32 warp tiles),
// 3-stage cp.async pipeline, 2 CTAs/SM (regs capped at 128).
__global__ __launch_bounds__(256, 2) void gemm_lg(const float* __restrict__ A,
                                                  const float* __restrict__ B,
                                                  float* __restrict__ C,
                                                  int M, int N, int K) {
    constexpr int APITCH = 36;          // BK + 4
    constexpr int BPITCH = 136;         // BN + 8 -> conflict-free
    constexpr int ASZ = 128 * APITCH;   // floats per A stage
    constexpr int BSZ = 32 * BPITCH;    // floats per B stage
    constexpr int STG = ASZ + BSZ;

    extern __shared__ float sm[];
    const uint32_t smb = (uint32_t)__cvta_generic_to_shared(sm);
    const uint32_t* s32 = (const uint32_t*)sm;

    const int tid  = threadIdx.x;
    const int lane = tid & 31;
    const int wid  = tid >> 5;          // 0..7
    const int gid  = lane >> 2;         // 0..7
    const int tig  = lane & 3;          // 0..3
    const int wm   = (wid & 1) * 64;    // 2 warps along M
    const int wn   = (wid >> 1) * 32;   // 4 warps along N

    const int bm0 = blockIdx.y * 128;
    const int bn0 = blockIdx.x * 128;

    float acc[4][4][4];
#pragma unroll
    for (int mt = 0; mt < 4; mt++)
#pragma unroll
        for (int nt = 0; nt < 4; nt++)
#pragma unroll
            for (int i = 0; i < 4; i++) acc[mt][nt][i] = 0.f;

    const int T = K / 32;

    auto issue = [&](int t) {
        const int k0 = t * 32;
        const uint32_t sb = smb + (uint32_t)((t % 3) * STG * 4);
#pragma unroll
        for (int i = 0; i < 4; i++) {       // A: 1024 float4 chunks
            const int c = tid + i * 256;
            const int row = c >> 3;
            const int kq = (c & 7) * 4;
            cp16(sb + (uint32_t)((row * APITCH + kq) * 4),
                 A + (size_t)(bm0 + row) * K + k0 + kq);
        }
#pragma unroll
        for (int i = 0; i < 4; i++) {       // B: 1024 float4 chunks
            const int c = tid + i * 256;
            const int kk = c >> 5;
            const int n4 = (c & 31) * 4;
            cp16(sb + (uint32_t)((ASZ + kk * BPITCH + n4) * 4),
                 B + (size_t)(k0 + kk) * N + bn0 + n4);
        }
        asm volatile("cp.async.commit_group;");
    };

    issue(0);
    issue(1);

    for (int t = 0; t < T; t++) {
        if (t < T - 1) { asm volatile("cp.async.wait_group 1;"); }
        else           { asm volatile("cp.async.wait_group 0;"); }
        __syncthreads();
        if (t + 2 < T) issue(t + 2);

        const int so = (t % 3) * STG;
        const uint32_t* sa = s32 + so;
        const uint32_t* sb = s32 + so + ASZ;
#pragma unroll
        for (int ks = 0; ks < 32; ks += 8) {
            uint32_t af[4][4];
#pragma unroll
            for (int mt = 0; mt < 4; mt++) {
                const int r = wm + mt * 16 + gid;
                af[mt][0] = sa[r * APITCH + ks + tig];
                af[mt][1] = sa[(r + 8) * APITCH + ks + tig];
                af[mt][2] = sa[r * APITCH + ks + tig + 4];
                af[mt][3] = sa[(r + 8) * APITCH + ks + tig + 4];
            }
            uint32_t bf[4][2];
#pragma unroll
            for (int nt = 0; nt < 4; nt++) {
                const int cc = wn + nt * 8 + gid;
                bf[nt][0] = sb[(ks + tig) * BPITCH + cc];
                bf[nt][1] = sb[(ks + tig + 4) * BPITCH + cc];
            }
#pragma unroll
            for (int mt = 0; mt < 4; mt++)
#pragma unroll
                for (int nt = 0; nt < 4; nt++)
                    mma8(acc[mt][nt], af[mt], bf[nt]);
        }
        __syncthreads();
    }

    // epilogue
#pragma unroll
    for (int mt = 0; mt < 4; mt++) {
#pragma unroll
        for (int nt = 0; nt < 4; nt++) {
            const int r = bm0 + wm + mt * 16 + gid;
            const int cc = bn0 + wn + nt * 8 + tig * 2;
            *(float2*)&C[(size_t)r * N + cc] =
                make_float2(acc[mt][nt][0], acc[mt][nt][1]);
            *(float2*)&C[(size_t)(r + 8) * N + cc] =
                make_float2(acc[mt][nt][2], acc[mt][nt][3]);
        }
    }
}

// ---------------- RoPE (fused q+k, in place) --------------------------------
__global__ void rope_fused(float* __restrict__ qb, float* __restrict__ kb) {
    const int row = blockIdx.x;
    const int which = blockIdx.y;
    float* buf = which ? kb : qb;
    const int heads = which ? NKV : NH;
    const int s = row & (SS - 1);
    const float log2theta = 13.287712379549449f;  // log2(10000)
    for (int idx = threadIdx.x; idx < heads * 64; idx += blockDim.x) {
        const int h = idx >> 6;
        const int i = idx & 63;
        const float inv = exp2f(-(float)(2 * i) * (1.0f / 128.0f) * log2theta);
        const float ang = (float)s * inv;
        const float c = cosf(ang);
        const float sn = sinf(ang);
        float* p = buf + (size_t)row * heads * HD + h * HD;
        const float x1 = p[i];
        const float x2 = p[i + 64];
        p[i]      = x1 * c - x2 * sn;
        p[i + 64] = x2 * c + x1 * sn;
    }
}

// ---------------- flash attention (fp32 via packed f32x2) --------------------
__global__ void attn_kernel(const float* __restrict__ q,
                            const float* __restrict__ k,
                            const float* __restrict__ v,
                            const float* __restrict__ ksuf,
                            const float* __restrict__ vsuf,
                            const int* __restrict__ validp,
                            float* __restrict__ outbuf) {
    __shared__ float Ks[32][128];
    __shared__ float Vs[32][128];

    const int valid = *validp;
    const int qt = blockIdx.x;
    const int h  = blockIdx.y;
    const int b  = blockIdx.z;
    const int kvh = h >> 2;

    const int tid = threadIdx.x;
    const int ql  = tid >> 3;
    const int sub = tid & 7;
    const int q_global = qt * 32 + ql;
    const bool qvalid = q_global < valid;

    const float scale = 0.08838834764831845f;
    const unsigned long long scale2 = pack2(scale);

    unsigned long long q2[8];
    {
        const float* qp = q + (size_t)(b * SS + q_global) * QDIM + h * HD;
#pragma unroll
        for (int t = 0; t < 4; t++) {
            ulonglong2 u = *(const ulonglong2*)(qp + t * 32 + sub * 4);
            q2[2 * t]     = mul2(scale2, u.x);
            q2[2 * t + 1] = mul2(scale2, u.y);
        }
    }

    unsigned long long o2[8];
#pragma unroll
    for (int j = 0; j < 8; j++) o2[j] = 0ull;
    float m = -1e30f, l = 0.f;

    const int kend = qt * 32 + 32;
    const float* kb_base = k + (size_t)(b * SS) * KVDIM + kvh * HD;
    const float* vb_base = v + (size_t)(b * SS) * KVDIM + kvh * HD;

    for (int k0 = 0; k0 < kend; k0 += 32) {
#pragma unroll
        for (int t = 0; t < 4; t++) {
            const int f  = tid + t * 256;
            const int kk = f >> 5;
            const int d4 = (f & 31) * 4;
            *(float4*)&Ks[kk][d4] =
                *(const float4*)(kb_base + (size_t)(k0 + kk) * KVDIM + d4);
            *(float4*)&Vs[kk][d4] =
                *(const float4*)(vb_base + (size_t)(k0 + kk) * KVDIM + d4);
        }
        __syncthreads();

        float sc[32];
#pragma unroll 8
        for (int kk = 0; kk < 32; kk++) {
            unsigned long long p2 = 0ull;
#pragma unroll
            for (int t = 0; t < 4; t++) {
                ulonglong2 kv = *(const ulonglong2*)&Ks[kk][t * 32 + sub * 4];
                p2 = fma2(q2[2 * t], kv.x, p2);
                p2 = fma2(q2[2 * t + 1], kv.y, p2);
            }
            float plo, phi;
            unpack2(p2, plo, phi);
            float p = plo + phi;
            p += __shfl_xor_sync(0xffffffffu, p, 1);
            p += __shfl_xor_sync(0xffffffffu, p, 2);
            p += __shfl_xor_sync(0xffffffffu, p, 4);
            sc[kk] = (k0 + kk <= q_global) ? p : -1e30f;
        }

        float tmax = sc[0];
#pragma unroll
        for (int kk = 1; kk < 32; kk++) tmax = fmaxf(tmax, sc[kk]);
        const float mnew = fmaxf(m, tmax);
        const float corr = __expf(m - mnew);
        l *= corr;
        const unsigned long long corr2 = pack2(corr);
#pragma unroll
        for (int j = 0; j < 8; j++) o2[j] = mul2(corr2, o2[j]);

#pragma unroll 8
        for (int kk = 0; kk < 32; kk++) {
            const float p = __expf(sc[kk] - mnew);
            l += p;
            const unsigned long long p2 = pack2(p);
#pragma unroll
            for (int t = 0; t < 4; t++) {
                ulonglong2 vv = *(const ulonglong2*)&Vs[kk][t * 32 + sub * 4];
                o2[2 * t]     = fma2(p2, vv.x, o2[2 * t]);
                o2[2 * t + 1] = fma2(p2, vv.y, o2[2 * t + 1]);
            }
        }
        m = mnew;
        __syncthreads();
    }

#pragma unroll
    for (int j = 0; j < LCK; j++) {
        const size_t off =
            (((size_t)(b * NKV + kvh) * LCK + j) * SS + q_global) * HD;
        const float* kp = ksuf + off;
        unsigned long long p2 = 0ull;
#pragma unroll
        for (int t = 0; t < 4; t++) {
            ulonglong2 kv = *(const ulonglong2*)(kp + t * 32 + sub * 4);
            p2 = fma2(q2[2 * t], kv.x, p2);
            p2 = fma2(q2[2 * t + 1], kv.y, p2);
        }
        float plo, phi;
        unpack2(p2, plo, phi);
        float p = plo + phi;
        p += __shfl_xor_sync(0xffffffffu, p, 1);
        p += __shfl_xor_sync(0xffffffffu, p, 2);
        p += __shfl_xor_sync(0xffffffffu, p, 4);

        const float mnew = fmaxf(m, p);
        const float corr = __expf(m - mnew);
        const float e = __expf(p - mnew);
        l = l * corr + e;
        const unsigned long long corr2 = pack2(corr);
        const unsigned long long e2 = pack2(e);
        const float* vp = vsuf + off;
#pragma unroll
        for (int t = 0; t < 4; t++) {
            ulonglong2 vv = *(const ulonglong2*)(vp + t * 32 + sub * 4);
            o2[2 * t]     = fma2(e2, vv.x, mul2(corr2, o2[2 * t]));
            o2[2 * t + 1] = fma2(e2, vv.y, mul2(corr2, o2[2 * t + 1]));
        }
        m = mnew;
    }

    const float invl = qvalid ? (1.0f / l) : 0.0f;
    float* op = outbuf + (size_t)(b * SS + q_global) * QDIM + h * HD;
#pragma unroll
    for (int t = 0; t < 4; t++) {
        float a0, a1, a2, a3;
        unpack2(o2[2 * t], a0, a1);
        unpack2(o2[2 * t + 1], a2, a3);
        float4 w;
        w.x = f2tf32(a0 * invl); w.y = f2tf32(a1 * invl);
        w.z = f2tf32(a2 * invl); w.w = f2tf32(a3 * invl);
        *(float4*)(op + t * 32 + sub * 4) = w;
    }
}

// ---------------- launch ----------------------------------------------------
extern "C" void kernel_launch(void* const* d_in, const int* in_sizes, int n_in,
                              void* d_out, int out_size) {
    const float* x    = (const float*)d_in[0];
    const float* ksuf = (const float*)d_in[1];
    const float* vsuf = (const float*)d_in[2];
    const float* Wq   = (const float*)d_in[3];
    const float* Wk   = (const float*)d_in[4];
    const float* Wv   = (const float*)d_in[5];
    const float* Wo   = (const float*)d_in[6];
    const int* valid  = (const int*)d_in[7];
    float* out = (float*)d_out;

    float *gq, *gk, *gv, *ga, *gxr, *wq, *wk, *wv, *wo;
    cudaGetSymbolAddress((void**)&gq, g_q);
    cudaGetSymbolAddress((void**)&gk, g_k);
    cudaGetSymbolAddress((void**)&gv, g_v);
    cudaGetSymbolAddress((void**)&ga, g_attn);
    cudaGetSymbolAddress((void**)&gxr, g_xr);
    cudaGetSymbolAddress((void**)&wq, g_wq);
    cudaGetSymbolAddress((void**)&wk, g_wk);
    cudaGetSymbolAddress((void**)&wv, g_wv);
    cudaGetSymbolAddress((void**)&wo, g_wo);

    // smem: 3 stages of (128*36 + 32*136) floats = 107520 B
    const int SMEM = 3 * (128 * 36 + 32 * 136) * 4;
    cudaFuncSetAttribute(gemm_lg, cudaFuncAttributeMaxDynamicSharedMemorySize, SMEM);

    // 0: fused tf32 rounding (x, Wq, Wk, Wv, Wo)
    {
        const size_t total4 = R_X + R_WQ + R_WK + R_WV + R_WO;  // 12M float4
        round_all_kernel<<<(unsigned)(total4 / 256), 256>>>(
            (const float4*)x, (float4*)gxr,
            (const float4*)Wq, (float4*)wq,
            (const float4*)Wk, (float4*)wk,
            (const float4*)Wv, (float4*)wv,
            (const float4*)Wo, (float4*)wo);
    }

    // 1,2: K, V projections
    gemm_lg<<<dim3(KVDIM / 128, MROWS / 128), 256, SMEM>>>(gxr, wk, gk, MROWS, KVDIM, HID);
    gemm_lg<<<dim3(KVDIM / 128, MROWS / 128), 256, SMEM>>>(gxr, wv, gv, MROWS, KVDIM, HID);

    // 3,4: Q projection split into two N-halves (profiler lands here)
    gemm_lg<<<dim3(QDIM / 256, MROWS / 128), 256, SMEM>>>(gxr, wq, gq, MROWS, QDIM, HID);
    gemm_lg<<<dim3(QDIM / 256, MROWS / 128), 256, SMEM>>>(gxr, wq + QDIM / 2, gq + QDIM / 2,
                                                          MROWS, QDIM, HID);

    // 5: RoPE
    rope_fused<<<dim3(MROWS, 2), 256>>>(gq, gk);
    // 6: attention (writes tf32-rounded output)
    attn_kernel<<<dim3(SS / 32, NH, BB), 256>>>(gq, gk, gv, ksuf, vsuf, valid, ga);
    // 7: output projection
    gemm_lg<<<dim3(QDIM / 128, MROWS / 128), 256, SMEM>>>(ga, wo, out, MROWS, QDIM, HID);
}

// round 8
// speedup vs baseline: 1.2836x; 1.2836x over previous
#include <cuda_runtime.h>
#include <cuda_fp16.h>
#include <math.h>
#include <stdint.h>

#define BB 2
#define SS 1024
#define HID 4096
#define NH 32
#define NKV 8
#define HD 128
#define LCK 3
#define MROWS (BB*SS)   // 2048
#define QDIM (NH*HD)    // 4096
#define KVDIM (NKV*HD)  // 1024

// ---------------- scratch (static device globals; no allocations) ----------
__device__ float  g_q[(size_t)MROWS * QDIM];       // 32 MB
__device__ float  g_k[(size_t)MROWS * KVDIM];      // 8 MB
__device__ float  g_v[(size_t)MROWS * KVDIM];      // 8 MB
__device__ __half g_xh[(size_t)MROWS * HID];       // 16 MB (fp16 x)
__device__ __half g_ah[(size_t)MROWS * QDIM];      // 16 MB (fp16 attn out)
__device__ uint32_t g_wqp[(size_t)(HID/2) * QDIM]; // 32 MB packed fp16 pairs
__device__ uint32_t g_wkp[(size_t)(HID/2) * KVDIM];
__device__ uint32_t g_wvp[(size_t)(HID/2) * KVDIM];
__device__ uint32_t g_wop[(size_t)(QDIM/2) * HID];

// ---------------- PTX helpers -----------------------------------------------
__device__ __forceinline__ void cp16(uint32_t dst, const void* src) {
    asm volatile("cp.async.cg.shared.global [%0], [%1], 16;" :: "r"(dst), "l"(src));
}
__device__ __forceinline__ uint32_t h2u(__half2 h) {
    union { __half2 h; uint32_t u; } cv;
    cv.h = h;
    return cv.u;
}
__device__ __forceinline__ void mma16(float* c, const uint32_t* a, const uint32_t* b) {
    asm volatile(
        "mma.sync.aligned.m16n8k16.row.col.f32.f16.f16.f32 "
        "{%0,%1,%2,%3},{%4,%5,%6,%7},{%8,%9},{%0,%1,%2,%3};"
        : "+f"(c[0]), "+f"(c[1]), "+f"(c[2]), "+f"(c[3])
        : "r"(a[0]), "r"(a[1]), "r"(a[2]), "r"(a[3]), "r"(b[0]), "r"(b[1]));
}
// packed f32x2 for attention
__device__ __forceinline__ unsigned long long fma2(unsigned long long a,
                                                   unsigned long long b,
                                                   unsigned long long c) {
    unsigned long long d;
    asm("fma.rn.f32x2 %0, %1, %2, %3;" : "=l"(d) : "l"(a), "l"(b), "l"(c));
    return d;
}
__device__ __forceinline__ unsigned long long mul2(unsigned long long a,
                                                   unsigned long long b) {
    unsigned long long d;
    asm("mul.rn.f32x2 %0, %1, %2;" : "=l"(d) : "l"(a), "l"(b));
    return d;
}
__device__ __forceinline__ unsigned long long pack2(float x) {
    unsigned long long d;
    asm("mov.b64 %0, {%1, %2};" : "=l"(d) : "f"(x), "f"(x));
    return d;
}
__device__ __forceinline__ void unpack2(unsigned long long v, float& lo, float& hi) {
    asm("mov.b64 {%0, %1}, %2;" : "=f"(lo), "=f"(hi) : "l"(v));
}

// ---------------- x -> fp16 -------------------------------------------------
__global__ void cvt_x_kernel(const float4* __restrict__ in, __half* __restrict__ out) {
    const size_t i = (size_t)blockIdx.x * 256 + threadIdx.x;  // one float4 each
    float4 v = in[i];
    *(__half2*)(out + i * 4)     = __floats2half2_rn(v.x, v.y);
    *(__half2*)(out + i * 4 + 2) = __floats2half2_rn(v.z, v.w);
}

// ---------------- weight pack: W[K][N] fp32 -> P[K/2][N] {k,k+1} half2 -------
__global__ void pack_w_kernel(const float* __restrict__ W, uint32_t* __restrict__ P, int N) {
    const int n4 = (blockIdx.x * 256 + threadIdx.x) * 4;
    const int kp = blockIdx.y;
    float4 r0 = *(const float4*)(W + (size_t)(2 * kp) * N + n4);
    float4 r1 = *(const float4*)(W + (size_t)(2 * kp + 1) * N + n4);
    uint4 o;
    o.x = h2u(__floats2half2_rn(r0.x, r1.x));
    o.y = h2u(__floats2half2_rn(r0.y, r1.y));
    o.z = h2u(__floats2half2_rn(r0.z, r1.z));
    o.w = h2u(__floats2half2_rn(r0.w, r1.w));
    *(uint4*)(P + (size_t)kp * N + n4) = o;
}

// ---------------- fp16 tensor-core GEMM --------------------------------------
// C[M,N] = A[M,K] @ B[K,N].  A fp16 row-major, B packed [K/2][N] {k,k+1} half2.
// Block 128x128, BK=32 halves, 8 warps (2Mx4N, 64x32 warp tiles), 3-stage cp.async.
// blockIdx.z selects (B0,C0) vs (B1,C1) so K/V can share one launch.
#define APITCHW 36            // A stage pitch in 32-bit words
#define BPITCHW 136           // B stage pitch in words (128 + 8 -> bank 8t+g)
#define ASZW (128 * APITCHW)  // 4608 words per A stage
#define BSZW (16 * BPITCHW)   // 2176 words per B stage
#define STGW (ASZW + BSZW)
#define GEMM_SMEM (3 * STGW * 4)  // 81408 B

__global__ __launch_bounds__(256, 2) void gemm_h(const __half* __restrict__ A,
                                                 const uint32_t* __restrict__ B0,
                                                 const uint32_t* __restrict__ B1,
                                                 float* __restrict__ C0,
                                                 float* __restrict__ C1,
                                                 int M, int N, int K) {
    const uint32_t* B = blockIdx.z ? B1 : B0;
    float* C = blockIdx.z ? C1 : C0;

    extern __shared__ float sm[];
    const uint32_t smb = (uint32_t)__cvta_generic_to_shared(sm);
    const uint32_t* s32 = (const uint32_t*)sm;

    const int tid  = threadIdx.x;
    const int lane = tid & 31;
    const int wid  = tid >> 5;          // 0..7
    const int gid  = lane >> 2;         // 0..7
    const int tig  = lane & 3;          // 0..3
    const int wm   = (wid & 1) * 64;
    const int wn   = (wid >> 1) * 32;

    const int bm0 = blockIdx.y * 128;
    const int bn0 = blockIdx.x * 128;

    float acc[4][4][4];
#pragma unroll
    for (int mt = 0; mt < 4; mt++)
#pragma unroll
        for (int nt = 0; nt < 4; nt++)
#pragma unroll
            for (int i = 0; i < 4; i++) acc[mt][nt][i] = 0.f;

    const int T = K / 32;

    auto issue = [&](int t) {
        const uint32_t sb = smb + (uint32_t)((t % 3) * STGW * 4);
        // A: 128 rows x 32 halves = 512 cp16 chunks
#pragma unroll
        for (int i = 0; i < 2; i++) {
            const int c = tid + i * 256;
            const int row = c >> 2;
            const int q = c & 3;               // 8-half (16B) chunk within row
            cp16(sb + (uint32_t)(row * APITCHW * 4 + q * 16),
                 A + (size_t)(bm0 + row) * K + t * 32 + q * 8);
        }
        // B: 16 packed rows x 128 words = 512 cp16 chunks
#pragma unroll
        for (int i = 0; i < 2; i++) {
            const int c = tid + i * 256;
            const int kk = c >> 5;             // 0..15
            const int n4 = (c & 31) * 4;       // word offset
            cp16(sb + (uint32_t)((ASZW + kk * BPITCHW + n4) * 4),
                 B + (size_t)(t * 16 + kk) * N + bn0 + n4);
        }
        asm volatile("cp.async.commit_group;");
    };

    issue(0);
    issue(1);

    for (int t = 0; t < T; t++) {
        if (t < T - 1) { asm volatile("cp.async.wait_group 1;"); }
        else           { asm volatile("cp.async.wait_group 0;"); }
        __syncthreads();
        if (t + 2 < T) issue(t + 2);

        const int so = (t % 3) * STGW;
        const uint32_t* sa = s32 + so;
        const uint32_t* sb = s32 + so + ASZW;
#pragma unroll
        for (int ks = 0; ks < 2; ks++) {       // two k16 steps per 32-half tile
            const int w0 = ks * 8;
            uint32_t af[4][4];
#pragma unroll
            for (int mt = 0; mt < 4; mt++) {
                const int r = wm + mt * 16 + gid;
                af[mt][0] = sa[r * APITCHW + w0 + tig];
                af[mt][1] = sa[(r + 8) * APITCHW + w0 + tig];
                af[mt][2] = sa[r * APITCHW + w0 + tig + 4];
                af[mt][3] = sa[(r + 8) * APITCHW + w0 + tig + 4];
            }
            uint32_t bf[4][2];
#pragma unroll
            for (int nt = 0; nt < 4; nt++) {
                const int col = wn + nt * 8 + gid;
                bf[nt][0] = sb[(w0 + tig) * BPITCHW + col];
                bf[nt][1] = sb[(w0 + tig + 4) * BPITCHW + col];
            }
#pragma unroll
            for (int mt = 0; mt < 4; mt++)
#pragma unroll
                for (int nt = 0; nt < 4; nt++)
                    mma16(acc[mt][nt], af[mt], bf[nt]);
        }
        __syncthreads();
    }

    // epilogue
#pragma unroll
    for (int mt = 0; mt < 4; mt++) {
#pragma unroll
        for (int nt = 0; nt < 4; nt++) {
            const int r = bm0 + wm + mt * 16 + gid;
            const int cc = bn0 + wn + nt * 8 + tig * 2;
            *(float2*)&C[(size_t)r * N + cc] =
                make_float2(acc[mt][nt][0], acc[mt][nt][1]);
            *(float2*)&C[(size_t)(r + 8) * N + cc] =
                make_float2(acc[mt][nt][2], acc[mt][nt][3]);
        }
    }
}

// ---------------- RoPE (fused q+k, in place, fp32) ---------------------------
__global__ void rope_fused(float* __restrict__ qb, float* __restrict__ kb) {
    const int row = blockIdx.x;
    const int which = blockIdx.y;
    float* buf = which ? kb : qb;
    const int heads = which ? NKV : NH;
    const int s = row & (SS - 1);
    const float log2theta = 13.287712379549449f;  // log2(10000)
    for (int idx = threadIdx.x; idx < heads * 64; idx += blockDim.x) {
        const int h = idx >> 6;
        const int i = idx & 63;
        const float inv = exp2f(-(float)(2 * i) * (1.0f / 128.0f) * log2theta);
        const float ang = (float)s * inv;
        const float c = cosf(ang);
        const float sn = sinf(ang);
        float* p = buf + (size_t)row * heads * HD + h * HD;
        const float x1 = p[i];
        const float x2 = p[i + 64];
        p[i]      = x1 * c - x2 * sn;
        p[i + 64] = x2 * c + x1 * sn;
    }
}

// ---------------- flash attention (fp32 f32x2; fp16 output) ------------------
__global__ void attn_kernel(const float* __restrict__ q,
                            const float* __restrict__ k,
                            const float* __restrict__ v,
                            const float* __restrict__ ksuf,
                            const float* __restrict__ vsuf,
                            const int* __restrict__ validp,
                            __half* __restrict__ outh) {
    __shared__ float Ks[32][128];
    __shared__ float Vs[32][128];

    const int valid = *validp;
    const int qt = blockIdx.x;
    const int h  = blockIdx.y;
    const int b  = blockIdx.z;
    const int kvh = h >> 2;

    const int tid = threadIdx.x;
    const int ql  = tid >> 3;
    const int sub = tid & 7;
    const int q_global = qt * 32 + ql;
    const bool qvalid = q_global < valid;

    const float scale = 0.08838834764831845f;
    const unsigned long long scale2 = pack2(scale);

    unsigned long long q2[8];
    {
        const float* qp = q + (size_t)(b * SS + q_global) * QDIM + h * HD;
#pragma unroll
        for (int t = 0; t < 4; t++) {
            ulonglong2 u = *(const ulonglong2*)(qp + t * 32 + sub * 4);
            q2[2 * t]     = mul2(scale2, u.x);
            q2[2 * t + 1] = mul2(scale2, u.y);
        }
    }

    unsigned long long o2[8];
#pragma unroll
    for (int j = 0; j < 8; j++) o2[j] = 0ull;
    float m = -1e30f, l = 0.f;

    const int kend = qt * 32 + 32;
    const float* kb_base = k + (size_t)(b * SS) * KVDIM + kvh * HD;
    const float* vb_base = v + (size_t)(b * SS) * KVDIM + kvh * HD;

    for (int k0 = 0; k0 < kend; k0 += 32) {
#pragma unroll
        for (int t = 0; t < 4; t++) {
            const int f  = tid + t * 256;
            const int kk = f >> 5;
            const int d4 = (f & 31) * 4;
            *(float4*)&Ks[kk][d4] =
                *(const float4*)(kb_base + (size_t)(k0 + kk) * KVDIM + d4);
            *(float4*)&Vs[kk][d4] =
                *(const float4*)(vb_base + (size_t)(k0 + kk) * KVDIM + d4);
        }
        __syncthreads();

        float sc[32];
#pragma unroll 8
        for (int kk = 0; kk < 32; kk++) {
            unsigned long long p2 = 0ull;
#pragma unroll
            for (int t = 0; t < 4; t++) {
                ulonglong2 kv = *(const ulonglong2*)&Ks[kk][t * 32 + sub * 4];
                p2 = fma2(q2[2 * t], kv.x, p2);
                p2 = fma2(q2[2 * t + 1], kv.y, p2);
            }
            float plo, phi;
            unpack2(p2, plo, phi);
            float p = plo + phi;
            p += __shfl_xor_sync(0xffffffffu, p, 1);
            p += __shfl_xor_sync(0xffffffffu, p, 2);
            p += __shfl_xor_sync(0xffffffffu, p, 4);
            sc[kk] = (k0 + kk <= q_global) ? p : -1e30f;
        }

        float tmax = sc[0];
#pragma unroll
        for (int kk = 1; kk < 32; kk++) tmax = fmaxf(tmax, sc[kk]);
        const float mnew = fmaxf(m, tmax);
        const float corr = __expf(m - mnew);
        l *= corr;
        const unsigned long long corr2 = pack2(corr);
#pragma unroll
        for (int j = 0; j < 8; j++) o2[j] = mul2(corr2, o2[j]);

#pragma unroll 8
        for (int kk = 0; kk < 32; kk++) {
            const float p = __expf(sc[kk] - mnew);
            l += p;
            const unsigned long long p2 = pack2(p);
#pragma unroll
            for (int t = 0; t < 4; t++) {
                ulonglong2 vv = *(const ulonglong2*)&Vs[kk][t * 32 + sub * 4];
                o2[2 * t]     = fma2(p2, vv.x, o2[2 * t]);
                o2[2 * t + 1] = fma2(p2, vv.y, o2[2 * t + 1]);
            }
        }
        m = mnew;
        __syncthreads();
    }

#pragma unroll
    for (int j = 0; j < LCK; j++) {
        const size_t off =
            (((size_t)(b * NKV + kvh) * LCK + j) * SS + q_global) * HD;
        const float* kp = ksuf + off;
        unsigned long long p2 = 0ull;
#pragma unroll
        for (int t = 0; t < 4; t++) {
            ulonglong2 kv = *(const ulonglong2*)(kp + t * 32 + sub * 4);
            p2 = fma2(q2[2 * t], kv.x, p2);
            p2 = fma2(q2[2 * t + 1], kv.y, p2);
        }
        float plo, phi;
        unpack2(p2, plo, phi);
        float p = plo + phi;
        p += __shfl_xor_sync(0xffffffffu, p, 1);
        p += __shfl_xor_sync(0xffffffffu, p, 2);
        p += __shfl_xor_sync(0xffffffffu, p, 4);

        const float mnew = fmaxf(m, p);
        const float corr = __expf(m - mnew);
        const float e = __expf(p - mnew);
        l = l * corr + e;
        const unsigned long long corr2 = pack2(corr);
        const unsigned long long e2 = pack2(e);
        const float* vp = vsuf + off;
#pragma unroll
        for (int t = 0; t < 4; t++) {
            ulonglong2 vv = *(const ulonglong2*)(vp + t * 32 + sub * 4);
            o2[2 * t]     = fma2(e2, vv.x, mul2(corr2, o2[2 * t]));
            o2[2 * t + 1] = fma2(e2, vv.y, mul2(corr2, o2[2 * t + 1]));
        }
        m = mnew;
    }

    // epilogue: normalize, fp16-round (feeds Wo GEMM), masked rows = 0
    const float invl = qvalid ? (1.0f / l) : 0.0f;
    __half* op = outh + (size_t)(b * SS + q_global) * QDIM + h * HD;
#pragma unroll
    for (int t = 0; t < 4; t++) {
        float a0, a1, a2, a3;
        unpack2(o2[2 * t], a0, a1);
        unpack2(o2[2 * t + 1], a2, a3);
        *(__half2*)(op + t * 32 + sub * 4)     = __floats2half2_rn(a0 * invl, a1 * invl);
        *(__half2*)(op + t * 32 + sub * 4 + 2) = __floats2half2_rn(a2 * invl, a3 * invl);
    }
}

// ---------------- launch ----------------------------------------------------
extern "C" void kernel_launch(void* const* d_in, const int* in_sizes, int n_in,
                              void* d_out, int out_size) {
    const float* x    = (const float*)d_in[0];
    const float* ksuf = (const float*)d_in[1];
    const float* vsuf = (const float*)d_in[2];
    const float* Wq   = (const float*)d_in[3];
    const float* Wk   = (const float*)d_in[4];
    const float* Wv   = (const float*)d_in[5];
    const float* Wo   = (const float*)d_in[6];
    const int* valid  = (const int*)d_in[7];
    float* out = (float*)d_out;

    float *gq, *gk, *gv;
    __half *xh, *ah;
    uint32_t *wqp, *wkp, *wvp, *wop;
    cudaGetSymbolAddress((void**)&gq, g_q);
    cudaGetSymbolAddress((void**)&gk, g_k);
    cudaGetSymbolAddress((void**)&gv, g_v);
    cudaGetSymbolAddress((void**)&xh, g_xh);
    cudaGetSymbolAddress((void**)&ah, g_ah);
    cudaGetSymbolAddress((void**)&wqp, g_wqp);
    cudaGetSymbolAddress((void**)&wkp, g_wkp);
    cudaGetSymbolAddress((void**)&wvp, g_wvp);
    cudaGetSymbolAddress((void**)&wop, g_wop);

    cudaFuncSetAttribute(gemm_h, cudaFuncAttributeMaxDynamicSharedMemorySize, GEMM_SMEM);

    // 0: x -> fp16
    cvt_x_kernel<<<(MROWS * HID) / (256 * 4), 256>>>((const float4*)x, xh);
    // 1-4: pack weights to fp16 pair-words
    pack_w_kernel<<<dim3(QDIM / 1024, HID / 2), 256>>>(Wq, wqp, QDIM);
    pack_w_kernel<<<dim3(KVDIM / 1024, HID / 2), 256>>>(Wk, wkp, KVDIM);
    pack_w_kernel<<<dim3(KVDIM / 1024, HID / 2), 256>>>(Wv, wvp, KVDIM);
    pack_w_kernel<<<dim3(HID / 1024, QDIM / 2), 256>>>(Wo, wop, HID);

    // 5: K and V projections fused (z selects weight/output)
    gemm_h<<<dim3(KVDIM / 128, MROWS / 128, 2), 256, GEMM_SMEM>>>(
        xh, wkp, wvp, gk, gv, MROWS, KVDIM, HID);
    // 6,7: Q projection in two N-halves (profiler lands on a GEMM)
    gemm_h<<<dim3(QDIM / 256, MROWS / 128, 1), 256, GEMM_SMEM>>>(
        xh, wqp, wqp, gq, gq, MROWS, QDIM, HID);
    gemm_h<<<dim3(QDIM / 256, MROWS / 128, 1), 256, GEMM_SMEM>>>(
        xh, wqp + QDIM / 2, wqp + QDIM / 2, gq + QDIM / 2, gq + QDIM / 2,
        MROWS, QDIM, HID);

    // 8: RoPE
    rope_fused<<<dim3(MROWS, 2), 256>>>(gq, gk);
    // 9: attention (fp16 output)
    attn_kernel<<<dim3(SS / 32, NH, BB), 256>>>(gq, gk, gv, ksuf, vsuf, valid, ah);
    // 10: output projection
    gemm_h<<<dim3(QDIM / 128, MROWS / 128, 1), 256, GEMM_SMEM>>>(
        ah, wop, wop, out, out, MROWS, QDIM, QDIM);
}

// round 9
// speedup vs baseline: 1.3142x; 1.0238x over previous
#include <cuda_runtime.h>
#include <cuda_fp16.h>
#include <math.h>
#include <stdint.h>

#define BB 2
#define SS 1024
#define HID 4096
#define NH 32
#define NKV 8
#define HD 128
#define LCK 3
#define MROWS (BB*SS)   // 2048
#define QDIM (NH*HD)    // 4096
#define KVDIM (NKV*HD)  // 1024
#define LOG2T 13.287712379549449f

// ---------------- scratch (static device globals; no allocations) ----------
__device__ float  g_q[(size_t)MROWS * QDIM];       // 32 MB (roped)
__device__ float  g_k[(size_t)MROWS * KVDIM];      // 8 MB (roped)
__device__ float  g_v[(size_t)MROWS * KVDIM];      // 8 MB
__device__ __half g_xh[(size_t)MROWS * HID];       // 16 MB (fp16 x)
__device__ __half g_ah[(size_t)MROWS * QDIM];      // 16 MB (fp16 attn out)
__device__ uint32_t g_wqp[(size_t)(HID/2) * QDIM]; // 32 MB packed fp16 pairs (perm cols)
__device__ uint32_t g_wkp[(size_t)(HID/2) * KVDIM];// perm cols
__device__ uint32_t g_wvp[(size_t)(HID/2) * KVDIM];
__device__ uint32_t g_wop[(size_t)(QDIM/2) * HID];

// ---------------- PTX helpers -----------------------------------------------
__device__ __forceinline__ void cp16(uint32_t dst, const void* src) {
    asm volatile("cp.async.cg.shared.global [%0], [%1], 16;" :: "r"(dst), "l"(src));
}
__device__ __forceinline__ uint32_t h2u(__half2 h) {
    union { __half2 h; uint32_t u; } cv;
    cv.h = h;
    return cv.u;
}
__device__ __forceinline__ void mma16(float* c, const uint32_t* a, const uint32_t* b) {
    asm volatile(
        "mma.sync.aligned.m16n8k16.row.col.f32.f16.f16.f32 "
        "{%0,%1,%2,%3},{%4,%5,%6,%7},{%8,%9},{%0,%1,%2,%3};"
        : "+f"(c[0]), "+f"(c[1]), "+f"(c[2]), "+f"(c[3])
        : "r"(a[0]), "r"(a[1]), "r"(a[2]), "r"(a[3]), "r"(b[0]), "r"(b[1]));
}
// packed f32x2 for attention
__device__ __forceinline__ unsigned long long fma2(unsigned long long a,
                                                   unsigned long long b,
                                                   unsigned long long c) {
    unsigned long long d;
    asm("fma.rn.f32x2 %0, %1, %2, %3;" : "=l"(d) : "l"(a), "l"(b), "l"(c));
    return d;
}
__device__ __forceinline__ unsigned long long mul2(unsigned long long a,
                                                   unsigned long long b) {
    unsigned long long d;
    asm("mul.rn.f32x2 %0, %1, %2;" : "=l"(d) : "l"(a), "l"(b));
    return d;
}
__device__ __forceinline__ unsigned long long pack2(float x) {
    unsigned long long d;
    asm("mov.b64 %0, {%1, %2};" : "=l"(d) : "f"(x), "f"(x));
    return d;
}
__device__ __forceinline__ void unpack2(unsigned long long v, float& lo, float& hi) {
    asm("mov.b64 {%0, %1}, %2;" : "=f"(lo), "=f"(hi) : "l"(v));
}

// ---------------- fused prep: x->fp16 + pack all 4 weights -------------------
// Region sizes in threads:
#define P_X  ((size_t)MROWS * HID / 4)          // 2M  (one float4 each)
#define P_WQ ((size_t)(HID/2) * (QDIM/4))       // 2M  (perm pack)
#define P_WK ((size_t)(HID/2) * (KVDIM/4))      // 512K (perm pack)
#define P_WV ((size_t)(HID/2) * (KVDIM/4))      // 512K (plain pack)
#define P_WO ((size_t)(QDIM/2) * (HID/4))       // 2M  (plain pack)
#define P_TOTAL (P_X + P_WQ + P_WK + P_WV + P_WO)  // 7M

__device__ __forceinline__ void pack_plain(const float* __restrict__ W,
                                           uint32_t* __restrict__ P, int N, size_t i) {
    const int npw = N >> 2;
    const int kp = (int)(i / npw);
    const int n4 = (int)(i - (size_t)kp * npw) * 4;
    float4 r0 = *(const float4*)(W + (size_t)(2 * kp) * N + n4);
    float4 r1 = *(const float4*)(W + (size_t)(2 * kp + 1) * N + n4);
    uint4 o;
    o.x = h2u(__floats2half2_rn(r0.x, r1.x));
    o.y = h2u(__floats2half2_rn(r0.y, r1.y));
    o.z = h2u(__floats2half2_rn(r0.z, r1.z));
    o.w = h2u(__floats2half2_rn(r0.w, r1.w));
    *(uint4*)(P + (size_t)kp * N + n4) = o;
}

// Permuted pack: output col c maps to orig col h*128 + (c%128)/2 + ((c&1)?64:0)
__device__ __forceinline__ void pack_perm(const float* __restrict__ W,
                                          uint32_t* __restrict__ P, int N, size_t i) {
    const int npw = N >> 2;
    const int kp = (int)(i / npw);
    const int n4 = (int)(i - (size_t)kp * npw) * 4;
    const float* w0 = W + (size_t)(2 * kp) * N;
    const float* w1 = W + (size_t)(2 * kp + 1) * N;
    uint32_t r[4];
#pragma unroll
    for (int j = 0; j < 4; j++) {
        const int c = n4 + j;
        const int h = c >> 7;
        const int w = c & 127;
        const int oc = (h << 7) + (w >> 1) + ((w & 1) << 6);
        r[j] = h2u(__floats2half2_rn(w0[oc], w1[oc]));
    }
    *(uint4*)(P + (size_t)kp * N + n4) = make_uint4(r[0], r[1], r[2], r[3]);
}

__global__ void prep_kernel(const float4* __restrict__ x,  __half* __restrict__ xh,
                            const float* __restrict__ Wq, uint32_t* __restrict__ wqp,
                            const float* __restrict__ Wk, uint32_t* __restrict__ wkp,
                            const float* __restrict__ Wv, uint32_t* __restrict__ wvp,
                            const float* __restrict__ Wo, uint32_t* __restrict__ wop) {
    size_t i = (size_t)blockIdx.x * 256 + threadIdx.x;
    if (i < P_X) {
        float4 v = x[i];
        *(__half2*)(xh + i * 4)     = __floats2half2_rn(v.x, v.y);
        *(__half2*)(xh + i * 4 + 2) = __floats2half2_rn(v.z, v.w);
    } else if ((i -= P_X) < P_WQ) {
        pack_perm(Wq, wqp, QDIM, i);
    } else if ((i -= P_WQ) < P_WK) {
        pack_perm(Wk, wkp, KVDIM, i);
    } else if ((i -= P_WK) < P_WV) {
        pack_plain(Wv, wvp, KVDIM, i);
    } else {
        i -= P_WV;
        pack_plain(Wo, wop, HID, i);
    }
}

// ---------------- fp16 tensor-core GEMM (+optional RoPE epilogue) ------------
// C[M,N] = A[M,K] @ B[K,N].  A fp16 row-major, B packed [K/2][N] {k,k+1} half2.
// Block 128x128, BK=32 halves, 8 warps (2Mx4N, 64x32 warp tiles), 3-stage cp.async.
// blockIdx.z selects (B0,C0) vs (B1,C1).  rope_mask bit z: apply RoPE epilogue
// (B was packed with permuted columns; epilogue un-permutes and rotates).
#define APITCHW 36
#define BPITCHW 136
#define ASZW (128 * APITCHW)
#define BSZW (16 * BPITCHW)
#define STGW (ASZW + BSZW)
#define GEMM_SMEM (3 * STGW * 4)  // 81408 B

__global__ __launch_bounds__(256, 2) void gemm_h(const __half* __restrict__ A,
                                                 const uint32_t* __restrict__ B0,
                                                 const uint32_t* __restrict__ B1,
                                                 float* __restrict__ C0,
                                                 float* __restrict__ C1,
                                                 int M, int N, int K, int rope_mask) {
    const uint32_t* B = blockIdx.z ? B1 : B0;
    float* C = blockIdx.z ? C1 : C0;
    const bool do_rope = (rope_mask >> blockIdx.z) & 1;

    extern __shared__ float sm[];
    const uint32_t smb = (uint32_t)__cvta_generic_to_shared(sm);
    const uint32_t* s32 = (const uint32_t*)sm;

    const int tid  = threadIdx.x;
    const int lane = tid & 31;
    const int wid  = tid >> 5;
    const int gid  = lane >> 2;
    const int tig  = lane & 3;
    const int wm   = (wid & 1) * 64;
    const int wn   = (wid >> 1) * 32;

    const int bm0 = blockIdx.y * 128;
    const int bn0 = blockIdx.x * 128;

    float acc[4][4][4];
#pragma unroll
    for (int mt = 0; mt < 4; mt++)
#pragma unroll
        for (int nt = 0; nt < 4; nt++)
#pragma unroll
            for (int i = 0; i < 4; i++) acc[mt][nt][i] = 0.f;

    const int T = K / 32;

    auto issue = [&](int t) {
        const uint32_t sb = smb + (uint32_t)((t % 3) * STGW * 4);
#pragma unroll
        for (int i = 0; i < 2; i++) {
            const int c = tid + i * 256;
            const int row = c >> 2;
            const int q = c & 3;
            cp16(sb + (uint32_t)(row * APITCHW * 4 + q * 16),
                 A + (size_t)(bm0 + row) * K + t * 32 + q * 8);
        }
#pragma unroll
        for (int i = 0; i < 2; i++) {
            const int c = tid + i * 256;
            const int kk = c >> 5;
            const int n4 = (c & 31) * 4;
            cp16(sb + (uint32_t)((ASZW + kk * BPITCHW + n4) * 4),
                 B + (size_t)(t * 16 + kk) * N + bn0 + n4);
        }
        asm volatile("cp.async.commit_group;");
    };

    issue(0);
    issue(1);

    for (int t = 0; t < T; t++) {
        if (t < T - 1) { asm volatile("cp.async.wait_group 1;"); }
        else           { asm volatile("cp.async.wait_group 0;"); }
        __syncthreads();
        if (t + 2 < T) issue(t + 2);

        const int so = (t % 3) * STGW;
        const uint32_t* sa = s32 + so;
        const uint32_t* sb = s32 + so + ASZW;
#pragma unroll
        for (int ks = 0; ks < 2; ks++) {
            const int w0 = ks * 8;
            uint32_t af[4][4];
#pragma unroll
            for (int mt = 0; mt < 4; mt++) {
                const int r = wm + mt * 16 + gid;
                af[mt][0] = sa[r * APITCHW + w0 + tig];
                af[mt][1] = sa[(r + 8) * APITCHW + w0 + tig];
                af[mt][2] = sa[r * APITCHW + w0 + tig + 4];
                af[mt][3] = sa[(r + 8) * APITCHW + w0 + tig + 4];
            }
            uint32_t bf[4][2];
#pragma unroll
            for (int nt = 0; nt < 4; nt++) {
                const int col = wn + nt * 8 + gid;
                bf[nt][0] = sb[(w0 + tig) * BPITCHW + col];
                bf[nt][1] = sb[(w0 + tig + 4) * BPITCHW + col];
            }
#pragma unroll
            for (int mt = 0; mt < 4; mt++)
#pragma unroll
                for (int nt = 0; nt < 4; nt++)
                    mma16(acc[mt][nt], af[mt], bf[nt]);
        }
        __syncthreads();
    }

    // ---- epilogue ----
    if (!do_rope) {
#pragma unroll
        for (int mt = 0; mt < 4; mt++) {
#pragma unroll
            for (int nt = 0; nt < 4; nt++) {
                const int r = bm0 + wm + mt * 16 + gid;
                const int cc = bn0 + wn + nt * 8 + tig * 2;
                *(float2*)&C[(size_t)r * N + cc] =
                    make_float2(acc[mt][nt][0], acc[mt][nt][1]);
                *(float2*)&C[(size_t)(r + 8) * N + cc] =
                    make_float2(acc[mt][nt][2], acc[mt][nt][3]);
            }
        }
    } else {
        // columns are permuted: cc=2u+p within head -> orig head*128 + u (+64 if p)
#pragma unroll
        for (int nt = 0; nt < 4; nt++) {
            const int cc = bn0 + wn + nt * 8 + tig * 2;   // even
            const int h = cc >> 7;
            const int u = (cc & 127) >> 1;
            const float inv = exp2f(-(float)(2 * u) * (1.0f / 128.0f) * LOG2T);
            const int c0 = h * 128 + u;
#pragma unroll
            for (int mt = 0; mt < 4; mt++) {
                const int r = bm0 + wm + mt * 16 + gid;
                {
                    const float ang = (float)(r & (SS - 1)) * inv;
                    const float cs = cosf(ang), sn = sinf(ang);
                    const float a0 = acc[mt][nt][0], a1 = acc[mt][nt][1];
                    C[(size_t)r * N + c0]      = a0 * cs - a1 * sn;
                    C[(size_t)r * N + c0 + 64] = a1 * cs + a0 * sn;
                }
                {
                    const int r2 = r + 8;
                    const float ang = (float)(r2 & (SS - 1)) * inv;
                    const float cs = cosf(ang), sn = sinf(ang);
                    const float a0 = acc[mt][nt][2], a1 = acc[mt][nt][3];
                    C[(size_t)r2 * N + c0]      = a0 * cs - a1 * sn;
                    C[(size_t)r2 * N + c0 + 64] = a1 * cs + a0 * sn;
                }
            }
        }
    }
}

// ---------------- flash attention (fp32 f32x2; 3-stage cp.async K/V) ---------
#define ATT_STGF (2 * 32 * 128)             // floats per stage (K + V)
#define ATT_SMEM (3 * ATT_STGF * 4)         // 98304 B

__global__ __launch_bounds__(256, 2) void attn_kernel(
        const float* __restrict__ q,
        const float* __restrict__ k,
        const float* __restrict__ v,
        const float* __restrict__ ksuf,
        const float* __restrict__ vsuf,
        const int* __restrict__ validp,
        __half* __restrict__ outh) {
    extern __shared__ float smA[];
    const uint32_t smb = (uint32_t)__cvta_generic_to_shared(smA);

    const int valid = *validp;
    const int qt = blockIdx.x;
    const int h  = blockIdx.y;
    const int b  = blockIdx.z;
    const int kvh = h >> 2;

    const int tid = threadIdx.x;
    const int ql  = tid >> 3;
    const int sub = tid & 7;
    const int q_global = qt * 32 + ql;
    const bool qvalid = q_global < valid;

    const float scale = 0.08838834764831845f;
    const unsigned long long scale2 = pack2(scale);

    unsigned long long q2[8];
    {
        const float* qp = q + (size_t)(b * SS + q_global) * QDIM + h * HD;
#pragma unroll
        for (int t = 0; t < 4; t++) {
            ulonglong2 u = *(const ulonglong2*)(qp + t * 32 + sub * 4);
            q2[2 * t]     = mul2(scale2, u.x);
            q2[2 * t + 1] = mul2(scale2, u.y);
        }
    }

    unsigned long long o2[8];
#pragma unroll
    for (int j = 0; j < 8; j++) o2[j] = 0ull;
    float m = -1e30f, l = 0.f;

    const float* kb_base = k + (size_t)(b * SS) * KVDIM + kvh * HD;
    const float* vb_base = v + (size_t)(b * SS) * KVDIM + kvh * HD;

    const int T = qt + 1;  // 32-key tiles (causal)

    auto issue = [&](int t) {
        const uint32_t sb = smb + (uint32_t)((t % 3) * ATT_STGF * 4);
        const int k0 = t * 32;
#pragma unroll
        for (int i = 0; i < 4; i++) {
            const int c = tid + i * 256;
            const int kk = c >> 5;
            const int d4 = (c & 31) * 4;
            cp16(sb + (uint32_t)((kk * 128 + d4) * 4),
                 kb_base + (size_t)(k0 + kk) * KVDIM + d4);
            cp16(sb + (uint32_t)((4096 + kk * 128 + d4) * 4),
                 vb_base + (size_t)(k0 + kk) * KVDIM + d4);
        }
        asm volatile("cp.async.commit_group;");
    };

    issue(0);
    if (T > 1) issue(1);

    for (int t = 0; t < T; t++) {
        if (t + 1 < T) { asm volatile("cp.async.wait_group 1;"); }
        else           { asm volatile("cp.async.wait_group 0;"); }
        __syncthreads();
        if (t + 2 < T) issue(t + 2);

        const float* Ks = smA + (t % 3) * ATT_STGF;
        const float* Vs = Ks + 4096;
        const int k0 = t * 32;

        float sc[32];
#pragma unroll 8
        for (int kk = 0; kk < 32; kk++) {
            unsigned long long p2 = 0ull;
#pragma unroll
            for (int tt = 0; tt < 4; tt++) {
                ulonglong2 kv = *(const ulonglong2*)&Ks[kk * 128 + tt * 32 + sub * 4];
                p2 = fma2(q2[2 * tt], kv.x, p2);
                p2 = fma2(q2[2 * tt + 1], kv.y, p2);
            }
            float plo, phi;
            unpack2(p2, plo, phi);
            float p = plo + phi;
            p += __shfl_xor_sync(0xffffffffu, p, 1);
            p += __shfl_xor_sync(0xffffffffu, p, 2);
            p += __shfl_xor_sync(0xffffffffu, p, 4);
            sc[kk] = (k0 + kk <= q_global) ? p : -1e30f;
        }

        float tmax = sc[0];
#pragma unroll
        for (int kk = 1; kk < 32; kk++) tmax = fmaxf(tmax, sc[kk]);
        const float mnew = fmaxf(m, tmax);
        const float corr = __expf(m - mnew);
        l *= corr;
        const unsigned long long corr2 = pack2(corr);
#pragma unroll
        for (int j = 0; j < 8; j++) o2[j] = mul2(corr2, o2[j]);

#pragma unroll 8
        for (int kk = 0; kk < 32; kk++) {
            const float p = __expf(sc[kk] - mnew);
            l += p;
            const unsigned long long p2 = pack2(p);
#pragma unroll
            for (int tt = 0; tt < 4; tt++) {
                ulonglong2 vv = *(const ulonglong2*)&Vs[kk * 128 + tt * 32 + sub * 4];
                o2[2 * tt]     = fma2(p2, vv.x, o2[2 * tt]);
                o2[2 * tt + 1] = fma2(p2, vv.y, o2[2 * tt + 1]);
            }
        }
        m = mnew;
        __syncthreads();
    }

    // ---- 3 suffix keys on the diagonal ----
#pragma unroll
    for (int j = 0; j < LCK; j++) {
        const size_t off =
            (((size_t)(b * NKV + kvh) * LCK + j) * SS + q_global) * HD;
        const float* kp = ksuf + off;
        unsigned long long p2 = 0ull;
#pragma unroll
        for (int tt = 0; tt < 4; tt++) {
            ulonglong2 kv = *(const ulonglong2*)(kp + tt * 32 + sub * 4);
            p2 = fma2(q2[2 * tt], kv.x, p2);
            p2 = fma2(q2[2 * tt + 1], kv.y, p2);
        }
        float plo, phi;
        unpack2(p2, plo, phi);
        float p = plo + phi;
        p += __shfl_xor_sync(0xffffffffu, p, 1);
        p += __shfl_xor_sync(0xffffffffu, p, 2);
        p += __shfl_xor_sync(0xffffffffu, p, 4);

        const float mnew = fmaxf(m, p);
        const float corr = __expf(m - mnew);
        const float e = __expf(p - mnew);
        l = l * corr + e;
        const unsigned long long corr2 = pack2(corr);
        const unsigned long long e2 = pack2(e);
        const float* vp = vsuf + off;
#pragma unroll
        for (int tt = 0; tt < 4; tt++) {
            ulonglong2 vv = *(const ulonglong2*)(vp + tt * 32 + sub * 4);
            o2[2 * tt]     = fma2(e2, vv.x, mul2(corr2, o2[2 * tt]));
            o2[2 * tt + 1] = fma2(e2, vv.y, mul2(corr2, o2[2 * tt + 1]));
        }
        m = mnew;
    }

    // epilogue: normalize, fp16 (feeds Wo GEMM), masked rows = 0
    const float invl = qvalid ? (1.0f / l) : 0.0f;
    __half* op = outh + (size_t)(b * SS + q_global) * QDIM + h * HD;
#pragma unroll
    for (int tt = 0; tt < 4; tt++) {
        float a0, a1, a2, a3;
        unpack2(o2[2 * tt], a0, a1);
        unpack2(o2[2 * tt + 1], a2, a3);
        *(__half2*)(op + tt * 32 + sub * 4)     = __floats2half2_rn(a0 * invl, a1 * invl);
        *(__half2*)(op + tt * 32 + sub * 4 + 2) = __floats2half2_rn(a2 * invl, a3 * invl);
    }
}

// ---------------- launch ----------------------------------------------------
extern "C" void kernel_launch(void* const* d_in, const int* in_sizes, int n_in,
                              void* d_out, int out_size) {
    const float* x    = (const float*)d_in[0];
    const float* ksuf = (const float*)d_in[1];
    const float* vsuf = (const float*)d_in[2];
    const float* Wq   = (const float*)d_in[3];
    const float* Wk   = (const float*)d_in[4];
    const float* Wv   = (const float*)d_in[5];
    const float* Wo   = (const float*)d_in[6];
    const int* valid  = (const int*)d_in[7];
    float* out = (float*)d_out;

    float *gq, *gk, *gv;
    __half *xh, *ah;
    uint32_t *wqp, *wkp, *wvp, *wop;
    cudaGetSymbolAddress((void**)&gq, g_q);
    cudaGetSymbolAddress((void**)&gk, g_k);
    cudaGetSymbolAddress((void**)&gv, g_v);
    cudaGetSymbolAddress((void**)&xh, g_xh);
    cudaGetSymbolAddress((void**)&ah, g_ah);
    cudaGetSymbolAddress((void**)&wqp, g_wqp);
    cudaGetSymbolAddress((void**)&wkp, g_wkp);
    cudaGetSymbolAddress((void**)&wvp, g_wvp);
    cudaGetSymbolAddress((void**)&wop, g_wop);

    cudaFuncSetAttribute(gemm_h, cudaFuncAttributeMaxDynamicSharedMemorySize, GEMM_SMEM);
    cudaFuncSetAttribute(attn_kernel, cudaFuncAttributeMaxDynamicSharedMemorySize, ATT_SMEM);

    // 0: fused prep (x->fp16, pack Wq/Wk permuted, Wv/Wo plain)
    prep_kernel<<<(unsigned)(P_TOTAL / 256), 256>>>(
        (const float4*)x, xh, Wq, wqp, Wk, wkp, Wv, wvp, Wo, wop);

    // 1: K and V projections (z=0: K with RoPE epilogue, z=1: V plain)
    gemm_h<<<dim3(KVDIM / 128, MROWS / 128, 2), 256, GEMM_SMEM>>>(
        xh, wkp, wvp, gk, gv, MROWS, KVDIM, HID, 0b01);

    // 2: Q projection (RoPE epilogue)
    gemm_h<<<dim3(QDIM / 128, MROWS / 128, 1), 256, GEMM_SMEM>>>(
        xh, wqp, wqp, gq, gq, MROWS, QDIM, HID, 0b01);

    // 3: attention (captured by ncu)
    attn_kernel<<<dim3(SS / 32, NH, BB), 256, ATT_SMEM>>>(
        gq, gk, gv, ksuf, vsuf, valid, ah);

    // 4: output projection
    gemm_h<<<dim3(QDIM / 128, MROWS / 128, 1), 256, GEMM_SMEM>>>(
        ah, wop, wop, out, out, MROWS, QDIM, QDIM, 0);
}

// round 10
// speedup vs baseline: 1.7843x; 1.3577x over previous
#include <cuda_runtime.h>
#include <cuda_fp16.h>
#include <math.h>
#include <stdint.h>

#define BB 2
#define SS 1024
#define HID 4096
#define NH 32
#define NKV 8
#define HD 128
#define LCK 3
#define MROWS (BB*SS)   // 2048
#define QDIM (NH*HD)    // 4096
#define KVDIM (NKV*HD)  // 1024
#define LOG2T 13.287712379549449f

// ---------------- scratch (static device globals; no allocations) ----------
__device__ float  g_q[(size_t)MROWS * QDIM];       // 32 MB (roped)
__device__ float  g_k[(size_t)MROWS * KVDIM];      // 8 MB (roped)
__device__ float  g_v[(size_t)MROWS * KVDIM];      // 8 MB
__device__ __half g_xh[(size_t)MROWS * HID];       // 16 MB (fp16 x)
__device__ __half g_ah[(size_t)MROWS * QDIM];      // 16 MB (fp16 attn out)
__device__ uint32_t g_wqp[(size_t)(HID/2) * QDIM]; // 32 MB packed fp16 pairs (perm cols)
__device__ uint32_t g_wkp[(size_t)(HID/2) * KVDIM];// perm cols
__device__ uint32_t g_wvp[(size_t)(HID/2) * KVDIM];
__device__ uint32_t g_wop[(size_t)(QDIM/2) * HID];

// ---------------- PTX helpers -----------------------------------------------
__device__ __forceinline__ void cp16(uint32_t dst, const void* src) {
    asm volatile("cp.async.cg.shared.global [%0], [%1], 16;" :: "r"(dst), "l"(src));
}
__device__ __forceinline__ uint32_t h2u(__half2 h) {
    union { __half2 h; uint32_t u; } cv;
    cv.h = h;
    return cv.u;
}
__device__ __forceinline__ void mma16(float* c, const uint32_t* a, const uint32_t* b) {
    asm volatile(
        "mma.sync.aligned.m16n8k16.row.col.f32.f16.f16.f32 "
        "{%0,%1,%2,%3},{%4,%5,%6,%7},{%8,%9},{%0,%1,%2,%3};"
        : "+f"(c[0]), "+f"(c[1]), "+f"(c[2]), "+f"(c[3])
        : "r"(a[0]), "r"(a[1]), "r"(a[2]), "r"(a[3]), "r"(b[0]), "r"(b[1]));
}
// packed f32x2 for attention
__device__ __forceinline__ unsigned long long fma2(unsigned long long a,
                                                   unsigned long long b,
                                                   unsigned long long c) {
    unsigned long long d;
    asm("fma.rn.f32x2 %0, %1, %2, %3;" : "=l"(d) : "l"(a), "l"(b), "l"(c));
    return d;
}
__device__ __forceinline__ unsigned long long mul2(unsigned long long a,
                                                   unsigned long long b) {
    unsigned long long d;
    asm("mul.rn.f32x2 %0, %1, %2;" : "=l"(d) : "l"(a), "l"(b));
    return d;
}
__device__ __forceinline__ unsigned long long pack2(float x) {
    unsigned long long d;
    asm("mov.b64 %0, {%1, %2};" : "=l"(d) : "f"(x), "f"(x));
    return d;
}
__device__ __forceinline__ void unpack2(unsigned long long v, float& lo, float& hi) {
    asm("mov.b64 {%0, %1}, %2;" : "=f"(lo), "=f"(hi) : "l"(v));
}

// ---------------- fused prep: x->fp16 + pack all 4 weights -------------------
#define P_X  ((size_t)MROWS * HID / 4)
#define P_WQ ((size_t)(HID/2) * (QDIM/4))
#define P_WK ((size_t)(HID/2) * (KVDIM/4))
#define P_WV ((size_t)(HID/2) * (KVDIM/4))
#define P_WO ((size_t)(QDIM/2) * (HID/4))
#define P_TOTAL (P_X + P_WQ + P_WK + P_WV + P_WO)

__device__ __forceinline__ void pack_plain(const float* __restrict__ W,
                                           uint32_t* __restrict__ P, int N, size_t i) {
    const int npw = N >> 2;
    const int kp = (int)(i / npw);
    const int n4 = (int)(i - (size_t)kp * npw) * 4;
    float4 r0 = *(const float4*)(W + (size_t)(2 * kp) * N + n4);
    float4 r1 = *(const float4*)(W + (size_t)(2 * kp + 1) * N + n4);
    uint4 o;
    o.x = h2u(__floats2half2_rn(r0.x, r1.x));
    o.y = h2u(__floats2half2_rn(r0.y, r1.y));
    o.z = h2u(__floats2half2_rn(r0.z, r1.z));
    o.w = h2u(__floats2half2_rn(r0.w, r1.w));
    *(uint4*)(P + (size_t)kp * N + n4) = o;
}

__device__ __forceinline__ void pack_perm(const float* __restrict__ W,
                                          uint32_t* __restrict__ P, int N, size_t i) {
    const int npw = N >> 2;
    const int kp = (int)(i / npw);
    const int n4 = (int)(i - (size_t)kp * npw) * 4;
    const float* w0 = W + (size_t)(2 * kp) * N;
    const float* w1 = W + (size_t)(2 * kp + 1) * N;
    uint32_t r[4];
#pragma unroll
    for (int j = 0; j < 4; j++) {
        const int c = n4 + j;
        const int h = c >> 7;
        const int w = c & 127;
        const int oc = (h << 7) + (w >> 1) + ((w & 1) << 6);
        r[j] = h2u(__floats2half2_rn(w0[oc], w1[oc]));
    }
    *(uint4*)(P + (size_t)kp * N + n4) = make_uint4(r[0], r[1], r[2], r[3]);
}

__global__ void prep_kernel(const float4* __restrict__ x,  __half* __restrict__ xh,
                            const float* __restrict__ Wq, uint32_t* __restrict__ wqp,
                            const float* __restrict__ Wk, uint32_t* __restrict__ wkp,
                            const float* __restrict__ Wv, uint32_t* __restrict__ wvp,
                            const float* __restrict__ Wo, uint32_t* __restrict__ wop) {
    size_t i = (size_t)blockIdx.x * 256 + threadIdx.x;
    if (i < P_X) {
        float4 v = x[i];
        *(__half2*)(xh + i * 4)     = __floats2half2_rn(v.x, v.y);
        *(__half2*)(xh + i * 4 + 2) = __floats2half2_rn(v.z, v.w);
    } else if ((i -= P_X) < P_WQ) {
        pack_perm(Wq, wqp, QDIM, i);
    } else if ((i -= P_WQ) < P_WK) {
        pack_perm(Wk, wkp, KVDIM, i);
    } else if ((i -= P_WK) < P_WV) {
        pack_plain(Wv, wvp, KVDIM, i);
    } else {
        i -= P_WV;
        pack_plain(Wo, wop, HID, i);
    }
}

// ---------------- fp16 tensor-core GEMM (+optional RoPE epilogue) ------------
#define APITCHW 36
#define BPITCHW 136
#define ASZW (128 * APITCHW)
#define BSZW (16 * BPITCHW)
#define STGW (ASZW + BSZW)
#define GEMM_SMEM (3 * STGW * 4)  // 81408 B

__global__ __launch_bounds__(256, 2) void gemm_h(const __half* __restrict__ A,
                                                 const uint32_t* __restrict__ B0,
                                                 const uint32_t* __restrict__ B1,
                                                 float* __restrict__ C0,
                                                 float* __restrict__ C1,
                                                 int M, int N, int K, int rope_mask) {
    const uint32_t* B = blockIdx.z ? B1 : B0;
    float* C = blockIdx.z ? C1 : C0;
    const bool do_rope = (rope_mask >> blockIdx.z) & 1;

    extern __shared__ float sm[];
    const uint32_t smb = (uint32_t)__cvta_generic_to_shared(sm);
    const uint32_t* s32 = (const uint32_t*)sm;

    const int tid  = threadIdx.x;
    const int lane = tid & 31;
    const int wid  = tid >> 5;
    const int gid  = lane >> 2;
    const int tig  = lane & 3;
    const int wm   = (wid & 1) * 64;
    const int wn   = (wid >> 1) * 32;

    const int bm0 = blockIdx.y * 128;
    const int bn0 = blockIdx.x * 128;

    float acc[4][4][4];
#pragma unroll
    for (int mt = 0; mt < 4; mt++)
#pragma unroll
        for (int nt = 0; nt < 4; nt++)
#pragma unroll
            for (int i = 0; i < 4; i++) acc[mt][nt][i] = 0.f;

    const int T = K / 32;

    auto issue = [&](int t) {
        const uint32_t sb = smb + (uint32_t)((t % 3) * STGW * 4);
#pragma unroll
        for (int i = 0; i < 2; i++) {
            const int c = tid + i * 256;
            const int row = c >> 2;
            const int q = c & 3;
            cp16(sb + (uint32_t)(row * APITCHW * 4 + q * 16),
                 A + (size_t)(bm0 + row) * K + t * 32 + q * 8);
        }
#pragma unroll
        for (int i = 0; i < 2; i++) {
            const int c = tid + i * 256;
            const int kk = c >> 5;
            const int n4 = (c & 31) * 4;
            cp16(sb + (uint32_t)((ASZW + kk * BPITCHW + n4) * 4),
                 B + (size_t)(t * 16 + kk) * N + bn0 + n4);
        }
        asm volatile("cp.async.commit_group;");
    };

    issue(0);
    issue(1);

    for (int t = 0; t < T; t++) {
        if (t < T - 1) { asm volatile("cp.async.wait_group 1;"); }
        else           { asm volatile("cp.async.wait_group 0;"); }
        __syncthreads();
        if (t + 2 < T) issue(t + 2);

        const int so = (t % 3) * STGW;
        const uint32_t* sa = s32 + so;
        const uint32_t* sb = s32 + so + ASZW;
#pragma unroll
        for (int ks = 0; ks < 2; ks++) {
            const int w0 = ks * 8;
            uint32_t af[4][4];
#pragma unroll
            for (int mt = 0; mt < 4; mt++) {
                const int r = wm + mt * 16 + gid;
                af[mt][0] = sa[r * APITCHW + w0 + tig];
                af[mt][1] = sa[(r + 8) * APITCHW + w0 + tig];
                af[mt][2] = sa[r * APITCHW + w0 + tig + 4];
                af[mt][3] = sa[(r + 8) * APITCHW + w0 + tig + 4];
            }
            uint32_t bf[4][2];
#pragma unroll
            for (int nt = 0; nt < 4; nt++) {
                const int col = wn + nt * 8 + gid;
                bf[nt][0] = sb[(w0 + tig) * BPITCHW + col];
                bf[nt][1] = sb[(w0 + tig + 4) * BPITCHW + col];
            }
#pragma unroll
            for (int mt = 0; mt < 4; mt++)
#pragma unroll
                for (int nt = 0; nt < 4; nt++)
                    mma16(acc[mt][nt], af[mt], bf[nt]);
        }
        __syncthreads();
    }

    if (!do_rope) {
#pragma unroll
        for (int mt = 0; mt < 4; mt++) {
#pragma unroll
            for (int nt = 0; nt < 4; nt++) {
                const int r = bm0 + wm + mt * 16 + gid;
                const int cc = bn0 + wn + nt * 8 + tig * 2;
                *(float2*)&C[(size_t)r * N + cc] =
                    make_float2(acc[mt][nt][0], acc[mt][nt][1]);
                *(float2*)&C[(size_t)(r + 8) * N + cc] =
                    make_float2(acc[mt][nt][2], acc[mt][nt][3]);
            }
        }
    } else {
#pragma unroll
        for (int nt = 0; nt < 4; nt++) {
            const int cc = bn0 + wn + nt * 8 + tig * 2;
            const int h = cc >> 7;
            const int u = (cc & 127) >> 1;
            const float inv = exp2f(-(float)(2 * u) * (1.0f / 128.0f) * LOG2T);
            const int c0 = h * 128 + u;
#pragma unroll
            for (int mt = 0; mt < 4; mt++) {
                const int r = bm0 + wm + mt * 16 + gid;
                {
                    const float ang = (float)(r & (SS - 1)) * inv;
                    const float cs = cosf(ang), sn = sinf(ang);
                    const float a0 = acc[mt][nt][0], a1 = acc[mt][nt][1];
                    C[(size_t)r * N + c0]      = a0 * cs - a1 * sn;
                    C[(size_t)r * N + c0 + 64] = a1 * cs + a0 * sn;
                }
                {
                    const int r2 = r + 8;
                    const float ang = (float)(r2 & (SS - 1)) * inv;
                    const float cs = cosf(ang), sn = sinf(ang);
                    const float a0 = acc[mt][nt][2], a1 = acc[mt][nt][3];
                    C[(size_t)r2 * N + c0]      = a0 * cs - a1 * sn;
                    C[(size_t)r2 * N + c0 + 64] = a1 * cs + a0 * sn;
                }
            }
        }
    }
}

// ---------------- flash attention v2: 2 queries/thread, 64 q/CTA -------------
// warp = 4 q-groups x 8 subs; each thread owns 2 queries x 16 dims.
// K/V chunks loaded once per lane feed BOTH queries -> LDS wavefronts per query
// halve vs R9.  8-key subtiles keep score regs at [2][8].
#define ATT_STGF (2 * 32 * 128)             // floats per stage (K + V)
#define ATT_SMEM (3 * ATT_STGF * 4)         // 98304 B

__global__ __launch_bounds__(256, 2) void attn_kernel(
        const float* __restrict__ q,
        const float* __restrict__ k,
        const float* __restrict__ v,
        const float* __restrict__ ksuf,
        const float* __restrict__ vsuf,
        const int* __restrict__ validp,
        __half* __restrict__ outh) {
    extern __shared__ float smA[];
    const uint32_t smb = (uint32_t)__cvta_generic_to_shared(smA);

    const int valid = *validp;
    const int h  = blockIdx.y;
    const int b  = blockIdx.z;
    const int kvh = h >> 2;

    const int tid = threadIdx.x;
    const int wid = tid >> 5;
    const int lane = tid & 31;
    const int sub = lane & 7;
    const int qg  = lane >> 3;
    const int q0 = blockIdx.x * 64 + wid * 8 + qg * 2;  // thread owns q0, q0+1

    const float scale = 0.08838834764831845f;
    const unsigned long long scale2 = pack2(scale);

    unsigned long long q2[2][8];
#pragma unroll
    for (int j = 0; j < 2; j++) {
        const float* qp = q + (size_t)(b * SS + q0 + j) * QDIM + h * HD;
#pragma unroll
        for (int t = 0; t < 4; t++) {
            ulonglong2 u = *(const ulonglong2*)(qp + t * 32 + sub * 4);
            q2[j][2 * t]     = mul2(scale2, u.x);
            q2[j][2 * t + 1] = mul2(scale2, u.y);
        }
    }

    unsigned long long o2[2][8];
#pragma unroll
    for (int j = 0; j < 2; j++)
#pragma unroll
        for (int c = 0; c < 8; c++) o2[j][c] = 0ull;
    float m[2] = {-1e30f, -1e30f}, l[2] = {0.f, 0.f};

    const float* kb_base = k + (size_t)(b * SS) * KVDIM + kvh * HD;
    const float* vb_base = v + (size_t)(b * SS) * KVDIM + kvh * HD;

    const int T = 2 * blockIdx.x + 2;  // key tiles (causal, 64 q per CTA)

    auto issue = [&](int t) {
        const uint32_t sb = smb + (uint32_t)((t % 3) * ATT_STGF * 4);
        const int k0 = t * 32;
#pragma unroll
        for (int i = 0; i < 4; i++) {
            const int c = tid + i * 256;
            const int kk = c >> 5;
            const int d4 = (c & 31) * 4;
            cp16(sb + (uint32_t)((kk * 128 + d4) * 4),
                 kb_base + (size_t)(k0 + kk) * KVDIM + d4);
            cp16(sb + (uint32_t)((4096 + kk * 128 + d4) * 4),
                 vb_base + (size_t)(k0 + kk) * KVDIM + d4);
        }
        asm volatile("cp.async.commit_group;");
    };

    issue(0);
    issue(1);

    for (int t = 0; t < T; t++) {
        if (t + 1 < T) { asm volatile("cp.async.wait_group 1;"); }
        else           { asm volatile("cp.async.wait_group 0;"); }
        __syncthreads();
        if (t + 2 < T) issue(t + 2);

        const float* Ks = smA + (t % 3) * ATT_STGF;
        const float* Vs = Ks + 4096;
        const int k0 = t * 32;

#pragma unroll
        for (int st = 0; st < 4; st++) {      // 8-key subtiles
            float sc[2][8];
#pragma unroll
            for (int kk8 = 0; kk8 < 8; kk8++) {
                const int kk = st * 8 + kk8;
                unsigned long long kc[8];
#pragma unroll
                for (int tt = 0; tt < 4; tt++) {
                    ulonglong2 u = *(const ulonglong2*)&Ks[kk * 128 + tt * 32 + sub * 4];
                    kc[2 * tt]     = u.x;
                    kc[2 * tt + 1] = u.y;
                }
#pragma unroll
                for (int j = 0; j < 2; j++) {
                    unsigned long long p2 = 0ull;
#pragma unroll
                    for (int c = 0; c < 8; c++) p2 = fma2(q2[j][c], kc[c], p2);
                    float plo, phi;
                    unpack2(p2, plo, phi);
                    float p = plo + phi;
                    p += __shfl_xor_sync(0xffffffffu, p, 1);
                    p += __shfl_xor_sync(0xffffffffu, p, 2);
                    p += __shfl_xor_sync(0xffffffffu, p, 4);
                    sc[j][kk8] = (k0 + kk <= q0 + j) ? p : -1e30f;
                }
            }
            // softmax update per query
#pragma unroll
            for (int j = 0; j < 2; j++) {
                float tmax = sc[j][0];
#pragma unroll
                for (int kk8 = 1; kk8 < 8; kk8++) tmax = fmaxf(tmax, sc[j][kk8]);
                const float mnew = fmaxf(m[j], tmax);
                const float corr = __expf(m[j] - mnew);
                l[j] *= corr;
                const unsigned long long corr2 = pack2(corr);
#pragma unroll
                for (int c = 0; c < 8; c++) o2[j][c] = mul2(corr2, o2[j][c]);
                m[j] = mnew;
#pragma unroll
                for (int kk8 = 0; kk8 < 8; kk8++) {
                    const float e = __expf(sc[j][kk8] - mnew);
                    l[j] += e;
                    sc[j][kk8] = e;
                }
            }
            // PV accumulate
#pragma unroll
            for (int kk8 = 0; kk8 < 8; kk8++) {
                const int kk = st * 8 + kk8;
                unsigned long long vc[8];
#pragma unroll
                for (int tt = 0; tt < 4; tt++) {
                    ulonglong2 u = *(const ulonglong2*)&Vs[kk * 128 + tt * 32 + sub * 4];
                    vc[2 * tt]     = u.x;
                    vc[2 * tt + 1] = u.y;
                }
#pragma unroll
                for (int j = 0; j < 2; j++) {
                    const unsigned long long e2 = pack2(sc[j][kk8]);
#pragma unroll
                    for (int c = 0; c < 8; c++) o2[j][c] = fma2(e2, vc[c], o2[j][c]);
                }
            }
        }
        __syncthreads();
    }

    // ---- 3 suffix keys on the diagonal (per query) ----
#pragma unroll
    for (int j = 0; j < 2; j++) {
#pragma unroll
        for (int sj = 0; sj < LCK; sj++) {
            const size_t off =
                (((size_t)(b * NKV + kvh) * LCK + sj) * SS + (q0 + j)) * HD;
            const float* kp = ksuf + off;
            unsigned long long p2 = 0ull;
#pragma unroll
            for (int tt = 0; tt < 4; tt++) {
                ulonglong2 kv = *(const ulonglong2*)(kp + tt * 32 + sub * 4);
                p2 = fma2(q2[j][2 * tt], kv.x, p2);
                p2 = fma2(q2[j][2 * tt + 1], kv.y, p2);
            }
            float plo, phi;
            unpack2(p2, plo, phi);
            float p = plo + phi;
            p += __shfl_xor_sync(0xffffffffu, p, 1);
            p += __shfl_xor_sync(0xffffffffu, p, 2);
            p += __shfl_xor_sync(0xffffffffu, p, 4);

            const float mnew = fmaxf(m[j], p);
            const float corr = __expf(m[j] - mnew);
            const float e = __expf(p - mnew);
            l[j] = l[j] * corr + e;
            const unsigned long long corr2 = pack2(corr);
            const unsigned long long e2 = pack2(e);
            const float* vp = vsuf + off;
#pragma unroll
            for (int tt = 0; tt < 4; tt++) {
                ulonglong2 vv = *(const ulonglong2*)(vp + tt * 32 + sub * 4);
                o2[j][2 * tt]     = fma2(e2, vv.x, mul2(corr2, o2[j][2 * tt]));
                o2[j][2 * tt + 1] = fma2(e2, vv.y, mul2(corr2, o2[j][2 * tt + 1]));
            }
            m[j] = mnew;
        }
    }

    // epilogue: normalize, fp16, masked rows = 0
#pragma unroll
    for (int j = 0; j < 2; j++) {
        const float invl = (q0 + j < valid) ? (1.0f / l[j]) : 0.0f;
        __half* op = outh + (size_t)(b * SS + q0 + j) * QDIM + h * HD;
#pragma unroll
        for (int tt = 0; tt < 4; tt++) {
            float a0, a1, a2, a3;
            unpack2(o2[j][2 * tt], a0, a1);
            unpack2(o2[j][2 * tt + 1], a2, a3);
            *(__half2*)(op + tt * 32 + sub * 4)     = __floats2half2_rn(a0 * invl, a1 * invl);
            *(__half2*)(op + tt * 32 + sub * 4 + 2) = __floats2half2_rn(a2 * invl, a3 * invl);
        }
    }
}

// ---------------- launch ----------------------------------------------------
extern "C" void kernel_launch(void* const* d_in, const int* in_sizes, int n_in,
                              void* d_out, int out_size) {
    const float* x    = (const float*)d_in[0];
    const float* ksuf = (const float*)d_in[1];
    const float* vsuf = (const float*)d_in[2];
    const float* Wq   = (const float*)d_in[3];
    const float* Wk   = (const float*)d_in[4];
    const float* Wv   = (const float*)d_in[5];
    const float* Wo   = (const float*)d_in[6];
    const int* valid  = (const int*)d_in[7];
    float* out = (float*)d_out;

    float *gq, *gk, *gv;
    __half *xh, *ah;
    uint32_t *wqp, *wkp, *wvp, *wop;
    cudaGetSymbolAddress((void**)&gq, g_q);
    cudaGetSymbolAddress((void**)&gk, g_k);
    cudaGetSymbolAddress((void**)&gv, g_v);
    cudaGetSymbolAddress((void**)&xh, g_xh);
    cudaGetSymbolAddress((void**)&ah, g_ah);
    cudaGetSymbolAddress((void**)&wqp, g_wqp);
    cudaGetSymbolAddress((void**)&wkp, g_wkp);
    cudaGetSymbolAddress((void**)&wvp, g_wvp);
    cudaGetSymbolAddress((void**)&wop, g_wop);

    cudaFuncSetAttribute(gemm_h, cudaFuncAttributeMaxDynamicSharedMemorySize, GEMM_SMEM);
    cudaFuncSetAttribute(attn_kernel, cudaFuncAttributeMaxDynamicSharedMemorySize, ATT_SMEM);

    // 0: fused prep
    prep_kernel<<<(unsigned)(P_TOTAL / 256), 256>>>(
        (const float4*)x, xh, Wq, wqp, Wk, wkp, Wv, wvp, Wo, wop);

    // 1: K and V projections (z=0: K with RoPE epilogue, z=1: V plain)
    gemm_h<<<dim3(KVDIM / 128, MROWS / 128, 2), 256, GEMM_SMEM>>>(
        xh, wkp, wvp, gk, gv, MROWS, KVDIM, HID, 0b01);

    // 2: Q projection (RoPE epilogue)
    gemm_h<<<dim3(QDIM / 128, MROWS / 128, 1), 256, GEMM_SMEM>>>(
        xh, wqp, wqp, gq, gq, MROWS, QDIM, HID, 0b01);

    // 3: attention (captured by ncu)
    attn_kernel<<<dim3(SS / 64, NH, BB), 256, ATT_SMEM>>>(
        gq, gk, gv, ksuf, vsuf, valid, ah);

    // 4: output projection
    gemm_h<<<dim3(QDIM / 128, MROWS / 128, 1), 256, GEMM_SMEM>>>(
        ah, wop, wop, out, out, MROWS, QDIM, QDIM, 0);
}

// round 11
// speedup vs baseline: 1.8977x; 1.0636x over previous
#include <cuda_runtime.h>
#include <cuda_fp16.h>
#include <math.h>
#include <stdint.h>

#define BB 2
#define SS 1024
#define HID 4096
#define NH 32
#define NKV 8
#define HD 128
#define LCK 3
#define MROWS (BB*SS)   // 2048
#define QDIM (NH*HD)    // 4096
#define KVDIM (NKV*HD)  // 1024
#define LOG2T 13.287712379549449f

// ---------------- scratch (static device globals; no allocations) ----------
__device__ float  g_q[(size_t)MROWS * QDIM];
__device__ float  g_k[(size_t)MROWS * KVDIM];
__device__ float  g_v[(size_t)MROWS * KVDIM];
__device__ __half g_xh[(size_t)MROWS * HID];
__device__ __half g_ah[(size_t)MROWS * QDIM];
__device__ uint32_t g_wqp[(size_t)(HID/2) * QDIM];
__device__ uint32_t g_wkp[(size_t)(HID/2) * KVDIM];
__device__ uint32_t g_wvp[(size_t)(HID/2) * KVDIM];
__device__ uint32_t g_wop[(size_t)(QDIM/2) * HID];

// ---------------- PTX helpers -----------------------------------------------
__device__ __forceinline__ void cp16(uint32_t dst, const void* src) {
    asm volatile("cp.async.cg.shared.global [%0], [%1], 16;" :: "r"(dst), "l"(src));
}
__device__ __forceinline__ uint32_t h2u(__half2 h) {
    union { __half2 h; uint32_t u; } cv;
    cv.h = h;
    return cv.u;
}
__device__ __forceinline__ void mma16(float* c, const uint32_t* a, const uint32_t* b) {
    asm volatile(
        "mma.sync.aligned.m16n8k16.row.col.f32.f16.f16.f32 "
        "{%0,%1,%2,%3},{%4,%5,%6,%7},{%8,%9},{%0,%1,%2,%3};"
        : "+f"(c[0]), "+f"(c[1]), "+f"(c[2]), "+f"(c[3])
        : "r"(a[0]), "r"(a[1]), "r"(a[2]), "r"(a[3]), "r"(b[0]), "r"(b[1]));
}
__device__ __forceinline__ void ldsm4(uint32_t* r, uint32_t addr) {
    asm volatile(
        "ldmatrix.sync.aligned.m8n8.x4.shared.b16 {%0,%1,%2,%3}, [%4];"
        : "=r"(r[0]), "=r"(r[1]), "=r"(r[2]), "=r"(r[3]) : "r"(addr));
}
// packed f32x2 for attention
__device__ __forceinline__ unsigned long long fma2(unsigned long long a,
                                                   unsigned long long b,
                                                   unsigned long long c) {
    unsigned long long d;
    asm("fma.rn.f32x2 %0, %1, %2, %3;" : "=l"(d) : "l"(a), "l"(b), "l"(c));
    return d;
}
__device__ __forceinline__ unsigned long long mul2(unsigned long long a,
                                                   unsigned long long b) {
    unsigned long long d;
    asm("mul.rn.f32x2 %0, %1, %2;" : "=l"(d) : "l"(a), "l"(b));
    return d;
}
__device__ __forceinline__ unsigned long long pack2(float x) {
    unsigned long long d;
    asm("mov.b64 %0, {%1, %2};" : "=l"(d) : "f"(x), "f"(x));
    return d;
}
__device__ __forceinline__ void unpack2(unsigned long long v, float& lo, float& hi) {
    asm("mov.b64 {%0, %1}, %2;" : "=f"(lo), "=f"(hi) : "l"(v));
}

// ---------------- fused prep: x->fp16 + pack all 4 weights -------------------
#define P_X  ((size_t)MROWS * HID / 4)
#define P_WQ ((size_t)(HID/2) * (QDIM/4))
#define P_WK ((size_t)(HID/2) * (KVDIM/4))
#define P_WV ((size_t)(HID/2) * (KVDIM/4))
#define P_WO ((size_t)(QDIM/2) * (HID/4))
#define P_TOTAL (P_X + P_WQ + P_WK + P_WV + P_WO)

__device__ __forceinline__ void pack_plain(const float* __restrict__ W,
                                           uint32_t* __restrict__ P, int N, size_t i) {
    const int npw = N >> 2;
    const int kp = (int)(i / npw);
    const int n4 = (int)(i - (size_t)kp * npw) * 4;
    float4 r0 = *(const float4*)(W + (size_t)(2 * kp) * N + n4);
    float4 r1 = *(const float4*)(W + (size_t)(2 * kp + 1) * N + n4);
    uint4 o;
    o.x = h2u(__floats2half2_rn(r0.x, r1.x));
    o.y = h2u(__floats2half2_rn(r0.y, r1.y));
    o.z = h2u(__floats2half2_rn(r0.z, r1.z));
    o.w = h2u(__floats2half2_rn(r0.w, r1.w));
    *(uint4*)(P + (size_t)kp * N + n4) = o;
}

__device__ __forceinline__ void pack_perm(const float* __restrict__ W,
                                          uint32_t* __restrict__ P, int N, size_t i) {
    const int npw = N >> 2;
    const int kp = (int)(i / npw);
    const int n4 = (int)(i - (size_t)kp * npw) * 4;
    const float* w0 = W + (size_t)(2 * kp) * N;
    const float* w1 = W + (size_t)(2 * kp + 1) * N;
    uint32_t r[4];
#pragma unroll
    for (int j = 0; j < 4; j++) {
        const int c = n4 + j;
        const int h = c >> 7;
        const int w = c & 127;
        const int oc = (h << 7) + (w >> 1) + ((w & 1) << 6);
        r[j] = h2u(__floats2half2_rn(w0[oc], w1[oc]));
    }
    *(uint4*)(P + (size_t)kp * N + n4) = make_uint4(r[0], r[1], r[2], r[3]);
}

__global__ void prep_kernel(const float4* __restrict__ x,  __half* __restrict__ xh,
                            const float* __restrict__ Wq, uint32_t* __restrict__ wqp,
                            const float* __restrict__ Wk, uint32_t* __restrict__ wkp,
                            const float* __restrict__ Wv, uint32_t* __restrict__ wvp,
                            const float* __restrict__ Wo, uint32_t* __restrict__ wop) {
    size_t i = (size_t)blockIdx.x * 256 + threadIdx.x;
    if (i < P_X) {
        float4 v = x[i];
        *(__half2*)(xh + i * 4)     = __floats2half2_rn(v.x, v.y);
        *(__half2*)(xh + i * 4 + 2) = __floats2half2_rn(v.z, v.w);
    } else if ((i -= P_X) < P_WQ) {
        pack_perm(Wq, wqp, QDIM, i);
    } else if ((i -= P_WQ) < P_WK) {
        pack_perm(Wk, wkp, KVDIM, i);
    } else if ((i -= P_WK) < P_WV) {
        pack_plain(Wv, wvp, KVDIM, i);
    } else {
        i -= P_WV;
        pack_plain(Wo, wop, HID, i);
    }
}

// ---------------- fp16 tensor-core GEMM (+optional RoPE epilogue) ------------
#define APITCHW 36
#define BPITCHW 136
#define ASZW (128 * APITCHW)
#define BSZW (16 * BPITCHW)
#define STGW (ASZW + BSZW)
#define GEMM_SMEM (3 * STGW * 4)  // 81408 B

__global__ __launch_bounds__(256, 2) void gemm_h(const __half* __restrict__ A,
                                                 const uint32_t* __restrict__ B0,
                                                 const uint32_t* __restrict__ B1,
                                                 float* __restrict__ C0,
                                                 float* __restrict__ C1,
                                                 int M, int N, int K, int rope_mask) {
    const uint32_t* B = blockIdx.z ? B1 : B0;
    float* C = blockIdx.z ? C1 : C0;
    const bool do_rope = (rope_mask >> blockIdx.z) & 1;

    extern __shared__ float sm[];
    const uint32_t smb = (uint32_t)__cvta_generic_to_shared(sm);
    const uint32_t* s32 = (const uint32_t*)sm;

    const int tid  = threadIdx.x;
    const int lane = tid & 31;
    const int wid  = tid >> 5;
    const int gid  = lane >> 2;
    const int tig  = lane & 3;
    const int wm   = (wid & 1) * 64;
    const int wn   = (wid >> 1) * 32;

    // ldmatrix lane mapping (x4: m8n8 matrices {m0-7,k0-7},{m8-15,k0-7},{m0-7,k8-15},{m8-15,k8-15})
    const int lrow   = lane & 7;
    const int lid4   = lane >> 3;
    const int a_moff = (lid4 & 1) * 8;
    const int a_woff = (lid4 >> 1) * 4;

    const int bm0 = blockIdx.y * 128;
    const int bn0 = blockIdx.x * 128;

    float acc[4][4][4];
#pragma unroll
    for (int mt = 0; mt < 4; mt++)
#pragma unroll
        for (int nt = 0; nt < 4; nt++)
#pragma unroll
            for (int i = 0; i < 4; i++) acc[mt][nt][i] = 0.f;

    const int T = K / 32;

    auto issue = [&](int t) {
        const uint32_t sb = smb + (uint32_t)((t % 3) * STGW * 4);
#pragma unroll
        for (int i = 0; i < 2; i++) {
            const int c = tid + i * 256;
            const int row = c >> 2;
            const int q = c & 3;
            cp16(sb + (uint32_t)(row * APITCHW * 4 + q * 16),
                 A + (size_t)(bm0 + row) * K + t * 32 + q * 8);
        }
#pragma unroll
        for (int i = 0; i < 2; i++) {
            const int c = tid + i * 256;
            const int kk = c >> 5;
            const int n4 = (c & 31) * 4;
            cp16(sb + (uint32_t)((ASZW + kk * BPITCHW + n4) * 4),
                 B + (size_t)(t * 16 + kk) * N + bn0 + n4);
        }
        asm volatile("cp.async.commit_group;");
    };

    issue(0);
    issue(1);

    for (int t = 0; t < T; t++) {
        if (t < T - 1) { asm volatile("cp.async.wait_group 1;"); }
        else           { asm volatile("cp.async.wait_group 0;"); }
        __syncthreads();
        if (t + 2 < T) issue(t + 2);

        const int so = (t % 3) * STGW;
        const uint32_t* sb = s32 + so + ASZW;
#pragma unroll
        for (int ks = 0; ks < 2; ks++) {
            const int w0 = ks * 8;
            uint32_t af[4][4];
#pragma unroll
            for (int mt = 0; mt < 4; mt++) {
                const uint32_t addr = smb + (uint32_t)(
                    (so + (wm + mt * 16 + a_moff + lrow) * APITCHW + w0 + a_woff) * 4);
                ldsm4(af[mt], addr);
            }
            uint32_t bf[4][2];
#pragma unroll
            for (int nt = 0; nt < 4; nt++) {
                const int col = wn + nt * 8 + gid;
                bf[nt][0] = sb[(w0 + tig) * BPITCHW + col];
                bf[nt][1] = sb[(w0 + tig + 4) * BPITCHW + col];
            }
#pragma unroll
            for (int mt = 0; mt < 4; mt++)
#pragma unroll
                for (int nt = 0; nt < 4; nt++)
                    mma16(acc[mt][nt], af[mt], bf[nt]);
        }
        __syncthreads();
    }

    if (!do_rope) {
#pragma unroll
        for (int mt = 0; mt < 4; mt++) {
#pragma unroll
            for (int nt = 0; nt < 4; nt++) {
                const int r = bm0 + wm + mt * 16 + gid;
                const int cc = bn0 + wn + nt * 8 + tig * 2;
                *(float2*)&C[(size_t)r * N + cc] =
                    make_float2(acc[mt][nt][0], acc[mt][nt][1]);
                *(float2*)&C[(size_t)(r + 8) * N + cc] =
                    make_float2(acc[mt][nt][2], acc[mt][nt][3]);
            }
        }
    } else {
#pragma unroll
        for (int nt = 0; nt < 4; nt++) {
            const int cc = bn0 + wn + nt * 8 + tig * 2;
            const int h = cc >> 7;
            const int u = (cc & 127) >> 1;
            const float inv = exp2f(-(float)(2 * u) * (1.0f / 128.0f) * LOG2T);
            const int c0 = h * 128 + u;
#pragma unroll
            for (int mt = 0; mt < 4; mt++) {
                const int r = bm0 + wm + mt * 16 + gid;
                {
                    const float ang = (float)(r & (SS - 1)) * inv;
                    const float cs = cosf(ang), sn = sinf(ang);
                    const float a0 = acc[mt][nt][0], a1 = acc[mt][nt][1];
                    C[(size_t)r * N + c0]      = a0 * cs - a1 * sn;
                    C[(size_t)r * N + c0 + 64] = a1 * cs + a0 * sn;
                }
                {
                    const int r2 = r + 8;
                    const float ang = (float)(r2 & (SS - 1)) * inv;
                    const float cs = cosf(ang), sn = sinf(ang);
                    const float a0 = acc[mt][nt][2], a1 = acc[mt][nt][3];
                    C[(size_t)r2 * N + c0]      = a0 * cs - a1 * sn;
                    C[(size_t)r2 * N + c0 + 64] = a1 * cs + a0 * sn;
                }
            }
        }
    }
}

// ---------------- flash attention v3: 2 q/thread + invalid-CTA early-out -----
#define ATT_STGF (2 * 32 * 128)
#define ATT_SMEM (3 * ATT_STGF * 4)  // 98304 B

__global__ __launch_bounds__(256, 2) void attn_kernel(
        const float* __restrict__ q,
        const float* __restrict__ k,
        const float* __restrict__ v,
        const float* __restrict__ ksuf,
        const float* __restrict__ vsuf,
        const int* __restrict__ validp,
        __half* __restrict__ outh) {
    extern __shared__ float smA[];
    const uint32_t smb = (uint32_t)__cvta_generic_to_shared(smA);

    const int valid = *validp;
    const int h  = blockIdx.y;
    const int b  = blockIdx.z;
    const int kvh = h >> 2;
    const int tid = threadIdx.x;
    const int q0base = blockIdx.x * 64;

    // fully-invalid CTA: write zeros, skip all work (saves the heaviest CTAs)
    if (q0base >= valid) {
        const __half2 z2 = __floats2half2_rn(0.f, 0.f);
        const int row = tid >> 6;           // 0..3
        const int col = (tid & 63) * 2;
#pragma unroll
        for (int r = 0; r < 64; r += 4) {
            *(__half2*)(outh + (size_t)(b * SS + q0base + r + row) * QDIM + h * HD + col) = z2;
        }
        return;
    }

    const int wid = tid >> 5;
    const int lane = tid & 31;
    const int sub = lane & 7;
    const int qg  = lane >> 3;
    const int q0 = q0base + wid * 8 + qg * 2;

    const float scale = 0.08838834764831845f;
    const unsigned long long scale2 = pack2(scale);

    unsigned long long q2[2][8];
#pragma unroll
    for (int j = 0; j < 2; j++) {
        const float* qp = q + (size_t)(b * SS + q0 + j) * QDIM + h * HD;
#pragma unroll
        for (int t = 0; t < 4; t++) {
            ulonglong2 u = *(const ulonglong2*)(qp + t * 32 + sub * 4);
            q2[j][2 * t]     = mul2(scale2, u.x);
            q2[j][2 * t + 1] = mul2(scale2, u.y);
        }
    }

    unsigned long long o2[2][8];
#pragma unroll
    for (int j = 0; j < 2; j++)
#pragma unroll
        for (int c = 0; c < 8; c++) o2[j][c] = 0ull;
    float m[2] = {-1e30f, -1e30f}, l[2] = {0.f, 0.f};

    const float* kb_base = k + (size_t)(b * SS) * KVDIM + kvh * HD;
    const float* vb_base = v + (size_t)(b * SS) * KVDIM + kvh * HD;

    const int Tcap = (valid + 31) >> 5;
    const int T = min(2 * blockIdx.x + 2, Tcap);

    auto issue = [&](int t) {
        const uint32_t sb = smb + (uint32_t)((t % 3) * ATT_STGF * 4);
        const int k0 = t * 32;
#pragma unroll
        for (int i = 0; i < 4; i++) {
            const int c = tid + i * 256;
            const int kk = c >> 5;
            const int d4 = (c & 31) * 4;
            cp16(sb + (uint32_t)((kk * 128 + d4) * 4),
                 kb_base + (size_t)(k0 + kk) * KVDIM + d4);
            cp16(sb + (uint32_t)((4096 + kk * 128 + d4) * 4),
                 vb_base + (size_t)(k0 + kk) * KVDIM + d4);
        }
        asm volatile("cp.async.commit_group;");
    };

    issue(0);
    if (T > 1) issue(1);

    for (int t = 0; t < T; t++) {
        if (t + 1 < T) { asm volatile("cp.async.wait_group 1;"); }
        else           { asm volatile("cp.async.wait_group 0;"); }
        __syncthreads();
        if (t + 2 < T) issue(t + 2);

        const float* Ks = smA + (t % 3) * ATT_STGF;
        const float* Vs = Ks + 4096;
        const int k0 = t * 32;

#pragma unroll
        for (int st = 0; st < 4; st++) {
            float sc[2][8];
#pragma unroll
            for (int kk8 = 0; kk8 < 8; kk8++) {
                const int kk = st * 8 + kk8;
                unsigned long long kc[8];
#pragma unroll
                for (int tt = 0; tt < 4; tt++) {
                    ulonglong2 u = *(const ulonglong2*)&Ks[kk * 128 + tt * 32 + sub * 4];
                    kc[2 * tt]     = u.x;
                    kc[2 * tt + 1] = u.y;
                }
#pragma unroll
                for (int j = 0; j < 2; j++) {
                    unsigned long long p2 = 0ull;
#pragma unroll
                    for (int c = 0; c < 8; c++) p2 = fma2(q2[j][c], kc[c], p2);
                    float plo, phi;
                    unpack2(p2, plo, phi);
                    float p = plo + phi;
                    p += __shfl_xor_sync(0xffffffffu, p, 1);
                    p += __shfl_xor_sync(0xffffffffu, p, 2);
                    p += __shfl_xor_sync(0xffffffffu, p, 4);
                    sc[j][kk8] = (k0 + kk <= q0 + j) ? p : -1e30f;
                }
            }
#pragma unroll
            for (int j = 0; j < 2; j++) {
                float tmax = sc[j][0];
#pragma unroll
                for (int kk8 = 1; kk8 < 8; kk8++) tmax = fmaxf(tmax, sc[j][kk8]);
                const float mnew = fmaxf(m[j], tmax);
                const float corr = __expf(m[j] - mnew);
                l[j] *= corr;
                const unsigned long long corr2 = pack2(corr);
#pragma unroll
                for (int c = 0; c < 8; c++) o2[j][c] = mul2(corr2, o2[j][c]);
                m[j] = mnew;
#pragma unroll
                for (int kk8 = 0; kk8 < 8; kk8++) {
                    const float e = __expf(sc[j][kk8] - mnew);
                    l[j] += e;
                    sc[j][kk8] = e;
                }
            }
#pragma unroll
            for (int kk8 = 0; kk8 < 8; kk8++) {
                const int kk = st * 8 + kk8;
                unsigned long long vc[8];
#pragma unroll
                for (int tt = 0; tt < 4; tt++) {
                    ulonglong2 u = *(const ulonglong2*)&Vs[kk * 128 + tt * 32 + sub * 4];
                    vc[2 * tt]     = u.x;
                    vc[2 * tt + 1] = u.y;
                }
#pragma unroll
                for (int j = 0; j < 2; j++) {
                    const unsigned long long e2 = pack2(sc[j][kk8]);
#pragma unroll
                    for (int c = 0; c < 8; c++) o2[j][c] = fma2(e2, vc[c], o2[j][c]);
                }
            }
        }
        __syncthreads();
    }

    // ---- 3 suffix keys on the diagonal (per query) ----
#pragma unroll
    for (int j = 0; j < 2; j++) {
#pragma unroll
        for (int sj = 0; sj < LCK; sj++) {
            const size_t off =
                (((size_t)(b * NKV + kvh) * LCK + sj) * SS + (q0 + j)) * HD;
            const float* kp = ksuf + off;
            unsigned long long p2 = 0ull;
#pragma unroll
            for (int tt = 0; tt < 4; tt++) {
                ulonglong2 kv = *(const ulonglong2*)(kp + tt * 32 + sub * 4);
                p2 = fma2(q2[j][2 * tt], kv.x, p2);
                p2 = fma2(q2[j][2 * tt + 1], kv.y, p2);
            }
            float plo, phi;
            unpack2(p2, plo, phi);
            float p = plo + phi;
            p += __shfl_xor_sync(0xffffffffu, p, 1);
            p += __shfl_xor_sync(0xffffffffu, p, 2);
            p += __shfl_xor_sync(0xffffffffu, p, 4);

            const float mnew = fmaxf(m[j], p);
            const float corr = __expf(m[j] - mnew);
            const float e = __expf(p - mnew);
            l[j] = l[j] * corr + e;
            const unsigned long long corr2 = pack2(corr);
            const unsigned long long e2 = pack2(e);
            const float* vp = vsuf + off;
#pragma unroll
            for (int tt = 0; tt < 4; tt++) {
                ulonglong2 vv = *(const ulonglong2*)(vp + tt * 32 + sub * 4);
                o2[j][2 * tt]     = fma2(e2, vv.x, mul2(corr2, o2[j][2 * tt]));
                o2[j][2 * tt + 1] = fma2(e2, vv.y, mul2(corr2, o2[j][2 * tt + 1]));
            }
            m[j] = mnew;
        }
    }

    // epilogue: normalize, fp16, masked rows = 0
#pragma unroll
    for (int j = 0; j < 2; j++) {
        const float invl = (q0 + j < valid) ? (1.0f / l[j]) : 0.0f;
        __half* op = outh + (size_t)(b * SS + q0 + j) * QDIM + h * HD;
#pragma unroll
        for (int tt = 0; tt < 4; tt++) {
            float a0, a1, a2, a3;
            unpack2(o2[j][2 * tt], a0, a1);
            unpack2(o2[j][2 * tt + 1], a2, a3);
            *(__half2*)(op + tt * 32 + sub * 4)     = __floats2half2_rn(a0 * invl, a1 * invl);
            *(__half2*)(op + tt * 32 + sub * 4 + 2) = __floats2half2_rn(a2 * invl, a3 * invl);
        }
    }
}

// ---------------- launch ----------------------------------------------------
extern "C" void kernel_launch(void* const* d_in, const int* in_sizes, int n_in,
                              void* d_out, int out_size) {
    const float* x    = (const float*)d_in[0];
    const float* ksuf = (const float*)d_in[1];
    const float* vsuf = (const float*)d_in[2];
    const float* Wq   = (const float*)d_in[3];
    const float* Wk   = (const float*)d_in[4];
    const float* Wv   = (const float*)d_in[5];
    const float* Wo   = (const float*)d_in[6];
    const int* valid  = (const int*)d_in[7];
    float* out = (float*)d_out;

    float *gq, *gk, *gv;
    __half *xh, *ah;
    uint32_t *wqp, *wkp, *wvp, *wop;
    cudaGetSymbolAddress((void**)&gq, g_q);
    cudaGetSymbolAddress((void**)&gk, g_k);
    cudaGetSymbolAddress((void**)&gv, g_v);
    cudaGetSymbolAddress((void**)&xh, g_xh);
    cudaGetSymbolAddress((void**)&ah, g_ah);
    cudaGetSymbolAddress((void**)&wqp, g_wqp);
    cudaGetSymbolAddress((void**)&wkp, g_wkp);
    cudaGetSymbolAddress((void**)&wvp, g_wvp);
    cudaGetSymbolAddress((void**)&wop, g_wop);

    cudaFuncSetAttribute(gemm_h, cudaFuncAttributeMaxDynamicSharedMemorySize, GEMM_SMEM);
    cudaFuncSetAttribute(attn_kernel, cudaFuncAttributeMaxDynamicSharedMemorySize, ATT_SMEM);

    // 0: fused prep
    prep_kernel<<<(unsigned)(P_TOTAL / 256), 256>>>(
        (const float4*)x, xh, Wq, wqp, Wk, wkp, Wv, wvp, Wo, wop);

    // 1: K and V projections (z=0: K with RoPE epilogue, z=1: V plain)
    gemm_h<<<dim3(KVDIM / 128, MROWS / 128, 2), 256, GEMM_SMEM>>>(
        xh, wkp, wvp, gk, gv, MROWS, KVDIM, HID, 0b01);

    // 2: Q projection (RoPE epilogue)
    gemm_h<<<dim3(QDIM / 128, MROWS / 128, 1), 256, GEMM_SMEM>>>(
        xh, wqp, wqp, gq, gq, MROWS, QDIM, HID, 0b01);

    // 3: attention (captured by ncu)
    attn_kernel<<<dim3(SS / 64, NH, BB), 256, ATT_SMEM>>>(
        gq, gk, gv, ksuf, vsuf, valid, ah);

    // 4: output projection
    gemm_h<<<dim3(QDIM / 128, MROWS / 128, 1), 256, GEMM_SMEM>>>(
        ah, wop, wop, out, out, MROWS, QDIM, QDIM, 0);
}

// round 12
// speedup vs baseline: 1.9549x; 1.0301x over previous
#include <cuda_runtime.h>
#include <cuda_fp16.h>
#include <math.h>
#include <stdint.h>

#define BB 2
#define SS 1024
#define HID 4096
#define NH 32
#define NKV 8
#define HD 128
#define LCK 3
#define MROWS (BB*SS)   // 2048
#define QDIM (NH*HD)    // 4096
#define KVDIM (NKV*HD)  // 1024
#define LOG2T 13.287712379549449f

// ---------------- scratch (static device globals; no allocations) ----------
__device__ float  g_q[(size_t)MROWS * QDIM];
__device__ float  g_k[(size_t)MROWS * KVDIM];
__device__ __half g_vh[(size_t)MROWS * KVDIM];     // fp16 V
__device__ __half g_xh[(size_t)MROWS * HID];
__device__ __half g_ah[(size_t)MROWS * QDIM];
__device__ uint32_t g_wqp[(size_t)(HID/2) * QDIM];
__device__ uint32_t g_wkp[(size_t)(HID/2) * KVDIM];
__device__ uint32_t g_wvp[(size_t)(HID/2) * KVDIM];
__device__ uint32_t g_wop[(size_t)(QDIM/2) * HID];

// ---------------- PTX helpers -----------------------------------------------
__device__ __forceinline__ void cp16(uint32_t dst, const void* src) {
    asm volatile("cp.async.cg.shared.global [%0], [%1], 16;" :: "r"(dst), "l"(src));
}
__device__ __forceinline__ uint32_t h2u(__half2 h) {
    union { __half2 h; uint32_t u; } cv;
    cv.h = h;
    return cv.u;
}
__device__ __forceinline__ void mma16(float* c, const uint32_t* a, const uint32_t* b) {
    asm volatile(
        "mma.sync.aligned.m16n8k16.row.col.f32.f16.f16.f32 "
        "{%0,%1,%2,%3},{%4,%5,%6,%7},{%8,%9},{%0,%1,%2,%3};"
        : "+f"(c[0]), "+f"(c[1]), "+f"(c[2]), "+f"(c[3])
        : "r"(a[0]), "r"(a[1]), "r"(a[2]), "r"(a[3]), "r"(b[0]), "r"(b[1]));
}
__device__ __forceinline__ void ldsm4(uint32_t* r, uint32_t addr) {
    asm volatile(
        "ldmatrix.sync.aligned.m8n8.x4.shared.b16 {%0,%1,%2,%3}, [%4];"
        : "=r"(r[0]), "=r"(r[1]), "=r"(r[2]), "=r"(r[3]) : "r"(addr));
}
// packed f32x2
__device__ __forceinline__ unsigned long long fma2(unsigned long long a,
                                                   unsigned long long b,
                                                   unsigned long long c) {
    unsigned long long d;
    asm("fma.rn.f32x2 %0, %1, %2, %3;" : "=l"(d) : "l"(a), "l"(b), "l"(c));
    return d;
}
__device__ __forceinline__ unsigned long long mul2(unsigned long long a,
                                                   unsigned long long b) {
    unsigned long long d;
    asm("mul.rn.f32x2 %0, %1, %2;" : "=l"(d) : "l"(a), "l"(b));
    return d;
}
__device__ __forceinline__ unsigned long long pack2(float x) {
    unsigned long long d;
    asm("mov.b64 %0, {%1, %2};" : "=l"(d) : "f"(x), "f"(x));
    return d;
}
__device__ __forceinline__ unsigned long long packf2(float lo, float hi) {
    unsigned long long d;
    asm("mov.b64 %0, {%1, %2};" : "=l"(d) : "f"(lo), "f"(hi));
    return d;
}
__device__ __forceinline__ void unpack2(unsigned long long v, float& lo, float& hi) {
    asm("mov.b64 {%0, %1}, %2;" : "=f"(lo), "=f"(hi) : "l"(v));
}

// ---------------- fused prep: x->fp16 + pack all 4 weights -------------------
#define P_X  ((size_t)MROWS * HID / 4)
#define P_WQ ((size_t)(HID/2) * (QDIM/4))
#define P_WK ((size_t)(HID/2) * (KVDIM/4))
#define P_WV ((size_t)(HID/2) * (KVDIM/4))
#define P_WO ((size_t)(QDIM/2) * (HID/4))
#define P_TOTAL (P_X + P_WQ + P_WK + P_WV + P_WO)

__device__ __forceinline__ void pack_plain(const float* __restrict__ W,
                                           uint32_t* __restrict__ P, int N, size_t i) {
    const int npw = N >> 2;
    const int kp = (int)(i / npw);
    const int n4 = (int)(i - (size_t)kp * npw) * 4;
    float4 r0 = *(const float4*)(W + (size_t)(2 * kp) * N + n4);
    float4 r1 = *(const float4*)(W + (size_t)(2 * kp + 1) * N + n4);
    uint4 o;
    o.x = h2u(__floats2half2_rn(r0.x, r1.x));
    o.y = h2u(__floats2half2_rn(r0.y, r1.y));
    o.z = h2u(__floats2half2_rn(r0.z, r1.z));
    o.w = h2u(__floats2half2_rn(r0.w, r1.w));
    *(uint4*)(P + (size_t)kp * N + n4) = o;
}

__device__ __forceinline__ void pack_perm(const float* __restrict__ W,
                                          uint32_t* __restrict__ P, int N, size_t i) {
    const int npw = N >> 2;
    const int kp = (int)(i / npw);
    const int n4 = (int)(i - (size_t)kp * npw) * 4;
    const float* w0 = W + (size_t)(2 * kp) * N;
    const float* w1 = W + (size_t)(2 * kp + 1) * N;
    uint32_t r[4];
#pragma unroll
    for (int j = 0; j < 4; j++) {
        const int c = n4 + j;
        const int h = c >> 7;
        const int w = c & 127;
        const int oc = (h << 7) + (w >> 1) + ((w & 1) << 6);
        r[j] = h2u(__floats2half2_rn(w0[oc], w1[oc]));
    }
    *(uint4*)(P + (size_t)kp * N + n4) = make_uint4(r[0], r[1], r[2], r[3]);
}

__global__ void prep_kernel(const float4* __restrict__ x,  __half* __restrict__ xh,
                            const float* __restrict__ Wq, uint32_t* __restrict__ wqp,
                            const float* __restrict__ Wk, uint32_t* __restrict__ wkp,
                            const float* __restrict__ Wv, uint32_t* __restrict__ wvp,
                            const float* __restrict__ Wo, uint32_t* __restrict__ wop) {
    size_t i = (size_t)blockIdx.x * 256 + threadIdx.x;
    if (i < P_X) {
        float4 v = x[i];
        *(__half2*)(xh + i * 4)     = __floats2half2_rn(v.x, v.y);
        *(__half2*)(xh + i * 4 + 2) = __floats2half2_rn(v.z, v.w);
    } else if ((i -= P_X) < P_WQ) {
        pack_perm(Wq, wqp, QDIM, i);
    } else if ((i -= P_WQ) < P_WK) {
        pack_perm(Wk, wkp, KVDIM, i);
    } else if ((i -= P_WK) < P_WV) {
        pack_plain(Wv, wvp, KVDIM, i);
    } else {
        i -= P_WV;
        pack_plain(Wo, wop, HID, i);
    }
}

// ---------------- fp16 tensor-core GEMM (+RoPE or fp16-out epilogue) ---------
#define APITCHW 36
#define BPITCHW 136
#define ASZW (128 * APITCHW)
#define BSZW (16 * BPITCHW)
#define STGW (ASZW + BSZW)
#define GEMM_SMEM (3 * STGW * 4)  // 81408 B

__global__ __launch_bounds__(256, 2) void gemm_h(const __half* __restrict__ A,
                                                 const uint32_t* __restrict__ B0,
                                                 const uint32_t* __restrict__ B1,
                                                 float* __restrict__ C0,
                                                 float* __restrict__ C1,
                                                 __half* __restrict__ CH,
                                                 int M, int N, int K,
                                                 int rope_mask, int half_mask) {
    const uint32_t* B = blockIdx.z ? B1 : B0;
    float* C = blockIdx.z ? C1 : C0;
    const bool do_rope = (rope_mask >> blockIdx.z) & 1;
    const bool do_half = (half_mask >> blockIdx.z) & 1;

    extern __shared__ float sm[];
    const uint32_t smb = (uint32_t)__cvta_generic_to_shared(sm);
    const uint32_t* s32 = (const uint32_t*)sm;

    const int tid  = threadIdx.x;
    const int lane = tid & 31;
    const int wid  = tid >> 5;
    const int gid  = lane >> 2;
    const int tig  = lane & 3;
    const int wm   = (wid & 1) * 64;
    const int wn   = (wid >> 1) * 32;

    const int lrow   = lane & 7;
    const int lid4   = lane >> 3;
    const int a_moff = (lid4 & 1) * 8;
    const int a_woff = (lid4 >> 1) * 4;

    const int bm0 = blockIdx.y * 128;
    const int bn0 = blockIdx.x * 128;

    float acc[4][4][4];
#pragma unroll
    for (int mt = 0; mt < 4; mt++)
#pragma unroll
        for (int nt = 0; nt < 4; nt++)
#pragma unroll
            for (int i = 0; i < 4; i++) acc[mt][nt][i] = 0.f;

    const int T = K / 32;

    auto issue = [&](int t) {
        const uint32_t sb = smb + (uint32_t)((t % 3) * STGW * 4);
#pragma unroll
        for (int i = 0; i < 2; i++) {
            const int c = tid + i * 256;
            const int row = c >> 2;
            const int q = c & 3;
            cp16(sb + (uint32_t)(row * APITCHW * 4 + q * 16),
                 A + (size_t)(bm0 + row) * K + t * 32 + q * 8);
        }
#pragma unroll
        for (int i = 0; i < 2; i++) {
            const int c = tid + i * 256;
            const int kk = c >> 5;
            const int n4 = (c & 31) * 4;
            cp16(sb + (uint32_t)((ASZW + kk * BPITCHW + n4) * 4),
                 B + (size_t)(t * 16 + kk) * N + bn0 + n4);
        }
        asm volatile("cp.async.commit_group;");
    };

    issue(0);
    issue(1);

    for (int t = 0; t < T; t++) {
        if (t < T - 1) { asm volatile("cp.async.wait_group 1;"); }
        else           { asm volatile("cp.async.wait_group 0;"); }
        __syncthreads();
        if (t + 2 < T) issue(t + 2);

        const int so = (t % 3) * STGW;
        const uint32_t* sb = s32 + so + ASZW;
#pragma unroll
        for (int ks = 0; ks < 2; ks++) {
            const int w0 = ks * 8;
            uint32_t af[4][4];
#pragma unroll
            for (int mt = 0; mt < 4; mt++) {
                const uint32_t addr = smb + (uint32_t)(
                    (so + (wm + mt * 16 + a_moff + lrow) * APITCHW + w0 + a_woff) * 4);
                ldsm4(af[mt], addr);
            }
            uint32_t bf[4][2];
#pragma unroll
            for (int nt = 0; nt < 4; nt++) {
                const int col = wn + nt * 8 + gid;
                bf[nt][0] = sb[(w0 + tig) * BPITCHW + col];
                bf[nt][1] = sb[(w0 + tig + 4) * BPITCHW + col];
            }
#pragma unroll
            for (int mt = 0; mt < 4; mt++)
#pragma unroll
                for (int nt = 0; nt < 4; nt++)
                    mma16(acc[mt][nt], af[mt], bf[nt]);
        }
        __syncthreads();
    }

    if (do_rope) {
#pragma unroll
        for (int nt = 0; nt < 4; nt++) {
            const int cc = bn0 + wn + nt * 8 + tig * 2;
            const int h = cc >> 7;
            const int u = (cc & 127) >> 1;
            const float inv = exp2f(-(float)(2 * u) * (1.0f / 128.0f) * LOG2T);
            const int c0 = h * 128 + u;
#pragma unroll
            for (int mt = 0; mt < 4; mt++) {
                const int r = bm0 + wm + mt * 16 + gid;
                {
                    const float ang = (float)(r & (SS - 1)) * inv;
                    const float cs = cosf(ang), sn = sinf(ang);
                    const float a0 = acc[mt][nt][0], a1 = acc[mt][nt][1];
                    C[(size_t)r * N + c0]      = a0 * cs - a1 * sn;
                    C[(size_t)r * N + c0 + 64] = a1 * cs + a0 * sn;
                }
                {
                    const int r2 = r + 8;
                    const float ang = (float)(r2 & (SS - 1)) * inv;
                    const float cs = cosf(ang), sn = sinf(ang);
                    const float a0 = acc[mt][nt][2], a1 = acc[mt][nt][3];
                    C[(size_t)r2 * N + c0]      = a0 * cs - a1 * sn;
                    C[(size_t)r2 * N + c0 + 64] = a1 * cs + a0 * sn;
                }
            }
        }
    } else if (do_half) {
#pragma unroll
        for (int mt = 0; mt < 4; mt++) {
#pragma unroll
            for (int nt = 0; nt < 4; nt++) {
                const int r = bm0 + wm + mt * 16 + gid;
                const int cc = bn0 + wn + nt * 8 + tig * 2;
                *(__half2*)&CH[(size_t)r * N + cc] =
                    __floats2half2_rn(acc[mt][nt][0], acc[mt][nt][1]);
                *(__half2*)&CH[(size_t)(r + 8) * N + cc] =
                    __floats2half2_rn(acc[mt][nt][2], acc[mt][nt][3]);
            }
        }
    } else {
#pragma unroll
        for (int mt = 0; mt < 4; mt++) {
#pragma unroll
            for (int nt = 0; nt < 4; nt++) {
                const int r = bm0 + wm + mt * 16 + gid;
                const int cc = bn0 + wn + nt * 8 + tig * 2;
                *(float2*)&C[(size_t)r * N + cc] =
                    make_float2(acc[mt][nt][0], acc[mt][nt][1]);
                *(float2*)&C[(size_t)(r + 8) * N + cc] =
                    make_float2(acc[mt][nt][2], acc[mt][nt][3]);
            }
        }
    }
}

// ---------------- flash attention v4: fp16 V stage + parity reduction --------
#define ATT_STGB 24576   // 16KB K(fp32) + 8KB V(fp16) per stage
#define ATT_SMEM (3 * ATT_STGB)  // 73728 B

__global__ __launch_bounds__(256, 2) void attn_kernel(
        const float* __restrict__ q,
        const float* __restrict__ k,
        const __half* __restrict__ vh,
        const float* __restrict__ ksuf,
        const float* __restrict__ vsuf,
        const int* __restrict__ validp,
        __half* __restrict__ outh) {
    extern __shared__ char smA[];
    const uint32_t smb = (uint32_t)__cvta_generic_to_shared(smA);

    const int valid = *validp;
    const int h  = blockIdx.y;
    const int b  = blockIdx.z;
    const int kvh = h >> 2;
    const int tid = threadIdx.x;
    const int q0base = blockIdx.x * 64;

    // fully-invalid CTA: write zeros, skip all work
    if (q0base >= valid) {
        const __half2 z2 = __floats2half2_rn(0.f, 0.f);
        const int row = tid >> 6;
        const int col = (tid & 63) * 2;
#pragma unroll
        for (int r = 0; r < 64; r += 4) {
            *(__half2*)(outh + (size_t)(b * SS + q0base + r + row) * QDIM + h * HD + col) = z2;
        }
        return;
    }

    const int wid = tid >> 5;
    const int lane = tid & 31;
    const int sub = lane & 7;
    const int qg  = lane >> 3;
    const int par = sub & 1;                 // this lane finalizes query q0+par
    const int q0 = q0base + wid * 8 + qg * 2;

    const float scale = 0.08838834764831845f;
    const unsigned long long scale2 = pack2(scale);

    unsigned long long q2[2][8];
#pragma unroll
    for (int j = 0; j < 2; j++) {
        const float* qp = q + (size_t)(b * SS + q0 + j) * QDIM + h * HD;
#pragma unroll
        for (int t = 0; t < 4; t++) {
            ulonglong2 u = *(const ulonglong2*)(qp + t * 32 + sub * 4);
            q2[j][2 * t]     = mul2(scale2, u.x);
            q2[j][2 * t + 1] = mul2(scale2, u.y);
        }
    }

    unsigned long long o2[2][8];
#pragma unroll
    for (int j = 0; j < 2; j++)
#pragma unroll
        for (int c = 0; c < 8; c++) o2[j][c] = 0ull;
    float m_my = -1e30f, l_my = 0.f;

    const float*  kb_base = k  + (size_t)(b * SS) * KVDIM + kvh * HD;
    const __half* vb_base = vh + (size_t)(b * SS) * KVDIM + kvh * HD;

    const int Tcap = (valid + 31) >> 5;
    const int T = min(2 * blockIdx.x + 2, Tcap);

    auto issue = [&](int t) {
        const uint32_t sb = smb + (uint32_t)((t % 3) * ATT_STGB);
        const int k0 = t * 32;
        // K fp32: 32 keys * 512B = 1024 chunks
#pragma unroll
        for (int i = 0; i < 4; i++) {
            const int c = tid + i * 256;
            const int kk = c >> 5;
            const int d4 = (c & 31) * 4;
            cp16(sb + (uint32_t)((kk * 128 + d4) * 4),
                 kb_base + (size_t)(k0 + kk) * KVDIM + d4);
        }
        // V fp16: 32 keys * 256B = 512 chunks
#pragma unroll
        for (int i = 0; i < 2; i++) {
            const int c = tid + i * 256;
            const int kk = c >> 4;
            const int h8 = (c & 15) * 8;     // halves
            cp16(sb + (uint32_t)(16384 + (kk * 128 + h8) * 2),
                 vb_base + (size_t)(k0 + kk) * KVDIM + h8);
        }
        asm volatile("cp.async.commit_group;");
    };

    issue(0);
    if (T > 1) issue(1);

    for (int t = 0; t < T; t++) {
        if (t + 1 < T) { asm volatile("cp.async.wait_group 1;"); }
        else           { asm volatile("cp.async.wait_group 0;"); }
        __syncthreads();
        if (t + 2 < T) issue(t + 2);

        const float*  Ks = (const float*)(smA + (t % 3) * ATT_STGB);
        const __half* Vs = (const __half*)(smA + (t % 3) * ATT_STGB + 16384);
        const int k0 = t * 32;

#pragma unroll
        for (int st = 0; st < 4; st++) {
            float sc[8];                     // this lane's query (q0+par) scores
#pragma unroll
            for (int kk8 = 0; kk8 < 8; kk8++) {
                const int kk = st * 8 + kk8;
                unsigned long long kc[8];
#pragma unroll
                for (int tt = 0; tt < 4; tt++) {
                    ulonglong2 u = *(const ulonglong2*)&Ks[kk * 128 + tt * 32 + sub * 4];
                    kc[2 * tt]     = u.x;
                    kc[2 * tt + 1] = u.y;
                }
                unsigned long long pa = 0ull, pb = 0ull;
#pragma unroll
                for (int c = 0; c < 8; c++) {
                    pa = fma2(q2[0][c], kc[c], pa);
                    pb = fma2(q2[1][c], kc[c], pb);
                }
                float a0, a1, b0, b1;
                unpack2(pa, a0, a1);
                unpack2(pb, b0, b1);
                const float s0 = a0 + a1, s1 = b0 + b1;
                // parity-packed reduction: identical tree to per-query reduce
                const float send = par ? s0 : s1;
                const float recv = __shfl_xor_sync(0xffffffffu, send, 1);
                float s = (par ? s1 : s0) + recv;
                s += __shfl_xor_sync(0xffffffffu, s, 2);
                s += __shfl_xor_sync(0xffffffffu, s, 4);
                sc[kk8] = (k0 + kk <= q0 + par) ? s : -1e30f;
            }
            // softmax update (state for query q0+par)
            float tmax = sc[0];
#pragma unroll
            for (int kk8 = 1; kk8 < 8; kk8++) tmax = fmaxf(tmax, sc[kk8]);
            const float mnew = fmaxf(m_my, tmax);
            const float corr = __expf(m_my - mnew);
            l_my *= corr;
            const float corr_ot = __shfl_xor_sync(0xffffffffu, corr, 1);
            const unsigned long long c0 = pack2(par ? corr_ot : corr);
            const unsigned long long c1 = pack2(par ? corr : corr_ot);
#pragma unroll
            for (int c = 0; c < 8; c++) {
                o2[0][c] = mul2(c0, o2[0][c]);
                o2[1][c] = mul2(c1, o2[1][c]);
            }
            m_my = mnew;
#pragma unroll
            for (int kk8 = 0; kk8 < 8; kk8++) {
                const float e = __expf(sc[kk8] - mnew);
                l_my += e;
                sc[kk8] = e;
            }
            // PV (V fp16 -> f32x2)
#pragma unroll
            for (int kk8 = 0; kk8 < 8; kk8++) {
                const int kk = st * 8 + kk8;
                unsigned long long vc[8];
#pragma unroll
                for (int tt = 0; tt < 4; tt++) {
                    uint2 u = *(const uint2*)&Vs[kk * 128 + tt * 32 + sub * 4];
                    float2 fa = __half22float2(*(__half2*)&u.x);
                    float2 fb = __half22float2(*(__half2*)&u.y);
                    vc[2 * tt]     = packf2(fa.x, fa.y);
                    vc[2 * tt + 1] = packf2(fb.x, fb.y);
                }
                const float e_ot = __shfl_xor_sync(0xffffffffu, sc[kk8], 1);
                const unsigned long long e0 = pack2(par ? e_ot : sc[kk8]);
                const unsigned long long e1 = pack2(par ? sc[kk8] : e_ot);
#pragma unroll
                for (int c = 0; c < 8; c++) {
                    o2[0][c] = fma2(e0, vc[c], o2[0][c]);
                    o2[1][c] = fma2(e1, vc[c], o2[1][c]);
                }
            }
        }
        __syncthreads();
    }

    // ---- 3 suffix keys on the diagonal (parity-packed) ----
#pragma unroll
    for (int sj = 0; sj < LCK; sj++) {
        const size_t off0 =
            (((size_t)(b * NKV + kvh) * LCK + sj) * SS + q0) * HD;
        unsigned long long pa = 0ull, pb = 0ull;
        const float* kp0 = ksuf + off0;
        const float* kp1 = kp0 + HD;
#pragma unroll
        for (int tt = 0; tt < 4; tt++) {
            ulonglong2 u0 = *(const ulonglong2*)(kp0 + tt * 32 + sub * 4);
            ulonglong2 u1 = *(const ulonglong2*)(kp1 + tt * 32 + sub * 4);
            pa = fma2(q2[0][2 * tt], u0.x, pa);
            pa = fma2(q2[0][2 * tt + 1], u0.y, pa);
            pb = fma2(q2[1][2 * tt], u1.x, pb);
            pb = fma2(q2[1][2 * tt + 1], u1.y, pb);
        }
        float a0, a1, b0, b1;
        unpack2(pa, a0, a1);
        unpack2(pb, b0, b1);
        const float s0 = a0 + a1, s1 = b0 + b1;
        const float send = par ? s0 : s1;
        const float recv = __shfl_xor_sync(0xffffffffu, send, 1);
        float s = (par ? s1 : s0) + recv;
        s += __shfl_xor_sync(0xffffffffu, s, 2);
        s += __shfl_xor_sync(0xffffffffu, s, 4);

        const float mnew = fmaxf(m_my, s);
        const float corr = __expf(m_my - mnew);
        const float e = __expf(s - mnew);
        l_my = l_my * corr + e;
        const float corr_ot = __shfl_xor_sync(0xffffffffu, corr, 1);
        const float e_ot    = __shfl_xor_sync(0xffffffffu, e, 1);
        const unsigned long long c0 = pack2(par ? corr_ot : corr);
        const unsigned long long c1 = pack2(par ? corr : corr_ot);
        const unsigned long long e0 = pack2(par ? e_ot : e);
        const unsigned long long e1 = pack2(par ? e : e_ot);
        const float* vp0 = vsuf + off0;
        const float* vp1 = vp0 + HD;
#pragma unroll
        for (int tt = 0; tt < 4; tt++) {
            ulonglong2 v0 = *(const ulonglong2*)(vp0 + tt * 32 + sub * 4);
            ulonglong2 v1 = *(const ulonglong2*)(vp1 + tt * 32 + sub * 4);
            o2[0][2 * tt]     = fma2(e0, v0.x, mul2(c0, o2[0][2 * tt]));
            o2[0][2 * tt + 1] = fma2(e0, v0.y, mul2(c0, o2[0][2 * tt + 1]));
            o2[1][2 * tt]     = fma2(e1, v1.x, mul2(c1, o2[1][2 * tt]));
            o2[1][2 * tt + 1] = fma2(e1, v1.y, mul2(c1, o2[1][2 * tt + 1]));
        }
        m_my = mnew;
    }

    // epilogue: gather l per query, normalize, fp16, masked rows = 0
    const float l_ot = __shfl_xor_sync(0xffffffffu, l_my, 1);
    const float l0 = par ? l_ot : l_my;
    const float l1 = par ? l_my : l_ot;
    const float invl[2] = { (q0 < valid) ? (1.0f / l0) : 0.0f,
                            (q0 + 1 < valid) ? (1.0f / l1) : 0.0f };
#pragma unroll
    for (int j = 0; j < 2; j++) {
        __half* op = outh + (size_t)(b * SS + q0 + j) * QDIM + h * HD;
#pragma unroll
        for (int tt = 0; tt < 4; tt++) {
            float a0, a1, a2, a3;
            unpack2(o2[j][2 * tt], a0, a1);
            unpack2(o2[j][2 * tt + 1], a2, a3);
            *(__half2*)(op + tt * 32 + sub * 4)     = __floats2half2_rn(a0 * invl[j], a1 * invl[j]);
            *(__half2*)(op + tt * 32 + sub * 4 + 2) = __floats2half2_rn(a2 * invl[j], a3 * invl[j]);
        }
    }
}

// ---------------- launch ----------------------------------------------------
extern "C" void kernel_launch(void* const* d_in, const int* in_sizes, int n_in,
                              void* d_out, int out_size) {
    const float* x    = (const float*)d_in[0];
    const float* ksuf = (const float*)d_in[1];
    const float* vsuf = (const float*)d_in[2];
    const float* Wq   = (const float*)d_in[3];
    const float* Wk   = (const float*)d_in[4];
    const float* Wv   = (const float*)d_in[5];
    const float* Wo   = (const float*)d_in[6];
    const int* valid  = (const int*)d_in[7];
    float* out = (float*)d_out;

    float *gq, *gk;
    __half *gvh, *xh, *ah;
    uint32_t *wqp, *wkp, *wvp, *wop;
    cudaGetSymbolAddress((void**)&gq, g_q);
    cudaGetSymbolAddress((void**)&gk, g_k);
    cudaGetSymbolAddress((void**)&gvh, g_vh);
    cudaGetSymbolAddress((void**)&xh, g_xh);
    cudaGetSymbolAddress((void**)&ah, g_ah);
    cudaGetSymbolAddress((void**)&wqp, g_wqp);
    cudaGetSymbolAddress((void**)&wkp, g_wkp);
    cudaGetSymbolAddress((void**)&wvp, g_wvp);
    cudaGetSymbolAddress((void**)&wop, g_wop);

    cudaFuncSetAttribute(gemm_h, cudaFuncAttributeMaxDynamicSharedMemorySize, GEMM_SMEM);
    cudaFuncSetAttribute(attn_kernel, cudaFuncAttributeMaxDynamicSharedMemorySize, ATT_SMEM);

    // 0: fused prep
    prep_kernel<<<(unsigned)(P_TOTAL / 256), 256>>>(
        (const float4*)x, xh, Wq, wqp, Wk, wkp, Wv, wvp, Wo, wop);

    // 1: K (rope, fp32) and V (fp16) projections in one launch
    gemm_h<<<dim3(KVDIM / 128, MROWS / 128, 2), 256, GEMM_SMEM>>>(
        xh, wkp, wvp, gk, gk, gvh, MROWS, KVDIM, HID, 0b01, 0b10);

    // 2: Q projection (rope)
    gemm_h<<<dim3(QDIM / 128, MROWS / 128, 1), 256, GEMM_SMEM>>>(
        xh, wqp, wqp, gq, gq, gvh, MROWS, QDIM, HID, 0b01, 0);

    // 3: attention (captured by ncu)
    attn_kernel<<<dim3(SS / 64, NH, BB), 256, ATT_SMEM>>>(
        gq, gk, gvh, ksuf, vsuf, valid, ah);

    // 4: output projection
    gemm_h<<<dim3(QDIM / 128, MROWS / 128, 1), 256, GEMM_SMEM>>>(
        ah, wop, wop, out, out, gvh, MROWS, QDIM, QDIM, 0, 0);
}

// round 13
// speedup vs baseline: 2.1608x; 1.1054x over previous
#include <cuda_runtime.h>
#include <cuda_fp16.h>
#include <math.h>
#include <stdint.h>

#define BB 2
#define SS 1024
#define HID 4096
#define NH 32
#define NKV 8
#define HD 128
#define LCK 3
#define MROWS (BB*SS)   // 2048
#define QDIM (NH*HD)    // 4096
#define KVDIM (NKV*HD)  // 1024
#define LOG2T 13.287712379549449f

// ---------------- scratch (static device globals; no allocations) ----------
__device__ float  g_q[(size_t)MROWS * QDIM];
__device__ float  g_k[(size_t)MROWS * KVDIM];
__device__ float  g_v[(size_t)MROWS * KVDIM];
__device__ __half g_xh[(size_t)MROWS * HID];
__device__ __half g_ah[(size_t)MROWS * QDIM];
__device__ uint32_t g_wqp[(size_t)(HID/2) * QDIM];
__device__ uint32_t g_wkp[(size_t)(HID/2) * KVDIM];
__device__ uint32_t g_wvp[(size_t)(HID/2) * KVDIM];
__device__ uint32_t g_wop[(size_t)(QDIM/2) * HID];

// ---------------- PTX helpers -----------------------------------------------
__device__ __forceinline__ void cp16(uint32_t dst, const void* src) {
    asm volatile("cp.async.cg.shared.global [%0], [%1], 16;" :: "r"(dst), "l"(src));
}
__device__ __forceinline__ uint32_t h2u(__half2 h) {
    union { __half2 h; uint32_t u; } cv;
    cv.h = h;
    return cv.u;
}
__device__ __forceinline__ void mma16(float* c, const uint32_t* a, const uint32_t* b) {
    asm volatile(
        "mma.sync.aligned.m16n8k16.row.col.f32.f16.f16.f32 "
        "{%0,%1,%2,%3},{%4,%5,%6,%7},{%8,%9},{%0,%1,%2,%3};"
        : "+f"(c[0]), "+f"(c[1]), "+f"(c[2]), "+f"(c[3])
        : "r"(a[0]), "r"(a[1]), "r"(a[2]), "r"(a[3]), "r"(b[0]), "r"(b[1]));
}
__device__ __forceinline__ void ldsm4(uint32_t* r, uint32_t addr) {
    asm volatile(
        "ldmatrix.sync.aligned.m8n8.x4.shared.b16 {%0,%1,%2,%3}, [%4];"
        : "=r"(r[0]), "=r"(r[1]), "=r"(r[2]), "=r"(r[3]) : "r"(addr));
}
// packed f32x2
__device__ __forceinline__ unsigned long long fma2(unsigned long long a,
                                                   unsigned long long b,
                                                   unsigned long long c) {
    unsigned long long d;
    asm("fma.rn.f32x2 %0, %1, %2, %3;" : "=l"(d) : "l"(a), "l"(b), "l"(c));
    return d;
}
__device__ __forceinline__ unsigned long long add2(unsigned long long a,
                                                   unsigned long long b) {
    unsigned long long d;
    asm("add.rn.f32x2 %0, %1, %2;" : "=l"(d) : "l"(a), "l"(b));
    return d;
}
__device__ __forceinline__ unsigned long long mul2(unsigned long long a,
                                                   unsigned long long b) {
    unsigned long long d;
    asm("mul.rn.f32x2 %0, %1, %2;" : "=l"(d) : "l"(a), "l"(b));
    return d;
}
__device__ __forceinline__ unsigned long long pack2(float x) {
    unsigned long long d;
    asm("mov.b64 %0, {%1, %2};" : "=l"(d) : "f"(x), "f"(x));
    return d;
}
__device__ __forceinline__ void unpack2(unsigned long long v, float& lo, float& hi) {
    asm("mov.b64 {%0, %1}, %2;" : "=f"(lo), "=f"(hi) : "l"(v));
}

// ---------------- fused prep: x->fp16 + pack all 4 weights -------------------
#define P_X  ((size_t)MROWS * HID / 4)
#define P_WQ ((size_t)(HID/2) * (QDIM/4))
#define P_WK ((size_t)(HID/2) * (KVDIM/4))
#define P_WV ((size_t)(HID/2) * (KVDIM/4))
#define P_WO ((size_t)(QDIM/2) * (HID/4))
#define P_TOTAL (P_X + P_WQ + P_WK + P_WV + P_WO)

__device__ __forceinline__ void pack_plain(const float* __restrict__ W,
                                           uint32_t* __restrict__ P, int N, size_t i) {
    const int npw = N >> 2;
    const int kp = (int)(i / npw);
    const int n4 = (int)(i - (size_t)kp * npw) * 4;
    float4 r0 = *(const float4*)(W + (size_t)(2 * kp) * N + n4);
    float4 r1 = *(const float4*)(W + (size_t)(2 * kp + 1) * N + n4);
    uint4 o;
    o.x = h2u(__floats2half2_rn(r0.x, r1.x));
    o.y = h2u(__floats2half2_rn(r0.y, r1.y));
    o.z = h2u(__floats2half2_rn(r0.z, r1.z));
    o.w = h2u(__floats2half2_rn(r0.w, r1.w));
    *(uint4*)(P + (size_t)kp * N + n4) = o;
}

__device__ __forceinline__ void pack_perm(const float* __restrict__ W,
                                          uint32_t* __restrict__ P, int N, size_t i) {
    const int npw = N >> 2;
    const int kp = (int)(i / npw);
    const int n4 = (int)(i - (size_t)kp * npw) * 4;
    const float* w0 = W + (size_t)(2 * kp) * N;
    const float* w1 = W + (size_t)(2 * kp + 1) * N;
    uint32_t r[4];
#pragma unroll
    for (int j = 0; j < 4; j++) {
        const int c = n4 + j;
        const int h = c >> 7;
        const int w = c & 127;
        const int oc = (h << 7) + (w >> 1) + ((w & 1) << 6);
        r[j] = h2u(__floats2half2_rn(w0[oc], w1[oc]));
    }
    *(uint4*)(P + (size_t)kp * N + n4) = make_uint4(r[0], r[1], r[2], r[3]);
}

__global__ void prep_kernel(const float4* __restrict__ x,  __half* __restrict__ xh,
                            const float* __restrict__ Wq, uint32_t* __restrict__ wqp,
                            const float* __restrict__ Wk, uint32_t* __restrict__ wkp,
                            const float* __restrict__ Wv, uint32_t* __restrict__ wvp,
                            const float* __restrict__ Wo, uint32_t* __restrict__ wop) {
    size_t i = (size_t)blockIdx.x * 256 + threadIdx.x;
    if (i < P_X) {
        float4 v = x[i];
        *(__half2*)(xh + i * 4)     = __floats2half2_rn(v.x, v.y);
        *(__half2*)(xh + i * 4 + 2) = __floats2half2_rn(v.z, v.w);
    } else if ((i -= P_X) < P_WQ) {
        pack_perm(Wq, wqp, QDIM, i);
    } else if ((i -= P_WQ) < P_WK) {
        pack_perm(Wk, wkp, KVDIM, i);
    } else if ((i -= P_WK) < P_WV) {
        pack_plain(Wv, wvp, KVDIM, i);
    } else {
        i -= P_WV;
        pack_plain(Wo, wop, HID, i);
    }
}

// ---------------- fp16 tensor-core GEMM (+optional RoPE epilogue) ------------
#define APITCHW 36
#define BPITCHW 136
#define ASZW (128 * APITCHW)
#define BSZW (16 * BPITCHW)
#define STGW (ASZW + BSZW)
#define GEMM_SMEM (3 * STGW * 4)  // 81408 B

__global__ __launch_bounds__(256, 2) void gemm_h(const __half* __restrict__ A,
                                                 const uint32_t* __restrict__ B0,
                                                 const uint32_t* __restrict__ B1,
                                                 float* __restrict__ C0,
                                                 float* __restrict__ C1,
                                                 int M, int N, int K, int rope_mask) {
    const uint32_t* B = blockIdx.z ? B1 : B0;
    float* C = blockIdx.z ? C1 : C0;
    const bool do_rope = (rope_mask >> blockIdx.z) & 1;

    extern __shared__ float sm[];
    const uint32_t smb = (uint32_t)__cvta_generic_to_shared(sm);
    const uint32_t* s32 = (const uint32_t*)sm;

    const int tid  = threadIdx.x;
    const int lane = tid & 31;
    const int wid  = tid >> 5;
    const int gid  = lane >> 2;
    const int tig  = lane & 3;
    const int wm   = (wid & 1) * 64;
    const int wn   = (wid >> 1) * 32;

    const int lrow   = lane & 7;
    const int lid4   = lane >> 3;
    const int a_moff = (lid4 & 1) * 8;
    const int a_woff = (lid4 >> 1) * 4;

    const int bm0 = blockIdx.y * 128;
    const int bn0 = blockIdx.x * 128;

    float acc[4][4][4];
#pragma unroll
    for (int mt = 0; mt < 4; mt++)
#pragma unroll
        for (int nt = 0; nt < 4; nt++)
#pragma unroll
            for (int i = 0; i < 4; i++) acc[mt][nt][i] = 0.f;

    const int T = K / 32;

    auto issue = [&](int t) {
        const uint32_t sb = smb + (uint32_t)((t % 3) * STGW * 4);
#pragma unroll
        for (int i = 0; i < 2; i++) {
            const int c = tid + i * 256;
            const int row = c >> 2;
            const int q = c & 3;
            cp16(sb + (uint32_t)(row * APITCHW * 4 + q * 16),
                 A + (size_t)(bm0 + row) * K + t * 32 + q * 8);
        }
#pragma unroll
        for (int i = 0; i < 2; i++) {
            const int c = tid + i * 256;
            const int kk = c >> 5;
            const int n4 = (c & 31) * 4;
            cp16(sb + (uint32_t)((ASZW + kk * BPITCHW + n4) * 4),
                 B + (size_t)(t * 16 + kk) * N + bn0 + n4);
        }
        asm volatile("cp.async.commit_group;");
    };

    issue(0);
    issue(1);

    for (int t = 0; t < T; t++) {
        if (t < T - 1) { asm volatile("cp.async.wait_group 1;"); }
        else           { asm volatile("cp.async.wait_group 0;"); }
        __syncthreads();
        if (t + 2 < T) issue(t + 2);

        const int so = (t % 3) * STGW;
        const uint32_t* sb = s32 + so + ASZW;
#pragma unroll
        for (int ks = 0; ks < 2; ks++) {
            const int w0 = ks * 8;
            uint32_t af[4][4];
#pragma unroll
            for (int mt = 0; mt < 4; mt++) {
                const uint32_t addr = smb + (uint32_t)(
                    (so + (wm + mt * 16 + a_moff + lrow) * APITCHW + w0 + a_woff) * 4);
                ldsm4(af[mt], addr);
            }
            uint32_t bf[4][2];
#pragma unroll
            for (int nt = 0; nt < 4; nt++) {
                const int col = wn + nt * 8 + gid;
                bf[nt][0] = sb[(w0 + tig) * BPITCHW + col];
                bf[nt][1] = sb[(w0 + tig + 4) * BPITCHW + col];
            }
#pragma unroll
            for (int mt = 0; mt < 4; mt++)
#pragma unroll
                for (int nt = 0; nt < 4; nt++)
                    mma16(acc[mt][nt], af[mt], bf[nt]);
        }
        __syncthreads();
    }

    if (!do_rope) {
#pragma unroll
        for (int mt = 0; mt < 4; mt++) {
#pragma unroll
            for (int nt = 0; nt < 4; nt++) {
                const int r = bm0 + wm + mt * 16 + gid;
                const int cc = bn0 + wn + nt * 8 + tig * 2;
                *(float2*)&C[(size_t)r * N + cc] =
                    make_float2(acc[mt][nt][0], acc[mt][nt][1]);
                *(float2*)&C[(size_t)(r + 8) * N + cc] =
                    make_float2(acc[mt][nt][2], acc[mt][nt][3]);
            }
        }
    } else {
#pragma unroll
        for (int nt = 0; nt < 4; nt++) {
            const int cc = bn0 + wn + nt * 8 + tig * 2;
            const int h = cc >> 7;
            const int u = (cc & 127) >> 1;
            const float inv = exp2f(-(float)(2 * u) * (1.0f / 128.0f) * LOG2T);
            const int c0 = h * 128 + u;
#pragma unroll
            for (int mt = 0; mt < 4; mt++) {
                const int r = bm0 + wm + mt * 16 + gid;
                {
                    const float ang = (float)(r & (SS - 1)) * inv;
                    const float cs = cosf(ang), sn = sinf(ang);
                    const float a0 = acc[mt][nt][0], a1 = acc[mt][nt][1];
                    C[(size_t)r * N + c0]      = a0 * cs - a1 * sn;
                    C[(size_t)r * N + c0 + 64] = a1 * cs + a0 * sn;
                }
                {
                    const int r2 = r + 8;
                    const float ang = (float)(r2 & (SS - 1)) * inv;
                    const float cs = cosf(ang), sn = sinf(ang);
                    const float a0 = acc[mt][nt][2], a1 = acc[mt][nt][3];
                    C[(size_t)r2 * N + c0]      = a0 * cs - a1 * sn;
                    C[(size_t)r2 * N + c0 + 64] = a1 * cs + a0 * sn;
                }
            }
        }
    }
}

// ---------------- flash attention v5: fp32 V + parity + split chains ---------
// grid (64, 16): x = h*2+b, y -> bx = 15-y (heavy CTAs scheduled first)
#define ATT_STGF (2 * 32 * 128)
#define ATT_SMEM (3 * ATT_STGF * 4)  // 98304 B

__global__ __launch_bounds__(256, 2) void attn_kernel(
        const float* __restrict__ q,
        const float* __restrict__ k,
        const float* __restrict__ v,
        const float* __restrict__ ksuf,
        const float* __restrict__ vsuf,
        const int* __restrict__ validp,
        __half* __restrict__ outh) {
    extern __shared__ float smA[];
    const uint32_t smb = (uint32_t)__cvta_generic_to_shared(smA);

    const int valid = *validp;
    const int hb = blockIdx.x;
    const int h  = hb >> 1;
    const int b  = hb & 1;
    const int bx = 15 - blockIdx.y;          // heavy-first scheduling
    const int kvh = h >> 2;
    const int tid = threadIdx.x;
    const int q0base = bx * 64;

    if (q0base >= valid) {
        const __half2 z2 = __floats2half2_rn(0.f, 0.f);
        const int row = tid >> 6;
        const int col = (tid & 63) * 2;
#pragma unroll
        for (int r = 0; r < 64; r += 4) {
            *(__half2*)(outh + (size_t)(b * SS + q0base + r + row) * QDIM + h * HD + col) = z2;
        }
        return;
    }

    const int wid = tid >> 5;
    const int lane = tid & 31;
    const int sub = lane & 7;
    const int qg  = lane >> 3;
    const int par = sub & 1;
    const int q0 = q0base + wid * 8 + qg * 2;

    const float scale = 0.08838834764831845f;
    const unsigned long long scale2 = pack2(scale);

    unsigned long long q2[2][8];
#pragma unroll
    for (int j = 0; j < 2; j++) {
        const float* qp = q + (size_t)(b * SS + q0 + j) * QDIM + h * HD;
#pragma unroll
        for (int t = 0; t < 4; t++) {
            ulonglong2 u = *(const ulonglong2*)(qp + t * 32 + sub * 4);
            q2[j][2 * t]     = mul2(scale2, u.x);
            q2[j][2 * t + 1] = mul2(scale2, u.y);
        }
    }

    unsigned long long o2[2][8];
#pragma unroll
    for (int j = 0; j < 2; j++)
#pragma unroll
        for (int c = 0; c < 8; c++) o2[j][c] = 0ull;
    float m_my = -1e30f, l_my = 0.f;

    const float* kb_base = k + (size_t)(b * SS) * KVDIM + kvh * HD;
    const float* vb_base = v + (size_t)(b * SS) * KVDIM + kvh * HD;

    const int Tcap = (valid + 31) >> 5;
    const int T = min(2 * bx + 2, Tcap);

    auto issue = [&](int t) {
        const uint32_t sb = smb + (uint32_t)((t % 3) * ATT_STGF * 4);
        const int k0 = t * 32;
#pragma unroll
        for (int i = 0; i < 4; i++) {
            const int c = tid + i * 256;
            const int kk = c >> 5;
            const int d4 = (c & 31) * 4;
            cp16(sb + (uint32_t)((kk * 128 + d4) * 4),
                 kb_base + (size_t)(k0 + kk) * KVDIM + d4);
            cp16(sb + (uint32_t)((4096 + kk * 128 + d4) * 4),
                 vb_base + (size_t)(k0 + kk) * KVDIM + d4);
        }
        asm volatile("cp.async.commit_group;");
    };

    issue(0);
    if (T > 1) issue(1);

    for (int t = 0; t < T; t++) {
        if (t + 1 < T) { asm volatile("cp.async.wait_group 1;"); }
        else           { asm volatile("cp.async.wait_group 0;"); }
        __syncthreads();
        if (t + 2 < T) issue(t + 2);

        const float* Ks = smA + (t % 3) * ATT_STGF;
        const float* Vs = Ks + 4096;
        const int k0 = t * 32;

#pragma unroll
        for (int st = 0; st < 4; st++) {
            float sc[8];
#pragma unroll
            for (int kk8 = 0; kk8 < 8; kk8++) {
                const int kk = st * 8 + kk8;
                unsigned long long kc[8];
#pragma unroll
                for (int tt = 0; tt < 4; tt++) {
                    ulonglong2 u = *(const ulonglong2*)&Ks[kk * 128 + tt * 32 + sub * 4];
                    kc[2 * tt]     = u.x;
                    kc[2 * tt + 1] = u.y;
                }
                // split chains: depth 4 instead of 8 (reassociation only)
                unsigned long long pa0 = 0ull, pa1 = 0ull, pb0 = 0ull, pb1 = 0ull;
#pragma unroll
                for (int c = 0; c < 4; c++) {
                    pa0 = fma2(q2[0][2 * c],     kc[2 * c],     pa0);
                    pa1 = fma2(q2[0][2 * c + 1], kc[2 * c + 1], pa1);
                    pb0 = fma2(q2[1][2 * c],     kc[2 * c],     pb0);
                    pb1 = fma2(q2[1][2 * c + 1], kc[2 * c + 1], pb1);
                }
                const unsigned long long pa = add2(pa0, pa1);
                const unsigned long long pb = add2(pb0, pb1);
                float a0, a1, b0, b1;
                unpack2(pa, a0, a1);
                unpack2(pb, b0, b1);
                const float s0 = a0 + a1, s1 = b0 + b1;
                const float send = par ? s0 : s1;
                const float recv = __shfl_xor_sync(0xffffffffu, send, 1);
                float s = (par ? s1 : s0) + recv;
                s += __shfl_xor_sync(0xffffffffu, s, 2);
                s += __shfl_xor_sync(0xffffffffu, s, 4);
                sc[kk8] = (k0 + kk <= q0 + par) ? s : -1e30f;
            }
            float tmax = sc[0];
#pragma unroll
            for (int kk8 = 1; kk8 < 8; kk8++) tmax = fmaxf(tmax, sc[kk8]);
            const float mnew = fmaxf(m_my, tmax);
            const float corr = __expf(m_my - mnew);
            l_my *= corr;
            const float corr_ot = __shfl_xor_sync(0xffffffffu, corr, 1);
            const unsigned long long c0 = pack2(par ? corr_ot : corr);
            const unsigned long long c1 = pack2(par ? corr : corr_ot);
#pragma unroll
            for (int c = 0; c < 8; c++) {
                o2[0][c] = mul2(c0, o2[0][c]);
                o2[1][c] = mul2(c1, o2[1][c]);
            }
            m_my = mnew;
#pragma unroll
            for (int kk8 = 0; kk8 < 8; kk8++) {
                const float e = __expf(sc[kk8] - mnew);
                l_my += e;
                sc[kk8] = e;
            }
#pragma unroll
            for (int kk8 = 0; kk8 < 8; kk8++) {
                const int kk = st * 8 + kk8;
                unsigned long long vc[8];
#pragma unroll
                for (int tt = 0; tt < 4; tt++) {
                    ulonglong2 u = *(const ulonglong2*)&Vs[kk * 128 + tt * 32 + sub * 4];
                    vc[2 * tt]     = u.x;
                    vc[2 * tt + 1] = u.y;
                }
                const float e_ot = __shfl_xor_sync(0xffffffffu, sc[kk8], 1);
                const unsigned long long e0 = pack2(par ? e_ot : sc[kk8]);
                const unsigned long long e1 = pack2(par ? sc[kk8] : e_ot);
#pragma unroll
                for (int c = 0; c < 8; c++) {
                    o2[0][c] = fma2(e0, vc[c], o2[0][c]);
                    o2[1][c] = fma2(e1, vc[c], o2[1][c]);
                }
            }
        }
        __syncthreads();
    }

    // ---- 3 suffix keys on the diagonal (parity-packed) ----
#pragma unroll
    for (int sj = 0; sj < LCK; sj++) {
        const size_t off0 =
            (((size_t)(b * NKV + kvh) * LCK + sj) * SS + q0) * HD;
        unsigned long long pa = 0ull, pb = 0ull;
        const float* kp0 = ksuf + off0;
        const float* kp1 = kp0 + HD;
#pragma unroll
        for (int tt = 0; tt < 4; tt++) {
            ulonglong2 u0 = *(const ulonglong2*)(kp0 + tt * 32 + sub * 4);
            ulonglong2 u1 = *(const ulonglong2*)(kp1 + tt * 32 + sub * 4);
            pa = fma2(q2[0][2 * tt], u0.x, pa);
            pa = fma2(q2[0][2 * tt + 1], u0.y, pa);
            pb = fma2(q2[1][2 * tt], u1.x, pb);
            pb = fma2(q2[1][2 * tt + 1], u1.y, pb);
        }
        float a0, a1, b0, b1;
        unpack2(pa, a0, a1);
        unpack2(pb, b0, b1);
        const float s0 = a0 + a1, s1 = b0 + b1;
        const float send = par ? s0 : s1;
        const float recv = __shfl_xor_sync(0xffffffffu, send, 1);
        float s = (par ? s1 : s0) + recv;
        s += __shfl_xor_sync(0xffffffffu, s, 2);
        s += __shfl_xor_sync(0xffffffffu, s, 4);

        const float mnew = fmaxf(m_my, s);
        const float corr = __expf(m_my - mnew);
        const float e = __expf(s - mnew);
        l_my = l_my * corr + e;
        const float corr_ot = __shfl_xor_sync(0xffffffffu, corr, 1);
        const float e_ot    = __shfl_xor_sync(0xffffffffu, e, 1);
        const unsigned long long c0 = pack2(par ? corr_ot : corr);
        const unsigned long long c1 = pack2(par ? corr : corr_ot);
        const unsigned long long e0 = pack2(par ? e_ot : e);
        const unsigned long long e1 = pack2(par ? e : e_ot);
        const float* vp0 = vsuf + off0;
        const float* vp1 = vp0 + HD;
#pragma unroll
        for (int tt = 0; tt < 4; tt++) {
            ulonglong2 v0 = *(const ulonglong2*)(vp0 + tt * 32 + sub * 4);
            ulonglong2 v1 = *(const ulonglong2*)(vp1 + tt * 32 + sub * 4);
            o2[0][2 * tt]     = fma2(e0, v0.x, mul2(c0, o2[0][2 * tt]));
            o2[0][2 * tt + 1] = fma2(e0, v0.y, mul2(c0, o2[0][2 * tt + 1]));
            o2[1][2 * tt]     = fma2(e1, v1.x, mul2(c1, o2[1][2 * tt]));
            o2[1][2 * tt + 1] = fma2(e1, v1.y, mul2(c1, o2[1][2 * tt + 1]));
        }
        m_my = mnew;
    }

    // epilogue
    const float l_ot = __shfl_xor_sync(0xffffffffu, l_my, 1);
    const float l0 = par ? l_ot : l_my;
    const float l1 = par ? l_my : l_ot;
    const float invl[2] = { (q0 < valid) ? (1.0f / l0) : 0.0f,
                            (q0 + 1 < valid) ? (1.0f / l1) : 0.0f };
#pragma unroll
    for (int j = 0; j < 2; j++) {
        __half* op = outh + (size_t)(b * SS + q0 + j) * QDIM + h * HD;
#pragma unroll
        for (int tt = 0; tt < 4; tt++) {
            float a0, a1, a2, a3;
            unpack2(o2[j][2 * tt], a0, a1);
            unpack2(o2[j][2 * tt + 1], a2, a3);
            *(__half2*)(op + tt * 32 + sub * 4)     = __floats2half2_rn(a0 * invl[j], a1 * invl[j]);
            *(__half2*)(op + tt * 32 + sub * 4 + 2) = __floats2half2_rn(a2 * invl[j], a3 * invl[j]);
        }
    }
}

// ---------------- launch ----------------------------------------------------
extern "C" void kernel_launch(void* const* d_in, const int* in_sizes, int n_in,
                              void* d_out, int out_size) {
    const float* x    = (const float*)d_in[0];
    const float* ksuf = (const float*)d_in[1];
    const float* vsuf = (const float*)d_in[2];
    const float* Wq   = (const float*)d_in[3];
    const float* Wk   = (const float*)d_in[4];
    const float* Wv   = (const float*)d_in[5];
    const float* Wo   = (const float*)d_in[6];
    const int* valid  = (const int*)d_in[7];
    float* out = (float*)d_out;

    float *gq, *gk, *gv;
    __half *xh, *ah;
    uint32_t *wqp, *wkp, *wvp, *wop;
    cudaGetSymbolAddress((void**)&gq, g_q);
    cudaGetSymbolAddress((void**)&gk, g_k);
    cudaGetSymbolAddress((void**)&gv, g_v);
    cudaGetSymbolAddress((void**)&xh, g_xh);
    cudaGetSymbolAddress((void**)&ah, g_ah);
    cudaGetSymbolAddress((void**)&wqp, g_wqp);
    cudaGetSymbolAddress((void**)&wkp, g_wkp);
    cudaGetSymbolAddress((void**)&wvp, g_wvp);
    cudaGetSymbolAddress((void**)&wop, g_wop);

    cudaFuncSetAttribute(gemm_h, cudaFuncAttributeMaxDynamicSharedMemorySize, GEMM_SMEM);
    cudaFuncSetAttribute(attn_kernel, cudaFuncAttributeMaxDynamicSharedMemorySize, ATT_SMEM);

    // 0: fused prep
    prep_kernel<<<(unsigned)(P_TOTAL / 256), 256>>>(
        (const float4*)x, xh, Wq, wqp, Wk, wkp, Wv, wvp, Wo, wop);

    // 1: K (rope) and V projections in one launch
    gemm_h<<<dim3(KVDIM / 128, MROWS / 128, 2), 256, GEMM_SMEM>>>(
        xh, wkp, wvp, gk, gv, MROWS, KVDIM, HID, 0b01);

    // 2: Q projection (rope)
    gemm_h<<<dim3(QDIM / 128, MROWS / 128, 1), 256, GEMM_SMEM>>>(
        xh, wqp, wqp, gq, gq, MROWS, QDIM, HID, 0b01);

    // 3: attention (heavy CTAs first; captured by ncu)
    attn_kernel<<<dim3(NH * BB, SS / 64), 256, ATT_SMEM>>>(
        gq, gk, gv, ksuf, vsuf, valid, ah);

    // 4: output projection
    gemm_h<<<dim3(QDIM / 128, MROWS / 128, 1), 256, GEMM_SMEM>>>(
        ah, wop, wop, out, out, MROWS, QDIM, QDIM, 0);
}

// round 14
// speedup vs baseline: 2.3967x; 1.1092x over previous
#include <cuda_runtime.h>
#include <cuda_fp16.h>
#include <math.h>
#include <stdint.h>

#define BB 2
#define SS 1024
#define HID 4096
#define NH 32
#define NKV 8
#define HD 128
#define LCK 3
#define MROWS (BB*SS)   // 2048
#define QDIM (NH*HD)    // 4096
#define KVDIM (NKV*HD)  // 1024
#define LOG2T 13.287712379549449f

// ---------------- scratch (static device globals; no allocations) ----------
__device__ float  g_q[(size_t)MROWS * QDIM];
__device__ float  g_k[(size_t)MROWS * KVDIM];
__device__ float  g_v[(size_t)MROWS * KVDIM];
__device__ __half g_xh[(size_t)MROWS * HID];
__device__ __half g_ah[(size_t)MROWS * QDIM];
__device__ uint32_t g_wqp[(size_t)(HID/2) * QDIM];
__device__ uint32_t g_wkp[(size_t)(HID/2) * KVDIM];
__device__ uint32_t g_wvp[(size_t)(HID/2) * KVDIM];
__device__ uint32_t g_wop[(size_t)(QDIM/2) * HID];

// ---------------- PTX helpers -----------------------------------------------
__device__ __forceinline__ void cp16(uint32_t dst, const void* src) {
    asm volatile("cp.async.cg.shared.global [%0], [%1], 16;" :: "r"(dst), "l"(src));
}
__device__ __forceinline__ uint32_t h2u(__half2 h) {
    union { __half2 h; uint32_t u; } cv;
    cv.h = h;
    return cv.u;
}
__device__ __forceinline__ void mma16(float* c, const uint32_t* a, const uint32_t* b) {
    asm volatile(
        "mma.sync.aligned.m16n8k16.row.col.f32.f16.f16.f32 "
        "{%0,%1,%2,%3},{%4,%5,%6,%7},{%8,%9},{%0,%1,%2,%3};"
        : "+f"(c[0]), "+f"(c[1]), "+f"(c[2]), "+f"(c[3])
        : "r"(a[0]), "r"(a[1]), "r"(a[2]), "r"(a[3]), "r"(b[0]), "r"(b[1]));
}
__device__ __forceinline__ void ldsm4(uint32_t* r, uint32_t addr) {
    asm volatile(
        "ldmatrix.sync.aligned.m8n8.x4.shared.b16 {%0,%1,%2,%3}, [%4];"
        : "=r"(r[0]), "=r"(r[1]), "=r"(r[2]), "=r"(r[3]) : "r"(addr));
}
// packed f32x2
__device__ __forceinline__ unsigned long long fma2(unsigned long long a,
                                                   unsigned long long b,
                                                   unsigned long long c) {
    unsigned long long d;
    asm("fma.rn.f32x2 %0, %1, %2, %3;" : "=l"(d) : "l"(a), "l"(b), "l"(c));
    return d;
}
__device__ __forceinline__ unsigned long long mul2(unsigned long long a,
                                                   unsigned long long b) {
    unsigned long long d;
    asm("mul.rn.f32x2 %0, %1, %2;" : "=l"(d) : "l"(a), "l"(b));
    return d;
}
__device__ __forceinline__ unsigned long long pack2(float x) {
    unsigned long long d;
    asm("mov.b64 %0, {%1, %2};" : "=l"(d) : "f"(x), "f"(x));
    return d;
}
__device__ __forceinline__ void unpack2(unsigned long long v, float& lo, float& hi) {
    asm("mov.b64 {%0, %1}, %2;" : "=f"(lo), "=f"(hi) : "l"(v));
}

// ---------------- fused prep: x->fp16 + pack all 4 weights -------------------
#define P_X  ((size_t)MROWS * HID / 4)
#define P_WQ ((size_t)(HID/2) * (QDIM/4))
#define P_WK ((size_t)(HID/2) * (KVDIM/4))
#define P_WV ((size_t)(HID/2) * (KVDIM/4))
#define P_WO ((size_t)(QDIM/2) * (HID/4))
#define P_TOTAL (P_X + P_WQ + P_WK + P_WV + P_WO)

__device__ __forceinline__ void pack_plain(const float* __restrict__ W,
                                           uint32_t* __restrict__ P, int N, size_t i) {
    const int npw = N >> 2;
    const int kp = (int)(i / npw);
    const int n4 = (int)(i - (size_t)kp * npw) * 4;
    float4 r0 = *(const float4*)(W + (size_t)(2 * kp) * N + n4);
    float4 r1 = *(const float4*)(W + (size_t)(2 * kp + 1) * N + n4);
    uint4 o;
    o.x = h2u(__floats2half2_rn(r0.x, r1.x));
    o.y = h2u(__floats2half2_rn(r0.y, r1.y));
    o.z = h2u(__floats2half2_rn(r0.z, r1.z));
    o.w = h2u(__floats2half2_rn(r0.w, r1.w));
    *(uint4*)(P + (size_t)kp * N + n4) = o;
}

__device__ __forceinline__ void pack_perm(const float* __restrict__ W,
                                          uint32_t* __restrict__ P, int N, size_t i) {
    const int npw = N >> 2;
    const int kp = (int)(i / npw);
    const int n4 = (int)(i - (size_t)kp * npw) * 4;
    const float* w0 = W + (size_t)(2 * kp) * N;
    const float* w1 = W + (size_t)(2 * kp + 1) * N;
    uint32_t r[4];
#pragma unroll
    for (int j = 0; j < 4; j++) {
        const int c = n4 + j;
        const int h = c >> 7;
        const int w = c & 127;
        const int oc = (h << 7) + (w >> 1) + ((w & 1) << 6);
        r[j] = h2u(__floats2half2_rn(w0[oc], w1[oc]));
    }
    *(uint4*)(P + (size_t)kp * N + n4) = make_uint4(r[0], r[1], r[2], r[3]);
}

__global__ void prep_kernel(const float4* __restrict__ x,  __half* __restrict__ xh,
                            const float* __restrict__ Wq, uint32_t* __restrict__ wqp,
                            const float* __restrict__ Wk, uint32_t* __restrict__ wkp,
                            const float* __restrict__ Wv, uint32_t* __restrict__ wvp,
                            const float* __restrict__ Wo, uint32_t* __restrict__ wop) {
    size_t i = (size_t)blockIdx.x * 256 + threadIdx.x;
    if (i < P_X) {
        float4 v = x[i];
        *(__half2*)(xh + i * 4)     = __floats2half2_rn(v.x, v.y);
        *(__half2*)(xh + i * 4 + 2) = __floats2half2_rn(v.z, v.w);
    } else if ((i -= P_X) < P_WQ) {
        pack_perm(Wq, wqp, QDIM, i);
    } else if ((i -= P_WQ) < P_WK) {
        pack_perm(Wk, wkp, KVDIM, i);
    } else if ((i -= P_WK) < P_WV) {
        pack_plain(Wv, wvp, KVDIM, i);
    } else {
        i -= P_WV;
        pack_plain(Wo, wop, HID, i);
    }
}

// ---------------- fp16 tensor-core GEMM (+optional RoPE epilogue) ------------
#define APITCHW 36
#define BPITCHW 136
#define ASZW (128 * APITCHW)
#define BSZW (16 * BPITCHW)
#define STGW (ASZW + BSZW)
#define GEMM_SMEM (3 * STGW * 4)  // 81408 B

__global__ __launch_bounds__(256, 2) void gemm_h(const __half* __restrict__ A,
                                                 const uint32_t* __restrict__ B0,
                                                 const uint32_t* __restrict__ B1,
                                                 float* __restrict__ C0,
                                                 float* __restrict__ C1,
                                                 int M, int N, int K, int rope_mask) {
    const uint32_t* B = blockIdx.z ? B1 : B0;
    float* C = blockIdx.z ? C1 : C0;
    const bool do_rope = (rope_mask >> blockIdx.z) & 1;

    extern __shared__ float sm[];
    const uint32_t smb = (uint32_t)__cvta_generic_to_shared(sm);
    const uint32_t* s32 = (const uint32_t*)sm;

    const int tid  = threadIdx.x;
    const int lane = tid & 31;
    const int wid  = tid >> 5;
    const int gid  = lane >> 2;
    const int tig  = lane & 3;
    const int wm   = (wid & 1) * 64;
    const int wn   = (wid >> 1) * 32;

    const int lrow   = lane & 7;
    const int lid4   = lane >> 3;
    const int a_moff = (lid4 & 1) * 8;
    const int a_woff = (lid4 >> 1) * 4;

    const int bm0 = blockIdx.y * 128;
    const int bn0 = blockIdx.x * 128;

    float acc[4][4][4];
#pragma unroll
    for (int mt = 0; mt < 4; mt++)
#pragma unroll
        for (int nt = 0; nt < 4; nt++)
#pragma unroll
            for (int i = 0; i < 4; i++) acc[mt][nt][i] = 0.f;

    const int T = K / 32;

    auto issue = [&](int t) {
        const uint32_t sb = smb + (uint32_t)((t % 3) * STGW * 4);
#pragma unroll
        for (int i = 0; i < 2; i++) {
            const int c = tid + i * 256;
            const int row = c >> 2;
            const int q = c & 3;
            cp16(sb + (uint32_t)(row * APITCHW * 4 + q * 16),
                 A + (size_t)(bm0 + row) * K + t * 32 + q * 8);
        }
#pragma unroll
        for (int i = 0; i < 2; i++) {
            const int c = tid + i * 256;
            const int kk = c >> 5;
            const int n4 = (c & 31) * 4;
            cp16(sb + (uint32_t)((ASZW + kk * BPITCHW + n4) * 4),
                 B + (size_t)(t * 16 + kk) * N + bn0 + n4);
        }
        asm volatile("cp.async.commit_group;");
    };

    issue(0);
    issue(1);

    for (int t = 0; t < T; t++) {
        if (t < T - 1) { asm volatile("cp.async.wait_group 1;"); }
        else           { asm volatile("cp.async.wait_group 0;"); }
        __syncthreads();
        if (t + 2 < T) issue(t + 2);

        const int so = (t % 3) * STGW;
        const uint32_t* sb = s32 + so + ASZW;
#pragma unroll
        for (int ks = 0; ks < 2; ks++) {
            const int w0 = ks * 8;
            uint32_t af[4][4];
#pragma unroll
            for (int mt = 0; mt < 4; mt++) {
                const uint32_t addr = smb + (uint32_t)(
                    (so + (wm + mt * 16 + a_moff + lrow) * APITCHW + w0 + a_woff) * 4);
                ldsm4(af[mt], addr);
            }
            uint32_t bf[4][2];
#pragma unroll
            for (int nt = 0; nt < 4; nt++) {
                const int col = wn + nt * 8 + gid;
                bf[nt][0] = sb[(w0 + tig) * BPITCHW + col];
                bf[nt][1] = sb[(w0 + tig + 4) * BPITCHW + col];
            }
#pragma unroll
            for (int mt = 0; mt < 4; mt++)
#pragma unroll
                for (int nt = 0; nt < 4; nt++)
                    mma16(acc[mt][nt], af[mt], bf[nt]);
        }
        __syncthreads();
    }

    if (!do_rope) {
#pragma unroll
        for (int mt = 0; mt < 4; mt++) {
#pragma unroll
            for (int nt = 0; nt < 4; nt++) {
                const int r = bm0 + wm + mt * 16 + gid;
                const int cc = bn0 + wn + nt * 8 + tig * 2;
                *(float2*)&C[(size_t)r * N + cc] =
                    make_float2(acc[mt][nt][0], acc[mt][nt][1]);
                *(float2*)&C[(size_t)(r + 8) * N + cc] =
                    make_float2(acc[mt][nt][2], acc[mt][nt][3]);
            }
        }
    } else {
#pragma unroll
        for (int nt = 0; nt < 4; nt++) {
            const int cc = bn0 + wn + nt * 8 + tig * 2;
            const int h = cc >> 7;
            const int u = (cc & 127) >> 1;
            const float inv = exp2f(-(float)(2 * u) * (1.0f / 128.0f) * LOG2T);
            const int c0 = h * 128 + u;
#pragma unroll
            for (int mt = 0; mt < 4; mt++) {
                const int r = bm0 + wm + mt * 16 + gid;
                {
                    const float ang = (float)(r & (SS - 1)) * inv;
                    const float cs = cosf(ang), sn = sinf(ang);
                    const float a0 = acc[mt][nt][0], a1 = acc[mt][nt][1];
                    C[(size_t)r * N + c0]      = a0 * cs - a1 * sn;
                    C[(size_t)r * N + c0 + 64] = a1 * cs + a0 * sn;
                }
                {
                    const int r2 = r + 8;
                    const float ang = (float)(r2 & (SS - 1)) * inv;
                    const float cs = cosf(ang), sn = sinf(ang);
                    const float a0 = acc[mt][nt][2], a1 = acc[mt][nt][3];
                    C[(size_t)r2 * N + c0]      = a0 * cs - a1 * sn;
                    C[(size_t)r2 * N + c0 + 64] = a1 * cs + a0 * sn;
                }
            }
        }
    }
}

// ---------------- flash attention v6: 4 q/thread, rotated accumulators -------
// warp = 2 q-groups x 16 subs; thread owns 8 dims (d = t*64 + sub*4 + i) of
// queries q0 + (r^x), x=0..3, r=sub&3 (rotated layout -> shfl-only exchange).
#define ATT_STGF (2 * 32 * 128)
#define ATT_SMEM (3 * ATT_STGF * 4)  // 98304 B

__global__ __launch_bounds__(256, 2) void attn_kernel(
        const float* __restrict__ q,
        const float* __restrict__ k,
        const float* __restrict__ v,
        const float* __restrict__ ksuf,
        const float* __restrict__ vsuf,
        const int* __restrict__ validp,
        __half* __restrict__ outh) {
    extern __shared__ float smA[];
    const uint32_t smb = (uint32_t)__cvta_generic_to_shared(smA);

    const int valid = *validp;
    const int hb = blockIdx.x;
    const int h  = hb >> 1;
    const int b  = hb & 1;
    const int bx = 15 - blockIdx.y;          // heavy-first scheduling
    const int kvh = h >> 2;
    const int tid = threadIdx.x;
    const int q0base = bx * 64;

    if (q0base >= valid) {
        const __half2 z2 = __floats2half2_rn(0.f, 0.f);
        const int row = tid >> 6;
        const int col = (tid & 63) * 2;
#pragma unroll
        for (int r = 0; r < 64; r += 4) {
            *(__half2*)(outh + (size_t)(b * SS + q0base + r + row) * QDIM + h * HD + col) = z2;
        }
        return;
    }

    const int wid  = tid >> 5;
    const int lane = tid & 31;
    const int sub  = lane & 15;              // 16 dim-lanes
    const int qg   = lane >> 4;              // 2 query groups
    const int r    = sub & 3;                // rotation index
    const int q0   = q0base + wid * 8 + qg * 4;
    const int qmy  = q0 + r;                 // this lane's own query

    const float scale = 0.08838834764831845f;
    const unsigned long long scale2 = pack2(scale);

    // q2[x] = fragment of query q0 + (r^x); 8 dims -> 2 ulonglong2 = 4 ull
    unsigned long long q2[4][4];
#pragma unroll
    for (int x = 0; x < 4; x++) {
        const float* qp = q + (size_t)(b * SS + q0 + (r ^ x)) * QDIM + h * HD;
        ulonglong2 ua = *(const ulonglong2*)(qp + sub * 4);
        ulonglong2 ub = *(const ulonglong2*)(qp + 64 + sub * 4);
        q2[x][0] = mul2(scale2, ua.x);
        q2[x][1] = mul2(scale2, ua.y);
        q2[x][2] = mul2(scale2, ub.x);
        q2[x][3] = mul2(scale2, ub.y);
    }

    unsigned long long o2[4][4];
#pragma unroll
    for (int x = 0; x < 4; x++)
#pragma unroll
        for (int c = 0; c < 4; c++) o2[x][c] = 0ull;
    float m_my = -1e30f, l_my = 0.f;

    const float* kb_base = k + (size_t)(b * SS) * KVDIM + kvh * HD;
    const float* vb_base = v + (size_t)(b * SS) * KVDIM + kvh * HD;

    const int Tcap = (valid + 31) >> 5;
    const int T = min(2 * bx + 2, Tcap);

    auto issue = [&](int t) {
        const uint32_t sb = smb + (uint32_t)((t % 3) * ATT_STGF * 4);
        const int k0 = t * 32;
#pragma unroll
        for (int i = 0; i < 4; i++) {
            const int c = tid + i * 256;
            const int kk = c >> 5;
            const int d4 = (c & 31) * 4;
            cp16(sb + (uint32_t)((kk * 128 + d4) * 4),
                 kb_base + (size_t)(k0 + kk) * KVDIM + d4);
            cp16(sb + (uint32_t)((4096 + kk * 128 + d4) * 4),
                 vb_base + (size_t)(k0 + kk) * KVDIM + d4);
        }
        asm volatile("cp.async.commit_group;");
    };

    issue(0);
    if (T > 1) issue(1);

    for (int t = 0; t < T; t++) {
        if (t + 1 < T) { asm volatile("cp.async.wait_group 1;"); }
        else           { asm volatile("cp.async.wait_group 0;"); }
        __syncthreads();
        if (t + 2 < T) issue(t + 2);

        const float* Ks = smA + (t % 3) * ATT_STGF;
        const float* Vs = Ks + 4096;
        const int k0 = t * 32;

#pragma unroll
        for (int st = 0; st < 4; st++) {
            float sc[8];
#pragma unroll
            for (int kk8 = 0; kk8 < 8; kk8++) {
                const int kk = st * 8 + kk8;
                ulonglong2 ka = *(const ulonglong2*)&Ks[kk * 128 + sub * 4];
                ulonglong2 kb = *(const ulonglong2*)&Ks[kk * 128 + 64 + sub * 4];
                float s[4];
#pragma unroll
                for (int x = 0; x < 4; x++) {
                    unsigned long long p = fma2(q2[x][0], ka.x, 0ull);
                    p = fma2(q2[x][1], ka.y, p);
                    p = fma2(q2[x][2], kb.x, p);
                    p = fma2(q2[x][3], kb.y, p);
                    float lo, hi;
                    unpack2(p, lo, hi);
                    s[x] = lo + hi;
                }
                // rotated butterfly: lane ends with full dot for its OWN query
                const float t0 = s[0] + __shfl_xor_sync(0xffffffffu, s[1], 1);
                const float t2 = s[2] + __shfl_xor_sync(0xffffffffu, s[3], 1);
                float u = t0 + __shfl_xor_sync(0xffffffffu, t2, 2);
                u += __shfl_xor_sync(0xffffffffu, u, 4);
                u += __shfl_xor_sync(0xffffffffu, u, 8);
                sc[kk8] = (k0 + kk <= qmy) ? u : -1e30f;
            }
            // softmax update for own query
            float tmax = sc[0];
#pragma unroll
            for (int kk8 = 1; kk8 < 8; kk8++) tmax = fmaxf(tmax, sc[kk8]);
            const float mnew = fmaxf(m_my, tmax);
            const float corr = __expf(m_my - mnew);
            l_my *= corr;
            const float cr1 = __shfl_xor_sync(0xffffffffu, corr, 1);
            const float cr2 = __shfl_xor_sync(0xffffffffu, corr, 2);
            const float cr3 = __shfl_xor_sync(0xffffffffu, corr, 3);
            const unsigned long long cp0 = pack2(corr), cp1 = pack2(cr1);
            const unsigned long long cp2 = pack2(cr2), cp3 = pack2(cr3);
#pragma unroll
            for (int c = 0; c < 4; c++) {
                o2[0][c] = mul2(cp0, o2[0][c]);
                o2[1][c] = mul2(cp1, o2[1][c]);
                o2[2][c] = mul2(cp2, o2[2][c]);
                o2[3][c] = mul2(cp3, o2[3][c]);
            }
            m_my = mnew;
#pragma unroll
            for (int kk8 = 0; kk8 < 8; kk8++) {
                const float e = __expf(sc[kk8] - mnew);
                l_my += e;
                sc[kk8] = e;
            }
            // PV
#pragma unroll
            for (int kk8 = 0; kk8 < 8; kk8++) {
                const int kk = st * 8 + kk8;
                ulonglong2 va = *(const ulonglong2*)&Vs[kk * 128 + sub * 4];
                ulonglong2 vb = *(const ulonglong2*)&Vs[kk * 128 + 64 + sub * 4];
                const float e0f = sc[kk8];
                const float e1f = __shfl_xor_sync(0xffffffffu, e0f, 1);
                const float e2f = __shfl_xor_sync(0xffffffffu, e0f, 2);
                const float e3f = __shfl_xor_sync(0xffffffffu, e0f, 3);
                const unsigned long long e0 = pack2(e0f), e1 = pack2(e1f);
                const unsigned long long e2 = pack2(e2f), e3 = pack2(e3f);
                o2[0][0] = fma2(e0, va.x, o2[0][0]);
                o2[0][1] = fma2(e0, va.y, o2[0][1]);
                o2[0][2] = fma2(e0, vb.x, o2[0][2]);
                o2[0][3] = fma2(e0, vb.y, o2[0][3]);
                o2[1][0] = fma2(e1, va.x, o2[1][0]);
                o2[1][1] = fma2(e1, va.y, o2[1][1]);
                o2[1][2] = fma2(e1, vb.x, o2[1][2]);
                o2[1][3] = fma2(e1, vb.y, o2[1][3]);
                o2[2][0] = fma2(e2, va.x, o2[2][0]);
                o2[2][1] = fma2(e2, va.y, o2[2][1]);
                o2[2][2] = fma2(e2, vb.x, o2[2][2]);
                o2[2][3] = fma2(e2, vb.y, o2[2][3]);
                o2[3][0] = fma2(e3, va.x, o2[3][0]);
                o2[3][1] = fma2(e3, va.y, o2[3][1]);
                o2[3][2] = fma2(e3, vb.x, o2[3][2]);
                o2[3][3] = fma2(e3, vb.y, o2[3][3]);
            }
        }
        __syncthreads();
    }

    // ---- 3 suffix keys on the diagonal ----
#pragma unroll
    for (int sj = 0; sj < LCK; sj++) {
        const size_t base_off =
            ((size_t)(b * NKV + kvh) * LCK + sj) * SS;
        float s[4];
#pragma unroll
        for (int x = 0; x < 4; x++) {
            const float* kp = ksuf + (base_off + q0 + (r ^ x)) * HD;
            ulonglong2 ua = *(const ulonglong2*)(kp + sub * 4);
            ulonglong2 ub = *(const ulonglong2*)(kp + 64 + sub * 4);
            unsigned long long p = fma2(q2[x][0], ua.x, 0ull);
            p = fma2(q2[x][1], ua.y, p);
            p = fma2(q2[x][2], ub.x, p);
            p = fma2(q2[x][3], ub.y, p);
            float lo, hi;
            unpack2(p, lo, hi);
            s[x] = lo + hi;
        }
        const float t0 = s[0] + __shfl_xor_sync(0xffffffffu, s[1], 1);
        const float t2 = s[2] + __shfl_xor_sync(0xffffffffu, s[3], 1);
        float u = t0 + __shfl_xor_sync(0xffffffffu, t2, 2);
        u += __shfl_xor_sync(0xffffffffu, u, 4);
        u += __shfl_xor_sync(0xffffffffu, u, 8);

        const float mnew = fmaxf(m_my, u);
        const float corr = __expf(m_my - mnew);
        const float e = __expf(u - mnew);
        l_my = l_my * corr + e;
        m_my = mnew;
        const float cr1 = __shfl_xor_sync(0xffffffffu, corr, 1);
        const float cr2 = __shfl_xor_sync(0xffffffffu, corr, 2);
        const float cr3 = __shfl_xor_sync(0xffffffffu, corr, 3);
        const float e1f = __shfl_xor_sync(0xffffffffu, e, 1);
        const float e2f = __shfl_xor_sync(0xffffffffu, e, 2);
        const float e3f = __shfl_xor_sync(0xffffffffu, e, 3);
        const unsigned long long cp[4] = {pack2(corr), pack2(cr1), pack2(cr2), pack2(cr3)};
        const unsigned long long ep[4] = {pack2(e), pack2(e1f), pack2(e2f), pack2(e3f)};
#pragma unroll
        for (int x = 0; x < 4; x++) {
            const float* vp = vsuf + (base_off + q0 + (r ^ x)) * HD;
            ulonglong2 va = *(const ulonglong2*)(vp + sub * 4);
            ulonglong2 vb = *(const ulonglong2*)(vp + 64 + sub * 4);
            o2[x][0] = fma2(ep[x], va.x, mul2(cp[x], o2[x][0]));
            o2[x][1] = fma2(ep[x], va.y, mul2(cp[x], o2[x][1]));
            o2[x][2] = fma2(ep[x], vb.x, mul2(cp[x], o2[x][2]));
            o2[x][3] = fma2(ep[x], vb.y, mul2(cp[x], o2[x][3]));
        }
    }

    // epilogue: gather l per query, normalize, fp16, masked rows = 0
    const float l1 = __shfl_xor_sync(0xffffffffu, l_my, 1);
    const float l2 = __shfl_xor_sync(0xffffffffu, l_my, 2);
    const float l3 = __shfl_xor_sync(0xffffffffu, l_my, 3);
    const float lv[4] = {l_my, l1, l2, l3};
#pragma unroll
    for (int x = 0; x < 4; x++) {
        const int qx = q0 + (r ^ x);
        const float invl = (qx < valid) ? (1.0f / lv[x]) : 0.0f;
        __half* op = outh + (size_t)(b * SS + qx) * QDIM + h * HD;
        float a0, a1, a2, a3;
        unpack2(o2[x][0], a0, a1);
        unpack2(o2[x][1], a2, a3);
        uint2 w0;
        w0.x = h2u(__floats2half2_rn(a0 * invl, a1 * invl));
        w0.y = h2u(__floats2half2_rn(a2 * invl, a3 * invl));
        *(uint2*)(op + sub * 4) = w0;
        unpack2(o2[x][2], a0, a1);
        unpack2(o2[x][3], a2, a3);
        uint2 w1;
        w1.x = h2u(__floats2half2_rn(a0 * invl, a1 * invl));
        w1.y = h2u(__floats2half2_rn(a2 * invl, a3 * invl));
        *(uint2*)(op + 64 + sub * 4) = w1;
    }
}

// ---------------- launch ----------------------------------------------------
extern "C" void kernel_launch(void* const* d_in, const int* in_sizes, int n_in,
                              void* d_out, int out_size) {
    const float* x    = (const float*)d_in[0];
    const float* ksuf = (const float*)d_in[1];
    const float* vsuf = (const float*)d_in[2];
    const float* Wq   = (const float*)d_in[3];
    const float* Wk   = (const float*)d_in[4];
    const float* Wv   = (const float*)d_in[5];
    const float* Wo   = (const float*)d_in[6];
    const int* valid  = (const int*)d_in[7];
    float* out = (float*)d_out;

    float *gq, *gk, *gv;
    __half *xh, *ah;
    uint32_t *wqp, *wkp, *wvp, *wop;
    cudaGetSymbolAddress((void**)&gq, g_q);
    cudaGetSymbolAddress((void**)&gk, g_k);
    cudaGetSymbolAddress((void**)&gv, g_v);
    cudaGetSymbolAddress((void**)&xh, g_xh);
    cudaGetSymbolAddress((void**)&ah, g_ah);
    cudaGetSymbolAddress((void**)&wqp, g_wqp);
    cudaGetSymbolAddress((void**)&wkp, g_wkp);
    cudaGetSymbolAddress((void**)&wvp, g_wvp);
    cudaGetSymbolAddress((void**)&wop, g_wop);

    cudaFuncSetAttribute(gemm_h, cudaFuncAttributeMaxDynamicSharedMemorySize, GEMM_SMEM);
    cudaFuncSetAttribute(attn_kernel, cudaFuncAttributeMaxDynamicSharedMemorySize, ATT_SMEM);

    // 0: fused prep
    prep_kernel<<<(unsigned)(P_TOTAL / 256), 256>>>(
        (const float4*)x, xh, Wq, wqp, Wk, wkp, Wv, wvp, Wo, wop);

    // 1: K (rope) and V projections in one launch
    gemm_h<<<dim3(KVDIM / 128, MROWS / 128, 2), 256, GEMM_SMEM>>>(
        xh, wkp, wvp, gk, gv, MROWS, KVDIM, HID, 0b01);

    // 2: Q projection (rope)
    gemm_h<<<dim3(QDIM / 128, MROWS / 128, 1), 256, GEMM_SMEM>>>(
        xh, wqp, wqp, gq, gq, MROWS, QDIM, HID, 0b01);

    // 3: attention (heavy CTAs first; captured by ncu)
    attn_kernel<<<dim3(NH * BB, SS / 64), 256, ATT_SMEM>>>(
        gq, gk, gv, ksuf, vsuf, valid, ah);

    // 4: output projection
    gemm_h<<<dim3(QDIM / 128, MROWS / 128, 1), 256, GEMM_SMEM>>>(
        ah, wop, wop, out, out, MROWS, QDIM, QDIM, 0);
}

// round 15
// speedup vs baseline: 2.5998x; 1.0848x over previous
#include <cuda_runtime.h>
#include <cuda_fp16.h>
#include <math.h>
#include <stdint.h>

#define BB 2
#define SS 1024
#define HID 4096
#define NH 32
#define NKV 8
#define HD 128
#define LCK 3
#define MROWS (BB*SS)   // 2048
#define QDIM (NH*HD)    // 4096
#define KVDIM (NKV*HD)  // 1024
#define LOG2T 13.287712379549449f

// ---------------- scratch (static device globals; no allocations) ----------
__device__ float  g_q[(size_t)MROWS * QDIM];
__device__ float  g_k[(size_t)MROWS * KVDIM];
__device__ float  g_v[(size_t)MROWS * KVDIM];
__device__ __half g_xh[(size_t)MROWS * HID];
__device__ __half g_ah[(size_t)MROWS * QDIM];
__device__ __half g_wqh[(size_t)HID * QDIM];   // fp16 weights [K][N] (perm cols)
__device__ __half g_wkh[(size_t)HID * KVDIM];  // perm cols
__device__ __half g_wvh[(size_t)HID * KVDIM];
__device__ __half g_woh[(size_t)QDIM * HID];

// ---------------- PTX helpers -----------------------------------------------
__device__ __forceinline__ void cp16(uint32_t dst, const void* src) {
    asm volatile("cp.async.cg.shared.global [%0], [%1], 16;" :: "r"(dst), "l"(src));
}
__device__ __forceinline__ uint32_t h2u(__half2 h) {
    union { __half2 h; uint32_t u; } cv;
    cv.h = h;
    return cv.u;
}
__device__ __forceinline__ void mma16(float* c, const uint32_t* a, const uint32_t* b) {
    asm volatile(
        "mma.sync.aligned.m16n8k16.row.col.f32.f16.f16.f32 "
        "{%0,%1,%2,%3},{%4,%5,%6,%7},{%8,%9},{%0,%1,%2,%3};"
        : "+f"(c[0]), "+f"(c[1]), "+f"(c[2]), "+f"(c[3])
        : "r"(a[0]), "r"(a[1]), "r"(a[2]), "r"(a[3]), "r"(b[0]), "r"(b[1]));
}
__device__ __forceinline__ void ldsm4(uint32_t* r, uint32_t addr) {
    asm volatile(
        "ldmatrix.sync.aligned.m8n8.x4.shared.b16 {%0,%1,%2,%3}, [%4];"
        : "=r"(r[0]), "=r"(r[1]), "=r"(r[2]), "=r"(r[3]) : "r"(addr));
}
__device__ __forceinline__ void ldsm4t(uint32_t* r, uint32_t addr) {
    asm volatile(
        "ldmatrix.sync.aligned.m8n8.x4.trans.shared.b16 {%0,%1,%2,%3}, [%4];"
        : "=r"(r[0]), "=r"(r[1]), "=r"(r[2]), "=r"(r[3]) : "r"(addr));
}
// packed f32x2
__device__ __forceinline__ unsigned long long fma2(unsigned long long a,
                                                   unsigned long long b,
                                                   unsigned long long c) {
    unsigned long long d;
    asm("fma.rn.f32x2 %0, %1, %2, %3;" : "=l"(d) : "l"(a), "l"(b), "l"(c));
    return d;
}
__device__ __forceinline__ unsigned long long mul2(unsigned long long a,
                                                   unsigned long long b) {
    unsigned long long d;
    asm("mul.rn.f32x2 %0, %1, %2;" : "=l"(d) : "l"(a), "l"(b));
    return d;
}
__device__ __forceinline__ unsigned long long pack2(float x) {
    unsigned long long d;
    asm("mov.b64 %0, {%1, %2};" : "=l"(d) : "f"(x), "f"(x));
    return d;
}
__device__ __forceinline__ void unpack2(unsigned long long v, float& lo, float& hi) {
    asm("mov.b64 {%0, %1}, %2;" : "=f"(lo), "=f"(hi) : "l"(v));
}

// ---------------- fused prep: x->fp16 + convert all 4 weights ----------------
// Each thread writes 16B (8 halves). Weight layout stays [K][N].
#define P_X  ((size_t)MROWS * HID / 4)          // 2M (float4 -> 4 halves)
#define P_WQ ((size_t)HID * QDIM / 8)           // 2M
#define P_WK ((size_t)HID * KVDIM / 8)          // 512K
#define P_WV ((size_t)HID * KVDIM / 8)          // 512K
#define P_WO ((size_t)QDIM * HID / 8)           // 2M
#define P_TOTAL (P_X + P_WQ + P_WK + P_WV + P_WO)

__device__ __forceinline__ void cvt_plain8(const float* __restrict__ W,
                                           __half* __restrict__ P, int N, size_t i) {
    const int npw = N >> 3;
    const int k = (int)(i / npw);
    const int c8 = (int)(i - (size_t)k * npw) * 8;
    const float4 r0 = *(const float4*)(W + (size_t)k * N + c8);
    const float4 r1 = *(const float4*)(W + (size_t)k * N + c8 + 4);
    uint4 o;
    o.x = h2u(__floats2half2_rn(r0.x, r0.y));
    o.y = h2u(__floats2half2_rn(r0.z, r0.w));
    o.z = h2u(__floats2half2_rn(r1.x, r1.y));
    o.w = h2u(__floats2half2_rn(r1.z, r1.w));
    *(uint4*)(P + (size_t)k * N + c8) = o;
}

// Permuted: output col c -> orig col h*128 + (c%128)/2 + ((c&1)?64:0)
__device__ __forceinline__ void cvt_perm8(const float* __restrict__ W,
                                          __half* __restrict__ P, int N, size_t i) {
    const int npw = N >> 3;
    const int k = (int)(i / npw);
    const int c8 = (int)(i - (size_t)k * npw) * 8;
    const float* wr = W + (size_t)k * N;
    __half hv[8];
#pragma unroll
    for (int j = 0; j < 8; j++) {
        const int c = c8 + j;
        const int h = c >> 7;
        const int w = c & 127;
        const int oc = (h << 7) + (w >> 1) + ((w & 1) << 6);
        hv[j] = __float2half_rn(wr[oc]);
    }
    *(uint4*)(P + (size_t)k * N + c8) = *(uint4*)hv;
}

__global__ void prep_kernel(const float4* __restrict__ x,  __half* __restrict__ xh,
                            const float* __restrict__ Wq, __half* __restrict__ wqh,
                            const float* __restrict__ Wk, __half* __restrict__ wkh,
                            const float* __restrict__ Wv, __half* __restrict__ wvh,
                            const float* __restrict__ Wo, __half* __restrict__ woh) {
    size_t i = (size_t)blockIdx.x * 256 + threadIdx.x;
    if (i < P_X) {
        float4 v = x[i];
        *(__half2*)(xh + i * 4)     = __floats2half2_rn(v.x, v.y);
        *(__half2*)(xh + i * 4 + 2) = __floats2half2_rn(v.z, v.w);
    } else if ((i -= P_X) < P_WQ) {
        cvt_perm8(Wq, wqh, QDIM, i);
    } else if ((i -= P_WQ) < P_WK) {
        cvt_perm8(Wk, wkh, KVDIM, i);
    } else if ((i -= P_WK) < P_WV) {
        cvt_plain8(Wv, wvh, KVDIM, i);
    } else {
        i -= P_WV;
        cvt_plain8(Wo, woh, HID, i);
    }
}

// ---------------- fp16 tensor-core GEMM (+optional RoPE epilogue) ------------
// A fp16 [M][K]; B fp16 [K][N]. B frags via ldmatrix.x4.trans.
#define APITCHW 36            // A pitch in words
#define BPITCHW 68            // B pitch in words (128 halves + 8 pad) -> bank 4r
#define ASZW (128 * APITCHW)
#define BSZW (32 * BPITCHW)   // 2176 words
#define STGW (ASZW + BSZW)
#define GEMM_SMEM (3 * STGW * 4)  // 81408 B

__global__ __launch_bounds__(256, 2) void gemm_h(const __half* __restrict__ A,
                                                 const __half* __restrict__ B0,
                                                 const __half* __restrict__ B1,
                                                 float* __restrict__ C0,
                                                 float* __restrict__ C1,
                                                 int M, int N, int K, int rope_mask) {
    const __half* B = blockIdx.z ? B1 : B0;
    float* C = blockIdx.z ? C1 : C0;
    const bool do_rope = (rope_mask >> blockIdx.z) & 1;

    extern __shared__ float sm[];
    const uint32_t smb = (uint32_t)__cvta_generic_to_shared(sm);

    const int tid  = threadIdx.x;
    const int lane = tid & 31;
    const int wid  = tid >> 5;
    const int gid  = lane >> 2;
    const int tig  = lane & 3;
    const int wm   = (wid & 1) * 64;
    const int wn   = (wid >> 1) * 32;

    const int lrow = lane & 7;
    const int lid4 = lane >> 3;
    const int a_moff = (lid4 & 1) * 8;
    const int a_woff = (lid4 >> 1) * 4;
    // B ldsm.trans: matrix lid4 -> row += (lid4&1)*8, col += (lid4>>1)*8
    const int b_roff = (lid4 & 1) * 8 + lrow;
    const int b_coff = (lid4 >> 1) * 8;

    const int bm0 = blockIdx.y * 128;
    const int bn0 = blockIdx.x * 128;

    float acc[4][4][4];
#pragma unroll
    for (int mt = 0; mt < 4; mt++)
#pragma unroll
        for (int nt = 0; nt < 4; nt++)
#pragma unroll
            for (int i = 0; i < 4; i++) acc[mt][nt][i] = 0.f;

    const int T = K / 32;

    auto issue = [&](int t) {
        const uint32_t sb = smb + (uint32_t)((t % 3) * STGW * 4);
#pragma unroll
        for (int i = 0; i < 2; i++) {       // A: 512 chunks
            const int c = tid + i * 256;
            const int row = c >> 2;
            const int q = c & 3;
            cp16(sb + (uint32_t)(row * APITCHW * 4 + q * 16),
                 A + (size_t)(bm0 + row) * K + t * 32 + q * 8);
        }
#pragma unroll
        for (int i = 0; i < 2; i++) {       // B: 32 rows x 256B = 512 chunks
            const int c = tid + i * 256;
            const int kk = c >> 4;
            const int h8 = (c & 15) * 8;
            cp16(sb + (uint32_t)((ASZW + kk * BPITCHW) * 4 + h8 * 2),
                 B + (size_t)(t * 32 + kk) * N + bn0 + h8);
        }
        asm volatile("cp.async.commit_group;");
    };

    issue(0);
    issue(1);

    for (int t = 0; t < T; t++) {
        if (t < T - 1) { asm volatile("cp.async.wait_group 1;"); }
        else           { asm volatile("cp.async.wait_group 0;"); }
        __syncthreads();
        if (t + 2 < T) issue(t + 2);

        const int so = (t % 3) * STGW;
#pragma unroll
        for (int ks = 0; ks < 2; ks++) {
            const int w0 = ks * 8;
            uint32_t af[4][4];
#pragma unroll
            for (int mt = 0; mt < 4; mt++) {
                const uint32_t addr = smb + (uint32_t)(
                    (so + (wm + mt * 16 + a_moff + lrow) * APITCHW + w0 + a_woff) * 4);
                ldsm4(af[mt], addr);
            }
            // B: 2 x ldsm.x4.trans covering n32 x k16
            uint32_t bf[4][2];
#pragma unroll
            for (int pr = 0; pr < 2; pr++) {
                uint32_t bt[4];
                const int row = ks * 16 + b_roff;
                const int col = wn + pr * 16 + b_coff;
                const uint32_t addr = smb + (uint32_t)(
                    (so + ASZW + row * BPITCHW) * 4 + col * 2);
                ldsm4t(bt, addr);
                bf[pr * 2][0]     = bt[0];
                bf[pr * 2][1]     = bt[1];
                bf[pr * 2 + 1][0] = bt[2];
                bf[pr * 2 + 1][1] = bt[3];
            }
#pragma unroll
            for (int mt = 0; mt < 4; mt++)
#pragma unroll
                for (int nt = 0; nt < 4; nt++)
                    mma16(acc[mt][nt], af[mt], bf[nt]);
        }
        // bottom sync removed: next iteration's top sync orders reuse
    }
    __syncthreads();  // final: keep stages stable until all reads done (no-op cost)

    if (!do_rope) {
#pragma unroll
        for (int mt = 0; mt < 4; mt++) {
#pragma unroll
            for (int nt = 0; nt < 4; nt++) {
                const int r = bm0 + wm + mt * 16 + gid;
                const int cc = bn0 + wn + nt * 8 + tig * 2;
                *(float2*)&C[(size_t)r * N + cc] =
                    make_float2(acc[mt][nt][0], acc[mt][nt][1]);
                *(float2*)&C[(size_t)(r + 8) * N + cc] =
                    make_float2(acc[mt][nt][2], acc[mt][nt][3]);
            }
        }
    } else {
#pragma unroll
        for (int nt = 0; nt < 4; nt++) {
            const int cc = bn0 + wn + nt * 8 + tig * 2;
            const int h = cc >> 7;
            const int u = (cc & 127) >> 1;
            const float inv = exp2f(-(float)(2 * u) * (1.0f / 128.0f) * LOG2T);
            const int c0 = h * 128 + u;
#pragma unroll
            for (int mt = 0; mt < 4; mt++) {
                const int r = bm0 + wm + mt * 16 + gid;
                {
                    const float ang = (float)(r & (SS - 1)) * inv;
                    const float cs = cosf(ang), sn = sinf(ang);
                    const float a0 = acc[mt][nt][0], a1 = acc[mt][nt][1];
                    C[(size_t)r * N + c0]      = a0 * cs - a1 * sn;
                    C[(size_t)r * N + c0 + 64] = a1 * cs + a0 * sn;
                }
                {
                    const int r2 = r + 8;
                    const float ang = (float)(r2 & (SS - 1)) * inv;
                    const float cs = cosf(ang), sn = sinf(ang);
                    const float a0 = acc[mt][nt][2], a1 = acc[mt][nt][3];
                    C[(size_t)r2 * N + c0]      = a0 * cs - a1 * sn;
                    C[(size_t)r2 * N + c0 + 64] = a1 * cs + a0 * sn;
                }
            }
        }
    }
}

// ---------------- flash attention v6: 4 q/thread, rotated accumulators -------
#define ATT_STGF (2 * 32 * 128)
#define ATT_SMEM (3 * ATT_STGF * 4)  // 98304 B

__global__ __launch_bounds__(256, 2) void attn_kernel(
        const float* __restrict__ q,
        const float* __restrict__ k,
        const float* __restrict__ v,
        const float* __restrict__ ksuf,
        const float* __restrict__ vsuf,
        const int* __restrict__ validp,
        __half* __restrict__ outh) {
    extern __shared__ float smA[];
    const uint32_t smb = (uint32_t)__cvta_generic_to_shared(smA);

    const int valid = *validp;
    const int hb = blockIdx.x;
    const int h  = hb >> 1;
    const int b  = hb & 1;
    const int bx = 15 - blockIdx.y;          // heavy-first scheduling
    const int kvh = h >> 2;
    const int tid = threadIdx.x;
    const int q0base = bx * 64;

    if (q0base >= valid) {
        const __half2 z2 = __floats2half2_rn(0.f, 0.f);
        const int row = tid >> 6;
        const int col = (tid & 63) * 2;
#pragma unroll
        for (int r = 0; r < 64; r += 4) {
            *(__half2*)(outh + (size_t)(b * SS + q0base + r + row) * QDIM + h * HD + col) = z2;
        }
        return;
    }

    const int wid  = tid >> 5;
    const int lane = tid & 31;
    const int sub  = lane & 15;
    const int qg   = lane >> 4;
    const int r    = sub & 3;
    const int q0   = q0base + wid * 8 + qg * 4;
    const int qmy  = q0 + r;

    const float scale = 0.08838834764831845f;
    const unsigned long long scale2 = pack2(scale);

    unsigned long long q2[4][4];
#pragma unroll
    for (int x = 0; x < 4; x++) {
        const float* qp = q + (size_t)(b * SS + q0 + (r ^ x)) * QDIM + h * HD;
        ulonglong2 ua = *(const ulonglong2*)(qp + sub * 4);
        ulonglong2 ub = *(const ulonglong2*)(qp + 64 + sub * 4);
        q2[x][0] = mul2(scale2, ua.x);
        q2[x][1] = mul2(scale2, ua.y);
        q2[x][2] = mul2(scale2, ub.x);
        q2[x][3] = mul2(scale2, ub.y);
    }

    unsigned long long o2[4][4];
#pragma unroll
    for (int x = 0; x < 4; x++)
#pragma unroll
        for (int c = 0; c < 4; c++) o2[x][c] = 0ull;
    float m_my = -1e30f, l_my = 0.f;

    const float* kb_base = k + (size_t)(b * SS) * KVDIM + kvh * HD;
    const float* vb_base = v + (size_t)(b * SS) * KVDIM + kvh * HD;

    const int Tcap = (valid + 31) >> 5;
    const int T = min(2 * bx + 2, Tcap);

    auto issue = [&](int t) {
        const uint32_t sb = smb + (uint32_t)((t % 3) * ATT_STGF * 4);
        const int k0 = t * 32;
#pragma unroll
        for (int i = 0; i < 4; i++) {
            const int c = tid + i * 256;
            const int kk = c >> 5;
            const int d4 = (c & 31) * 4;
            cp16(sb + (uint32_t)((kk * 128 + d4) * 4),
                 kb_base + (size_t)(k0 + kk) * KVDIM + d4);
            cp16(sb + (uint32_t)((4096 + kk * 128 + d4) * 4),
                 vb_base + (size_t)(k0 + kk) * KVDIM + d4);
        }
        asm volatile("cp.async.commit_group;");
    };

    issue(0);
    if (T > 1) issue(1);

    for (int t = 0; t < T; t++) {
        if (t + 1 < T) { asm volatile("cp.async.wait_group 1;"); }
        else           { asm volatile("cp.async.wait_group 0;"); }
        __syncthreads();
        if (t + 2 < T) issue(t + 2);

        const float* Ks = smA + (t % 3) * ATT_STGF;
        const float* Vs = Ks + 4096;
        const int k0 = t * 32;

#pragma unroll
        for (int st = 0; st < 4; st++) {
            float sc[8];
#pragma unroll
            for (int kk8 = 0; kk8 < 8; kk8++) {
                const int kk = st * 8 + kk8;
                ulonglong2 ka = *(const ulonglong2*)&Ks[kk * 128 + sub * 4];
                ulonglong2 kb = *(const ulonglong2*)&Ks[kk * 128 + 64 + sub * 4];
                float s[4];
#pragma unroll
                for (int x = 0; x < 4; x++) {
                    unsigned long long p = fma2(q2[x][0], ka.x, 0ull);
                    p = fma2(q2[x][1], ka.y, p);
                    p = fma2(q2[x][2], kb.x, p);
                    p = fma2(q2[x][3], kb.y, p);
                    float lo, hi;
                    unpack2(p, lo, hi);
                    s[x] = lo + hi;
                }
                const float t0 = s[0] + __shfl_xor_sync(0xffffffffu, s[1], 1);
                const float t2 = s[2] + __shfl_xor_sync(0xffffffffu, s[3], 1);
                float u = t0 + __shfl_xor_sync(0xffffffffu, t2, 2);
                u += __shfl_xor_sync(0xffffffffu, u, 4);
                u += __shfl_xor_sync(0xffffffffu, u, 8);
                sc[kk8] = (k0 + kk <= qmy) ? u : -1e30f;
            }
            float tmax = sc[0];
#pragma unroll
            for (int kk8 = 1; kk8 < 8; kk8++) tmax = fmaxf(tmax, sc[kk8]);
            const float mnew = fmaxf(m_my, tmax);
            const float corr = __expf(m_my - mnew);
            l_my *= corr;
            const float cr1 = __shfl_xor_sync(0xffffffffu, corr, 1);
            const float cr2 = __shfl_xor_sync(0xffffffffu, corr, 2);
            const float cr3 = __shfl_xor_sync(0xffffffffu, corr, 3);
            const unsigned long long cp0 = pack2(corr), cp1 = pack2(cr1);
            const unsigned long long cp2 = pack2(cr2), cp3 = pack2(cr3);
#pragma unroll
            for (int c = 0; c < 4; c++) {
                o2[0][c] = mul2(cp0, o2[0][c]);
                o2[1][c] = mul2(cp1, o2[1][c]);
                o2[2][c] = mul2(cp2, o2[2][c]);
                o2[3][c] = mul2(cp3, o2[3][c]);
            }
            m_my = mnew;
#pragma unroll
            for (int kk8 = 0; kk8 < 8; kk8++) {
                const float e = __expf(sc[kk8] - mnew);
                l_my += e;
                sc[kk8] = e;
            }
#pragma unroll
            for (int kk8 = 0; kk8 < 8; kk8++) {
                const int kk = st * 8 + kk8;
                ulonglong2 va = *(const ulonglong2*)&Vs[kk * 128 + sub * 4];
                ulonglong2 vb = *(const ulonglong2*)&Vs[kk * 128 + 64 + sub * 4];
                const float e0f = sc[kk8];
                const float e1f = __shfl_xor_sync(0xffffffffu, e0f, 1);
                const float e2f = __shfl_xor_sync(0xffffffffu, e0f, 2);
                const float e3f = __shfl_xor_sync(0xffffffffu, e0f, 3);
                const unsigned long long e0 = pack2(e0f), e1 = pack2(e1f);
                const unsigned long long e2 = pack2(e2f), e3 = pack2(e3f);
                o2[0][0] = fma2(e0, va.x, o2[0][0]);
                o2[0][1] = fma2(e0, va.y, o2[0][1]);
                o2[0][2] = fma2(e0, vb.x, o2[0][2]);
                o2[0][3] = fma2(e0, vb.y, o2[0][3]);
                o2[1][0] = fma2(e1, va.x, o2[1][0]);
                o2[1][1] = fma2(e1, va.y, o2[1][1]);
                o2[1][2] = fma2(e1, vb.x, o2[1][2]);
                o2[1][3] = fma2(e1, vb.y, o2[1][3]);
                o2[2][0] = fma2(e2, va.x, o2[2][0]);
                o2[2][1] = fma2(e2, va.y, o2[2][1]);
                o2[2][2] = fma2(e2, vb.x, o2[2][2]);
                o2[2][3] = fma2(e2, vb.y, o2[2][3]);
                o2[3][0] = fma2(e3, va.x, o2[3][0]);
                o2[3][1] = fma2(e3, va.y, o2[3][1]);
                o2[3][2] = fma2(e3, vb.x, o2[3][2]);
                o2[3][3] = fma2(e3, vb.y, o2[3][3]);
            }
        }
        // bottom sync removed: next iteration's top sync orders stage reuse
    }

    // ---- 3 suffix keys on the diagonal ----
#pragma unroll
    for (int sj = 0; sj < LCK; sj++) {
        const size_t base_off =
            ((size_t)(b * NKV + kvh) * LCK + sj) * SS;
        float s[4];
#pragma unroll
        for (int x = 0; x < 4; x++) {
            const float* kp = ksuf + (base_off + q0 + (r ^ x)) * HD;
            ulonglong2 ua = *(const ulonglong2*)(kp + sub * 4);
            ulonglong2 ub = *(const ulonglong2*)(kp + 64 + sub * 4);
            unsigned long long p = fma2(q2[x][0], ua.x, 0ull);
            p = fma2(q2[x][1], ua.y, p);
            p = fma2(q2[x][2], ub.x, p);
            p = fma2(q2[x][3], ub.y, p);
            float lo, hi;
            unpack2(p, lo, hi);
            s[x] = lo + hi;
        }
        const float t0 = s[0] + __shfl_xor_sync(0xffffffffu, s[1], 1);
        const float t2 = s[2] + __shfl_xor_sync(0xffffffffu, s[3], 1);
        float u = t0 + __shfl_xor_sync(0xffffffffu, t2, 2);
        u += __shfl_xor_sync(0xffffffffu, u, 4);
        u += __shfl_xor_sync(0xffffffffu, u, 8);

        const float mnew = fmaxf(m_my, u);
        const float corr = __expf(m_my - mnew);
        const float e = __expf(u - mnew);
        l_my = l_my * corr + e;
        m_my = mnew;
        const float cr1 = __shfl_xor_sync(0xffffffffu, corr, 1);
        const float cr2 = __shfl_xor_sync(0xffffffffu, corr, 2);
        const float cr3 = __shfl_xor_sync(0xffffffffu, corr, 3);
        const float e1f = __shfl_xor_sync(0xffffffffu, e, 1);
        const float e2f = __shfl_xor_sync(0xffffffffu, e, 2);
        const float e3f = __shfl_xor_sync(0xffffffffu, e, 3);
        const unsigned long long cp[4] = {pack2(corr), pack2(cr1), pack2(cr2), pack2(cr3)};
        const unsigned long long ep[4] = {pack2(e), pack2(e1f), pack2(e2f), pack2(e3f)};
#pragma unroll
        for (int x = 0; x < 4; x++) {
            const float* vp = vsuf + (base_off + q0 + (r ^ x)) * HD;
            ulonglong2 va = *(const ulonglong2*)(vp + sub * 4);
            ulonglong2 vb = *(const ulonglong2*)(vp + 64 + sub * 4);
            o2[x][0] = fma2(ep[x], va.x, mul2(cp[x], o2[x][0]));
            o2[x][1] = fma2(ep[x], va.y, mul2(cp[x], o2[x][1]));
            o2[x][2] = fma2(ep[x], vb.x, mul2(cp[x], o2[x][2]));
            o2[x][3] = fma2(ep[x], vb.y, mul2(cp[x], o2[x][3]));
        }
    }

    // epilogue
    const float l1 = __shfl_xor_sync(0xffffffffu, l_my, 1);
    const float l2 = __shfl_xor_sync(0xffffffffu, l_my, 2);
    const float l3 = __shfl_xor_sync(0xffffffffu, l_my, 3);
    const float lv[4] = {l_my, l1, l2, l3};
#pragma unroll
    for (int x = 0; x < 4; x++) {
        const int qx = q0 + (r ^ x);
        const float invl = (qx < valid) ? (1.0f / lv[x]) : 0.0f;
        __half* op = outh + (size_t)(b * SS + qx) * QDIM + h * HD;
        float a0, a1, a2, a3;
        unpack2(o2[x][0], a0, a1);
        unpack2(o2[x][1], a2, a3);
        uint2 w0;
        w0.x = h2u(__floats2half2_rn(a0 * invl, a1 * invl));
        w0.y = h2u(__floats2half2_rn(a2 * invl, a3 * invl));
        *(uint2*)(op + sub * 4) = w0;
        unpack2(o2[x][2], a0, a1);
        unpack2(o2[x][3], a2, a3);
        uint2 w1;
        w1.x = h2u(__floats2half2_rn(a0 * invl, a1 * invl));
        w1.y = h2u(__floats2half2_rn(a2 * invl, a3 * invl));
        *(uint2*)(op + 64 + sub * 4) = w1;
    }
}

// ---------------- launch ----------------------------------------------------
extern "C" void kernel_launch(void* const* d_in, const int* in_sizes, int n_in,
                              void* d_out, int out_size) {
    const float* x    = (const float*)d_in[0];
    const float* ksuf = (const float*)d_in[1];
    const float* vsuf = (const float*)d_in[2];
    const float* Wq   = (const float*)d_in[3];
    const float* Wk   = (const float*)d_in[4];
    const float* Wv   = (const float*)d_in[5];
    const float* Wo   = (const float*)d_in[6];
    const int* valid  = (const int*)d_in[7];
    float* out = (float*)d_out;

    float *gq, *gk, *gv;
    __half *xh, *ah, *wqh, *wkh, *wvh, *woh;
    cudaGetSymbolAddress((void**)&gq, g_q);
    cudaGetSymbolAddress((void**)&gk, g_k);
    cudaGetSymbolAddress((void**)&gv, g_v);
    cudaGetSymbolAddress((void**)&xh, g_xh);
    cudaGetSymbolAddress((void**)&ah, g_ah);
    cudaGetSymbolAddress((void**)&wqh, g_wqh);
    cudaGetSymbolAddress((void**)&wkh, g_wkh);
    cudaGetSymbolAddress((void**)&wvh, g_wvh);
    cudaGetSymbolAddress((void**)&woh, g_woh);

    cudaFuncSetAttribute(gemm_h, cudaFuncAttributeMaxDynamicSharedMemorySize, GEMM_SMEM);
    cudaFuncSetAttribute(attn_kernel, cudaFuncAttributeMaxDynamicSharedMemorySize, ATT_SMEM);

    // 0: fused prep
    prep_kernel<<<(unsigned)(P_TOTAL / 256), 256>>>(
        (const float4*)x, xh, Wq, wqh, Wk, wkh, Wv, wvh, Wo, woh);

    // 1: K (rope) and V projections in one launch
    gemm_h<<<dim3(KVDIM / 128, MROWS / 128, 2), 256, GEMM_SMEM>>>(
        xh, wkh, wvh, gk, gv, MROWS, KVDIM, HID, 0b01);

    // 2: Q projection (rope)
    gemm_h<<<dim3(QDIM / 128, MROWS / 128, 1), 256, GEMM_SMEM>>>(
        xh, wqh, wqh, gq, gq, MROWS, QDIM, HID, 0b01);

    // 3: attention (heavy CTAs first; captured by ncu)
    attn_kernel<<<dim3(NH * BB, SS / 64), 256, ATT_SMEM>>>(
        gq, gk, gv, ksuf, vsuf, valid, ah);

    // 4: output projection
    gemm_h<<<dim3(QDIM / 128, MROWS / 128, 1), 256, GEMM_SMEM>>>(
        ah, woh, woh, out, out, MROWS, QDIM, QDIM, 0);
}